// round 7
// baseline (speedup 1.0000x reference)
#include <cuda_runtime.h>
#include <cuda_bf16.h>
#include <math.h>

#define Bsz 2
#define Ssz 2048
#define HIDs 2048
#define Hh 16
#define KVh 8
#define Dh 128
#define KP 6144              // K' = 3*2048 for bf16x3 split
#define NT 96                // KP / 64 k-chunks
#define STG_A (128 * 72 * 2)            // 18432 B per A tile (stride 144B)
#define STG_BYTES (2 * STG_A)
#define GEMM_SMEM (2 * STG_BYTES)

// flash smem: two K stages (Kh+Kl each 128x136 bf16) + one V buffer (Vh+Vl)
#define FK_HALF 34816                   // one 128x136 bf16 matrix (stride 272B)
#define FK_STG (2 * FK_HALF)            // Kh + Kl = 69632
#define FV_OFF (2 * FK_STG)             // 139264
#define FL_SMEM (FV_OFF + FK_STG)       // 208896

// ---------------- scratch (static device arrays: no allocs allowed) ----------
__device__ float g_q[(size_t)Bsz * Ssz * Hh * Dh];
__device__ float g_k[(size_t)Bsz * Ssz * KVh * Dh];
__device__ float g_v[(size_t)Bsz * Ssz * KVh * Dh];
__device__ float g_att[(size_t)Bsz * Ssz * Hh * Dh];

__device__ __align__(16) __nv_bfloat16 g_xp[(size_t)4096 * KP];
__device__ __align__(16) __nv_bfloat16 g_ap[(size_t)4096 * KP];
__device__ __align__(16) __nv_bfloat16 g_wqt[(size_t)2048 * KP];
__device__ __align__(16) __nv_bfloat16 g_wkt[(size_t)1024 * KP];
__device__ __align__(16) __nv_bfloat16 g_wvt[(size_t)1024 * KP];
__device__ __align__(16) __nv_bfloat16 g_wot[(size_t)2048 * KP];

// head-major bf16 splits for flash
__device__ __align__(16) __nv_bfloat16 g_qh[(size_t)Bsz * Hh * Ssz * Dh];
__device__ __align__(16) __nv_bfloat16 g_ql[(size_t)Bsz * Hh * Ssz * Dh];
__device__ __align__(16) __nv_bfloat16 g_kh[(size_t)Bsz * KVh * Ssz * Dh];
__device__ __align__(16) __nv_bfloat16 g_kl[(size_t)Bsz * KVh * Ssz * Dh];
__device__ __align__(16) __nv_bfloat16 g_vth[(size_t)Bsz * KVh * Dh * Ssz];
__device__ __align__(16) __nv_bfloat16 g_vtl[(size_t)Bsz * KVh * Dh * Ssz];

// ====================== PTX helpers =========================================
__device__ __forceinline__ unsigned smem_u32(const void* p) {
    unsigned a;
    asm("{ .reg .u64 t; cvta.to.shared.u64 t, %1; cvt.u32.u64 %0, t; }"
        : "=r"(a) : "l"(p));
    return a;
}
#define CP16(dst, src) \
    asm volatile("cp.async.cg.shared.global [%0], [%1], 16;" :: "r"(dst), "l"(src))
#define CP_COMMIT() asm volatile("cp.async.commit_group;")

__device__ __forceinline__ void ldsm4(unsigned& r0, unsigned& r1,
                                      unsigned& r2, unsigned& r3, unsigned a) {
    asm volatile("ldmatrix.sync.aligned.m8n8.x4.shared.b16 {%0,%1,%2,%3}, [%4];"
                 : "=r"(r0), "=r"(r1), "=r"(r2), "=r"(r3) : "r"(a));
}
__device__ __forceinline__ void mma16816(float* d, const unsigned* a,
                                         unsigned b0, unsigned b1) {
    asm volatile(
        "mma.sync.aligned.m16n8k16.row.col.f32.bf16.bf16.f32 "
        "{%0,%1,%2,%3}, {%4,%5,%6,%7}, {%8,%9}, {%0,%1,%2,%3};"
        : "+f"(d[0]), "+f"(d[1]), "+f"(d[2]), "+f"(d[3])
        : "r"(a[0]), "r"(a[1]), "r"(a[2]), "r"(a[3]), "r"(b0), "r"(b1));
}
__device__ __forceinline__ unsigned pack2(float lo, float hi) {
    unsigned d;
    asm("cvt.rn.bf16x2.f32 %0, %1, %2;" : "=r"(d) : "f"(hi), "f"(lo));
    return d;
}
__device__ __forceinline__ float bfres(float x) {
    return x - __bfloat162float(__float2bfloat16(x));
}

// ====================== conversion kernels ==================================
__global__ __launch_bounds__(256) void conv_a(
    const float* __restrict__ src, __nv_bfloat16* __restrict__ dst)
{
    size_t i = (size_t)blockIdx.x * 256 + threadIdx.x;
    int m = (int)(i >> 9);
    int k4 = (int)(i & 511);
    float4 v = ((const float4*)(src + (size_t)m * 2048))[k4];
    __nv_bfloat16 h0 = __float2bfloat16(v.x), h1 = __float2bfloat16(v.y);
    __nv_bfloat16 h2 = __float2bfloat16(v.z), h3 = __float2bfloat16(v.w);
    __nv_bfloat16 l0 = __float2bfloat16(v.x - __bfloat162float(h0));
    __nv_bfloat16 l1 = __float2bfloat16(v.y - __bfloat162float(h1));
    __nv_bfloat16 l2 = __float2bfloat16(v.z - __bfloat162float(h2));
    __nv_bfloat16 l3 = __float2bfloat16(v.w - __bfloat162float(h3));
    __nv_bfloat162 hA = __nv_bfloat162(h0, h1), hB = __nv_bfloat162(h2, h3);
    __nv_bfloat162 lA = __nv_bfloat162(l0, l1), lB = __nv_bfloat162(l2, l3);
    __nv_bfloat162* row = (__nv_bfloat162*)(dst + (size_t)m * KP) + k4 * 2;
    row[0] = hA; row[1] = hB;
    row[1024] = lA; row[1025] = lB;
    row[2048] = hA; row[2049] = hB;
}

__global__ __launch_bounds__(256) void conv_w(
    const float* __restrict__ W, __nv_bfloat16* __restrict__ Bt, int N)
{
    __shared__ float ts[32][33];
    int n0 = blockIdx.x * 32, k0 = blockIdx.y * 32;
    int tx = threadIdx.x & 31, ty = threadIdx.x >> 5;
    #pragma unroll
    for (int r = 0; r < 4; ++r)
        ts[ty + r * 8][tx] = W[(size_t)(k0 + ty + r * 8) * N + n0 + tx];
    __syncthreads();
    #pragma unroll
    for (int r = 0; r < 4; ++r) {
        int n = n0 + ty + r * 8, k = k0 + tx;
        float v = ts[tx][ty + r * 8];
        __nv_bfloat16 hi = __float2bfloat16(v);
        __nv_bfloat16 lo = __float2bfloat16(v - __bfloat162float(hi));
        __nv_bfloat16* row = Bt + (size_t)n * KP;
        row[k] = hi; row[2048 + k] = hi; row[4096 + k] = lo;
    }
}

// [B,S,nh,128] fp32 -> [B,nh,S,128] bf16 hi/lo (optionally scaled)
__global__ __launch_bounds__(256) void conv_qk(
    const float* __restrict__ src, __nv_bfloat16* __restrict__ dh,
    __nv_bfloat16* __restrict__ dl, int nh, float scale)
{
    size_t i = (size_t)blockIdx.x * 256 + threadIdx.x;
    int c4 = (int)(i & 31);
    size_t rest = i >> 5;
    int hh = (int)(rest % nh);
    size_t bs = rest / nh;
    float4 v = ((const float4*)src)[i];
    v.x *= scale; v.y *= scale; v.z *= scale; v.w *= scale;
    __nv_bfloat16 h0 = __float2bfloat16(v.x), h1 = __float2bfloat16(v.y);
    __nv_bfloat16 h2 = __float2bfloat16(v.z), h3 = __float2bfloat16(v.w);
    __nv_bfloat16 l0 = __float2bfloat16(v.x - __bfloat162float(h0));
    __nv_bfloat16 l1 = __float2bfloat16(v.y - __bfloat162float(h1));
    __nv_bfloat16 l2 = __float2bfloat16(v.z - __bfloat162float(h2));
    __nv_bfloat16 l3 = __float2bfloat16(v.w - __bfloat162float(h3));
    int s = (int)(bs % Ssz), b = (int)(bs / Ssz);
    size_t o = ((((size_t)b * nh + hh) * Ssz + s) * 128 + c4 * 4) >> 2;
    ((__nv_bfloat162*)dh)[o * 2] = __nv_bfloat162(h0, h1);
    ((__nv_bfloat162*)dh)[o * 2 + 1] = __nv_bfloat162(h2, h3);
    ((__nv_bfloat162*)dl)[o * 2] = __nv_bfloat162(l0, l1);
    ((__nv_bfloat162*)dl)[o * 2 + 1] = __nv_bfloat162(l2, l3);
}

// V [B,S,KV,128] fp32 -> Vt hi/lo [B*KV, 128, S] bf16
__global__ __launch_bounds__(256) void conv_vt(
    const float* __restrict__ v, __nv_bfloat16* __restrict__ th,
    __nv_bfloat16* __restrict__ tl)
{
    __shared__ float ts[32][33];
    int s0 = blockIdx.x * 32, d0 = blockIdx.y * 32;
    int bk = blockIdx.z;
    int b = bk >> 3, kv = bk & 7;
    int tx = threadIdx.x & 31, ty = threadIdx.x >> 5;
    #pragma unroll
    for (int r = 0; r < 4; ++r)
        ts[ty + r * 8][tx] =
            v[((size_t)(b * Ssz + s0 + ty + r * 8) * KVh + kv) * 128 + d0 + tx];
    __syncthreads();
    #pragma unroll
    for (int r = 0; r < 4; ++r) {
        float x = ts[tx][ty + r * 8];
        __nv_bfloat16 hi = __float2bfloat16(x);
        __nv_bfloat16 lo = __float2bfloat16(x - __bfloat162float(hi));
        size_t o = ((size_t)bk * 128 + d0 + ty + r * 8) * Ssz + s0 + tx;
        th[o] = hi; tl[o] = lo;
    }
}

// ====================== HMMA bf16 GEMM (unchanged) ==========================
__global__ __launch_bounds__(256, 2) void gemm_mma(
    const __nv_bfloat16* __restrict__ A, const __nv_bfloat16* __restrict__ Bm,
    float* __restrict__ C, int N)
{
    extern __shared__ __align__(16) char smem[];
    const unsigned sb = smem_u32(smem);
    const int tid = threadIdx.x;
    const int lane = tid & 31;
    const int wid = tid >> 5;
    const int wr = wid >> 1;
    const int wc = wid & 1;
    const int bm = blockIdx.y << 7, bn = blockIdx.x << 7;

    const int lrow = tid >> 3, lcol = tid & 7;
    const __nv_bfloat16* Ag = A + (size_t)(bm + lrow) * KP + lcol * 8;
    const __nv_bfloat16* Bg = Bm + (size_t)(bn + lrow) * KP + lcol * 8;
    const unsigned sOff = lrow * 144 + lcol * 16;

    float acc[2][8][4];
    #pragma unroll
    for (int i = 0; i < 2; ++i)
        #pragma unroll
        for (int j = 0; j < 8; ++j)
            #pragma unroll
            for (int e = 0; e < 4; ++e) acc[i][j][e] = 0.0f;

    const unsigned aBase0 = sb + (32 * wr + (lane & 15)) * 144 + (lane >> 4) * 16;
    const unsigned bBase0 = sb + STG_A + (64 * wc + (lane & 15)) * 144 + (lane >> 4) * 16;

    {
        const unsigned as = sb + sOff, bs = sb + STG_A + sOff;
        #pragma unroll
        for (int i = 0; i < 4; ++i) {
            CP16(as + i * 32 * 144, Ag + (size_t)(32 * i) * KP);
            CP16(bs + i * 32 * 144, Bg + (size_t)(32 * i) * KP);
        }
        CP_COMMIT();
    }

    for (int c = 0; c < NT; ++c) {
        if (c + 1 < NT) {
            const unsigned st = ((c + 1) & 1) * STG_BYTES;
            const unsigned as = sb + st + sOff, bs = sb + st + STG_A + sOff;
            const __nv_bfloat16* ag = Ag + (size_t)(c + 1) * 64;
            const __nv_bfloat16* bg = Bg + (size_t)(c + 1) * 64;
            #pragma unroll
            for (int i = 0; i < 4; ++i) {
                CP16(as + i * 32 * 144, ag + (size_t)(32 * i) * KP);
                CP16(bs + i * 32 * 144, bg + (size_t)(32 * i) * KP);
            }
            CP_COMMIT();
            asm volatile("cp.async.wait_group 1;" ::: "memory");
        } else {
            asm volatile("cp.async.wait_group 0;" ::: "memory");
        }
        __syncthreads();

        const unsigned st = (c & 1) * STG_BYTES;
        const unsigned aB = aBase0 + st, bB = bBase0 + st;
        #pragma unroll
        for (int ks = 0; ks < 4; ++ks) {
            unsigned a[2][4];
            ldsm4(a[0][0], a[0][1], a[0][2], a[0][3], aB + ks * 32);
            ldsm4(a[1][0], a[1][1], a[1][2], a[1][3], aB + 16 * 144 + ks * 32);
            unsigned b[8][2];
            #pragma unroll
            for (int nt = 0; nt < 4; ++nt) {
                unsigned r0, r1, r2, r3;
                ldsm4(r0, r1, r2, r3, bB + nt * 16 * 144 + ks * 32);
                b[nt * 2][0] = r0; b[nt * 2][1] = r2;
                b[nt * 2 + 1][0] = r1; b[nt * 2 + 1][1] = r3;
            }
            #pragma unroll
            for (int mt = 0; mt < 2; ++mt)
                #pragma unroll
                for (int nt = 0; nt < 8; ++nt)
                    mma16816(acc[mt][nt], a[mt], b[nt][0], b[nt][1]);
        }
        __syncthreads();
    }

    #pragma unroll
    for (int mt = 0; mt < 2; ++mt) {
        const int r0 = bm + 32 * wr + 16 * mt + (lane >> 2);
        #pragma unroll
        for (int nt = 0; nt < 8; ++nt) {
            const int col = bn + 64 * wc + 8 * nt + (lane & 3) * 2;
            float2 v0 = make_float2(acc[mt][nt][0], acc[mt][nt][1]);
            float2 v1 = make_float2(acc[mt][nt][2], acc[mt][nt][3]);
            *(float2*)&C[(size_t)r0 * N + col]       = v0;
            *(float2*)&C[(size_t)(r0 + 8) * N + col] = v1;
        }
    }
}

// ---------------- RMSNorm + RoPE (in place) ----------------------------------
__global__ __launch_bounds__(256) void norm_rope_k(
    float* __restrict__ t, const float* __restrict__ w,
    const float* __restrict__ cs, const float* __restrict__ sn, int nh)
{
    const int warp = blockIdx.x * 8 + (threadIdx.x >> 5);
    const int lane = threadIdx.x & 31;
    const int s = (warp / nh) % Ssz;

    float* row = t + (size_t)warp * Dh;
    float v0 = row[lane];
    float v1 = row[lane + 32];
    float v2 = row[lane + 64];
    float v3 = row[lane + 96];

    float ss = v0 * v0 + v1 * v1 + v2 * v2 + v3 * v3;
    #pragma unroll
    for (int o = 16; o; o >>= 1) ss += __shfl_xor_sync(0xffffffffu, ss, o);
    float r = rsqrtf(ss * (1.0f / 128.0f) + 1e-6f);

    v0 = v0 * r * w[lane];
    v1 = v1 * r * w[lane + 32];
    v2 = v2 * r * w[lane + 64];
    v3 = v3 * r * w[lane + 96];

    const float* cr = cs + (size_t)s * Dh;
    const float* sr = sn + (size_t)s * Dh;
    float o0 = v0 * cr[lane]      - v2 * sr[lane];
    float o1 = v1 * cr[lane + 32] - v3 * sr[lane + 32];
    float o2 = v2 * cr[lane + 64] + v0 * sr[lane + 64];
    float o3 = v3 * cr[lane + 96] + v1 * sr[lane + 96];

    row[lane]      = o0;
    row[lane + 32] = o1;
    row[lane + 64] = o2;
    row[lane + 96] = o3;
}

// ====================== HMMA flash attention (kv-tile 128) ==================
__device__ __forceinline__ void fl_load_k(
    unsigned sb, int stage, int tid,
    const __nv_bfloat16* khp, const __nv_bfloat16* klp, int nBase)
{
    const int r = tid >> 1, c0 = (tid & 1) * 8;
    const char* gk = (const char*)(khp + (size_t)(nBase + r) * 128) + c0 * 16;
    const char* gl = (const char*)(klp + (size_t)(nBase + r) * 128) + c0 * 16;
    const unsigned dk = sb + stage * FK_STG + r * 272 + c0 * 16;
    #pragma unroll
    for (int i = 0; i < 8; ++i) {
        CP16(dk + i * 16, gk + i * 16);
        CP16(dk + FK_HALF + i * 16, gl + i * 16);
    }
}
__device__ __forceinline__ void fl_load_v(
    unsigned sb, int tid,
    const __nv_bfloat16* vthp, const __nv_bfloat16* vtlp, int nBase)
{
    const int r = tid >> 1, c0 = (tid & 1) * 8;
    const char* gv = (const char*)(vthp + (size_t)r * Ssz + nBase) + c0 * 16;
    const char* gw = (const char*)(vtlp + (size_t)r * Ssz + nBase) + c0 * 16;
    const unsigned dv = sb + FV_OFF + r * 272 + c0 * 16;
    #pragma unroll
    for (int i = 0; i < 8; ++i) {
        CP16(dv + i * 16, gv + i * 16);
        CP16(dv + FK_HALF + i * 16, gw + i * 16);
    }
}

__global__ __launch_bounds__(256, 1) void flash_mma(
    const __nv_bfloat16* __restrict__ qh, const __nv_bfloat16* __restrict__ ql,
    const __nv_bfloat16* __restrict__ kh, const __nv_bfloat16* __restrict__ kl,
    const __nv_bfloat16* __restrict__ vth, const __nv_bfloat16* __restrict__ vtl,
    float* __restrict__ out)
{
    extern __shared__ __align__(16) char smem[];
    const unsigned sb = smem_u32(smem);
    const int tid = threadIdx.x, lane = tid & 31, w = tid >> 5;
    const int qi = 15 - blockIdx.x;              // big blocks first
    const int h = blockIdx.y, b = blockIdx.z;
    const int kvh = h >> 1;
    const int mBase = qi << 7;

    const __nv_bfloat16* qhp = qh + (((size_t)b * Hh + h) * Ssz + mBase) * Dh;
    const __nv_bfloat16* qlp = ql + (((size_t)b * Hh + h) * Ssz + mBase) * Dh;
    const __nv_bfloat16* khp = kh + ((size_t)b * KVh + kvh) * Ssz * Dh;
    const __nv_bfloat16* klp = kl + ((size_t)b * KVh + kvh) * Ssz * Dh;
    const __nv_bfloat16* vthp = vth + ((size_t)b * KVh + kvh) * Dh * Ssz;
    const __nv_bfloat16* vtlp = vtl + ((size_t)b * KVh + kvh) * Dh * Ssz;

    // prologue: stage Q in the V buffer, start K0
    {
        const int r = tid >> 1, c0 = (tid & 1) * 8;
        const unsigned dq = sb + FV_OFF + r * 272 + c0 * 16;
        const char* gq = (const char*)(qhp + (size_t)r * Dh) + c0 * 16;
        const char* gl = (const char*)(qlp + (size_t)r * Dh) + c0 * 16;
        #pragma unroll
        for (int i = 0; i < 8; ++i) {
            CP16(dq + i * 16, gq + i * 16);
            CP16(dq + FK_HALF + i * 16, gl + i * 16);
        }
        CP_COMMIT();
    }
    fl_load_k(sb, 0, tid, khp, klp, 0);
    CP_COMMIT();
    asm volatile("cp.async.wait_group 1;" ::: "memory");   // Q done
    __syncthreads();

    // extract Q fragments to registers
    unsigned qhf[8][4], qlf[8][4];
    {
        const unsigned qB = sb + FV_OFF + (16 * w + (lane & 15)) * 272 + (lane >> 4) * 16;
        #pragma unroll
        for (int kt = 0; kt < 8; ++kt) {
            ldsm4(qhf[kt][0], qhf[kt][1], qhf[kt][2], qhf[kt][3], qB + kt * 32);
            ldsm4(qlf[kt][0], qlf[kt][1], qlf[kt][2], qlf[kt][3],
                  qB + FK_HALF + kt * 32);
        }
    }
    __syncthreads();

    float o_[16][4];
    #pragma unroll
    for (int n = 0; n < 16; ++n)
        #pragma unroll
        for (int e = 0; e < 4; ++e) o_[n][e] = 0.0f;
    float m_lo = -1e30f, m_hi = -1e30f, l_lo = 0.0f, l_hi = 0.0f;
    const int gm_lo = mBase + 16 * w + (lane >> 2);
    const int gm_hi = gm_lo + 8;

    for (int t = 0; t <= qi; ++t) {
        // V_t into the (now free) V buffer
        fl_load_v(sb, tid, vthp, vtlp, t * 128);
        CP_COMMIT();
        if (t < qi) {
            fl_load_k(sb, (t + 1) & 1, tid, khp, klp, (t + 1) * 128);
            CP_COMMIT();
            asm volatile("cp.async.wait_group 2;" ::: "memory");  // K_t ready
        } else {
            asm volatile("cp.async.wait_group 1;" ::: "memory");  // K_t ready
        }
        __syncthreads();
        const unsigned stb = sb + (t & 1) * FK_STG;

        // ---- QK^T (3-term split), 128 cols ----
        float s_[16][4];
        #pragma unroll
        for (int j = 0; j < 16; ++j)
            #pragma unroll
            for (int e = 0; e < 4; ++e) s_[j][e] = 0.0f;

        const unsigned kB = stb + (lane & 15) * 272 + (lane >> 4) * 16;
        #pragma unroll
        for (int kt = 0; kt < 8; ++kt) {
            #pragma unroll
            for (int nt = 0; nt < 8; ++nt) {
                unsigned r0, r1, r2, r3;
                ldsm4(r0, r1, r2, r3, kB + nt * 16 * 272 + kt * 32);
                mma16816(s_[nt * 2],     qhf[kt], r0, r2);
                mma16816(s_[nt * 2 + 1], qhf[kt], r1, r3);
                mma16816(s_[nt * 2],     qlf[kt], r0, r2);
                mma16816(s_[nt * 2 + 1], qlf[kt], r1, r3);
            }
            #pragma unroll
            for (int nt = 0; nt < 8; ++nt) {
                unsigned r0, r1, r2, r3;
                ldsm4(r0, r1, r2, r3, kB + FK_HALF + nt * 16 * 272 + kt * 32);
                mma16816(s_[nt * 2],     qhf[kt], r0, r2);
                mma16816(s_[nt * 2 + 1], qhf[kt], r1, r3);
            }
        }

        // ---- mask (diagonal tile only) + online softmax ----
        if (t == qi) {
            const int nBase = t << 7;
            #pragma unroll
            for (int j = 0; j < 16; ++j) {
                const int gn0 = nBase + 8 * j + (lane & 3) * 2;
                if (gn0 > gm_lo)     s_[j][0] = -1e30f;
                if (gn0 + 1 > gm_lo) s_[j][1] = -1e30f;
                if (gn0 > gm_hi)     s_[j][2] = -1e30f;
                if (gn0 + 1 > gm_hi) s_[j][3] = -1e30f;
            }
        }
        float mx_lo = m_lo, mx_hi = m_hi;
        #pragma unroll
        for (int j = 0; j < 16; ++j) {
            mx_lo = fmaxf(mx_lo, fmaxf(s_[j][0], s_[j][1]));
            mx_hi = fmaxf(mx_hi, fmaxf(s_[j][2], s_[j][3]));
        }
        mx_lo = fmaxf(mx_lo, __shfl_xor_sync(0xffffffffu, mx_lo, 1));
        mx_lo = fmaxf(mx_lo, __shfl_xor_sync(0xffffffffu, mx_lo, 2));
        mx_hi = fmaxf(mx_hi, __shfl_xor_sync(0xffffffffu, mx_hi, 1));
        mx_hi = fmaxf(mx_hi, __shfl_xor_sync(0xffffffffu, mx_hi, 2));

        const float al = __expf(m_lo - mx_lo);
        const float ah = __expf(m_hi - mx_hi);
        m_lo = mx_lo; m_hi = mx_hi;

        float sl = 0.0f, sh = 0.0f;
        #pragma unroll
        for (int j = 0; j < 16; ++j) {
            float p0 = __expf(s_[j][0] - mx_lo);
            float p1 = __expf(s_[j][1] - mx_lo);
            float p2 = __expf(s_[j][2] - mx_hi);
            float p3 = __expf(s_[j][3] - mx_hi);
            s_[j][0] = p0; s_[j][1] = p1; s_[j][2] = p2; s_[j][3] = p3;
            sl += p0 + p1; sh += p2 + p3;
        }
        sl += __shfl_xor_sync(0xffffffffu, sl, 1);
        sl += __shfl_xor_sync(0xffffffffu, sl, 2);
        sh += __shfl_xor_sync(0xffffffffu, sh, 1);
        sh += __shfl_xor_sync(0xffffffffu, sh, 2);
        l_lo = l_lo * al + sl;
        l_hi = l_hi * ah + sh;
        #pragma unroll
        for (int n = 0; n < 16; ++n) {
            o_[n][0] *= al; o_[n][1] *= al;
            o_[n][2] *= ah; o_[n][3] *= ah;
        }

        // ---- wait for V_t, then PV (3-term split) ----
        if (t < qi) asm volatile("cp.async.wait_group 1;" ::: "memory");
        else        asm volatile("cp.async.wait_group 0;" ::: "memory");
        __syncthreads();

        const unsigned vB = sb + FV_OFF + (lane & 15) * 272 + (lane >> 4) * 16;
        #pragma unroll
        for (int kt2 = 0; kt2 < 8; ++kt2) {
            const float* pa = s_[2 * kt2];
            const float* pb = s_[2 * kt2 + 1];
            unsigned ahf[4], alf[4];
            ahf[0] = pack2(pa[0], pa[1]); ahf[1] = pack2(pa[2], pa[3]);
            ahf[2] = pack2(pb[0], pb[1]); ahf[3] = pack2(pb[2], pb[3]);
            alf[0] = pack2(bfres(pa[0]), bfres(pa[1]));
            alf[1] = pack2(bfres(pa[2]), bfres(pa[3]));
            alf[2] = pack2(bfres(pb[0]), bfres(pb[1]));
            alf[3] = pack2(bfres(pb[2]), bfres(pb[3]));
            #pragma unroll
            for (int vt = 0; vt < 8; ++vt) {
                unsigned r0, r1, r2, r3;
                ldsm4(r0, r1, r2, r3, vB + vt * 16 * 272 + kt2 * 32);
                mma16816(o_[2 * vt],     ahf, r0, r2);
                mma16816(o_[2 * vt + 1], ahf, r1, r3);
                mma16816(o_[2 * vt],     alf, r0, r2);
                mma16816(o_[2 * vt + 1], alf, r1, r3);
            }
            #pragma unroll
            for (int vt = 0; vt < 8; ++vt) {
                unsigned r0, r1, r2, r3;
                ldsm4(r0, r1, r2, r3, vB + FK_HALF + vt * 16 * 272 + kt2 * 32);
                mma16816(o_[2 * vt],     ahf, r0, r2);
                mma16816(o_[2 * vt + 1], ahf, r1, r3);
            }
        }
        __syncthreads();   // V/K buffers free for next iteration's loads
    }

    // ---- epilogue ----
    const float il = 1.0f / l_lo, ih = 1.0f / l_hi;
    float* orl = out + ((size_t)(b * Ssz + gm_lo) * Hh + h) * Dh;
    float* orh = out + ((size_t)(b * Ssz + gm_hi) * Hh + h) * Dh;
    #pragma unroll
    for (int n = 0; n < 16; ++n) {
        const int col = 8 * n + (lane & 3) * 2;
        *(float2*)(orl + col) = make_float2(o_[n][0] * il, o_[n][1] * il);
        *(float2*)(orh + col) = make_float2(o_[n][2] * ih, o_[n][3] * ih);
    }
}

// ---------------- host launch -------------------------------------------------
extern "C" void kernel_launch(void* const* d_in, const int* in_sizes, int n_in,
                              void* d_out, int out_size)
{
    const float* x   = (const float*)d_in[0];
    const float* Wq  = (const float*)d_in[1];
    const float* Wk  = (const float*)d_in[2];
    const float* Wv  = (const float*)d_in[3];
    const float* Wo  = (const float*)d_in[4];
    const float* qnw = (const float*)d_in[5];
    const float* knw = (const float*)d_in[6];
    const float* cs  = (const float*)d_in[7];
    const float* sn  = (const float*)d_in[8];

    float *qb, *kb, *vb, *ab;
    __nv_bfloat16 *xp, *ap, *wqt, *wkt, *wvt, *wot;
    __nv_bfloat16 *qhh, *qll, *khh, *kll, *vth, *vtl;
    cudaGetSymbolAddress((void**)&qb, g_q);
    cudaGetSymbolAddress((void**)&kb, g_k);
    cudaGetSymbolAddress((void**)&vb, g_v);
    cudaGetSymbolAddress((void**)&ab, g_att);
    cudaGetSymbolAddress((void**)&xp, g_xp);
    cudaGetSymbolAddress((void**)&ap, g_ap);
    cudaGetSymbolAddress((void**)&wqt, g_wqt);
    cudaGetSymbolAddress((void**)&wkt, g_wkt);
    cudaGetSymbolAddress((void**)&wvt, g_wvt);
    cudaGetSymbolAddress((void**)&wot, g_wot);
    cudaGetSymbolAddress((void**)&qhh, g_qh);
    cudaGetSymbolAddress((void**)&qll, g_ql);
    cudaGetSymbolAddress((void**)&khh, g_kh);
    cudaGetSymbolAddress((void**)&kll, g_kl);
    cudaGetSymbolAddress((void**)&vth, g_vth);
    cudaGetSymbolAddress((void**)&vtl, g_vtl);

    cudaFuncSetAttribute(gemm_mma, cudaFuncAttributeMaxDynamicSharedMemorySize, GEMM_SMEM);
    cudaFuncSetAttribute(flash_mma, cudaFuncAttributeMaxDynamicSharedMemorySize, FL_SMEM);

    // split/convert inputs + weights
    conv_a<<<8192, 256>>>(x, xp);
    conv_w<<<dim3(64, 64), 256>>>(Wq, wqt, 2048);
    conv_w<<<dim3(32, 64), 256>>>(Wk, wkt, 1024);
    conv_w<<<dim3(32, 64), 256>>>(Wv, wvt, 1024);
    conv_w<<<dim3(64, 64), 256>>>(Wo, wot, 2048);

    // QKV projections (bf16x3 HMMA)
    gemm_mma<<<dim3(16, 32), 256, GEMM_SMEM>>>(xp, wqt, qb, 2048);
    gemm_mma<<<dim3(8, 32), 256, GEMM_SMEM>>>(xp, wkt, kb, 1024);
    gemm_mma<<<dim3(8, 32), 256, GEMM_SMEM>>>(xp, wvt, vb, 1024);

    // RMSNorm + RoPE
    norm_rope_k<<<(Bsz * Ssz * Hh) / 8, 256>>>(qb, qnw, cs, sn, Hh);
    norm_rope_k<<<(Bsz * Ssz * KVh) / 8, 256>>>(kb, knw, cs, sn, KVh);

    // head-major bf16 splits for flash (Q pre-scaled by 1/sqrt(D))
    conv_qk<<<8192, 256>>>(qb, qhh, qll, Hh, 0.08838834764831845f);
    conv_qk<<<4096, 256>>>(kb, khh, kll, KVh, 1.0f);
    conv_vt<<<dim3(64, 4, 16), 256>>>(vb, vth, vtl);

    // flash attention (HMMA, kv-tile 128)
    flash_mma<<<dim3(16, Hh, Bsz), 256, FL_SMEM>>>(qhh, qll, khh, kll, vth, vtl, ab);

    // output projection
    conv_a<<<8192, 256>>>(ab, ap);
    gemm_mma<<<dim3(16, 32), 256, GEMM_SMEM>>>(ap, wot, (float*)d_out, 2048);
}

// round 8
// speedup vs baseline: 1.1168x; 1.1168x over previous
#include <cuda_runtime.h>
#include <cuda_bf16.h>
#include <math.h>

#define Bsz 2
#define Ssz 2048
#define HIDs 2048
#define Hh 16
#define KVh 8
#define Dh 128
#define KP 6144              // K' = 3*2048 for bf16x3 split
#define NT 96                // KP / 64 k-chunks
#define STG_A (128 * 72 * 2)            // 18432 B per A tile (stride 144B)
#define STG_BYTES (2 * STG_A)           // 36864
#define GEMM_SMEM (3 * STG_BYTES)       // 3-stage = 110592

// flash smem (R5 layout): per stage Kh[64][136],Kl[64][136],Vth[128][72],Vtl[128][72]
#define FL_STAGE 71680
#define FL_SMEM (2 * FL_STAGE)          // 143360

// ---------------- scratch (static device arrays: no allocs allowed) ----------
__device__ float g_qkv[(size_t)4096 * 4096];          // fused QKV output [M, 4096]
__device__ float g_att[(size_t)Bsz * Ssz * Hh * Dh];

__device__ __align__(16) __nv_bfloat16 g_xp[(size_t)4096 * KP];
__device__ __align__(16) __nv_bfloat16 g_ap[(size_t)4096 * KP];
__device__ __align__(16) __nv_bfloat16 g_wqkvt[(size_t)4096 * KP];  // Wq|Wk|Wv ^T split
__device__ __align__(16) __nv_bfloat16 g_wot[(size_t)2048 * KP];

// head-major bf16 splits for flash
__device__ __align__(16) __nv_bfloat16 g_qh[(size_t)Bsz * Hh * Ssz * Dh];
__device__ __align__(16) __nv_bfloat16 g_ql[(size_t)Bsz * Hh * Ssz * Dh];
__device__ __align__(16) __nv_bfloat16 g_kh[(size_t)Bsz * KVh * Ssz * Dh];
__device__ __align__(16) __nv_bfloat16 g_kl[(size_t)Bsz * KVh * Ssz * Dh];
__device__ __align__(16) __nv_bfloat16 g_vth[(size_t)Bsz * KVh * Dh * Ssz];
__device__ __align__(16) __nv_bfloat16 g_vtl[(size_t)Bsz * KVh * Dh * Ssz];

// ====================== PTX helpers =========================================
__device__ __forceinline__ unsigned smem_u32(const void* p) {
    unsigned a;
    asm("{ .reg .u64 t; cvta.to.shared.u64 t, %1; cvt.u32.u64 %0, t; }"
        : "=r"(a) : "l"(p));
    return a;
}
#define CP16(dst, src) \
    asm volatile("cp.async.cg.shared.global [%0], [%1], 16;" :: "r"(dst), "l"(src))
#define CP_COMMIT() asm volatile("cp.async.commit_group;")

__device__ __forceinline__ void ldsm4(unsigned& r0, unsigned& r1,
                                      unsigned& r2, unsigned& r3, unsigned a) {
    asm volatile("ldmatrix.sync.aligned.m8n8.x4.shared.b16 {%0,%1,%2,%3}, [%4];"
                 : "=r"(r0), "=r"(r1), "=r"(r2), "=r"(r3) : "r"(a));
}
__device__ __forceinline__ void mma16816(float* d, const unsigned* a,
                                         unsigned b0, unsigned b1) {
    asm volatile(
        "mma.sync.aligned.m16n8k16.row.col.f32.bf16.bf16.f32 "
        "{%0,%1,%2,%3}, {%4,%5,%6,%7}, {%8,%9}, {%0,%1,%2,%3};"
        : "+f"(d[0]), "+f"(d[1]), "+f"(d[2]), "+f"(d[3])
        : "r"(a[0]), "r"(a[1]), "r"(a[2]), "r"(a[3]), "r"(b0), "r"(b1));
}
__device__ __forceinline__ unsigned pack2(float lo, float hi) {
    unsigned d;
    asm("cvt.rn.bf16x2.f32 %0, %1, %2;" : "=r"(d) : "f"(hi), "f"(lo));
    return d;
}
__device__ __forceinline__ float bfres(float x) {
    return x - __bfloat162float(__float2bfloat16(x));
}

// ====================== conversion kernels ==================================
// A' = [hi | lo | hi] along K'   (src [M, 2048] fp32 row-major)
__global__ __launch_bounds__(256) void conv_a(
    const float* __restrict__ src, __nv_bfloat16* __restrict__ dst)
{
    size_t i = (size_t)blockIdx.x * 256 + threadIdx.x;
    int m = (int)(i >> 9);
    int k4 = (int)(i & 511);
    float4 v = ((const float4*)(src + (size_t)m * 2048))[k4];
    __nv_bfloat16 h0 = __float2bfloat16(v.x), h1 = __float2bfloat16(v.y);
    __nv_bfloat16 h2 = __float2bfloat16(v.z), h3 = __float2bfloat16(v.w);
    __nv_bfloat16 l0 = __float2bfloat16(v.x - __bfloat162float(h0));
    __nv_bfloat16 l1 = __float2bfloat16(v.y - __bfloat162float(h1));
    __nv_bfloat16 l2 = __float2bfloat16(v.z - __bfloat162float(h2));
    __nv_bfloat16 l3 = __float2bfloat16(v.w - __bfloat162float(h3));
    __nv_bfloat162 hA = __nv_bfloat162(h0, h1), hB = __nv_bfloat162(h2, h3);
    __nv_bfloat162 lA = __nv_bfloat162(l0, l1), lB = __nv_bfloat162(l2, l3);
    __nv_bfloat162* row = (__nv_bfloat162*)(dst + (size_t)m * KP) + k4 * 2;
    row[0] = hA; row[1] = hB;
    row[1024] = lA; row[1025] = lB;
    row[2048] = hA; row[2049] = hB;
}

// B' = W^T split: [n,k]=hi, [n,K+k]=hi, [n,2K+k]=lo.  W is [2048, N] fp32.
__global__ __launch_bounds__(256) void conv_w(
    const float* __restrict__ W, __nv_bfloat16* __restrict__ Bt, int N)
{
    __shared__ float ts[32][33];
    int n0 = blockIdx.x * 32, k0 = blockIdx.y * 32;
    int tx = threadIdx.x & 31, ty = threadIdx.x >> 5;
    #pragma unroll
    for (int r = 0; r < 4; ++r)
        ts[ty + r * 8][tx] = W[(size_t)(k0 + ty + r * 8) * N + n0 + tx];
    __syncthreads();
    #pragma unroll
    for (int r = 0; r < 4; ++r) {
        int n = n0 + ty + r * 8, k = k0 + tx;
        float v = ts[tx][ty + r * 8];
        __nv_bfloat16 hi = __float2bfloat16(v);
        __nv_bfloat16 lo = __float2bfloat16(v - __bfloat162float(hi));
        __nv_bfloat16* row = Bt + (size_t)n * KP;
        row[k] = hi; row[2048 + k] = hi; row[4096 + k] = lo;
    }
}

// fused-QKV source: [B,S, 4096] fp32, head block at col hh*128
// -> [B,nh,S,128] bf16 hi/lo (optionally scaled)
__global__ __launch_bounds__(256) void conv_qk(
    const float* __restrict__ src, __nv_bfloat16* __restrict__ dh,
    __nv_bfloat16* __restrict__ dl, int nh, float scale)
{
    size_t i = (size_t)blockIdx.x * 256 + threadIdx.x;   // over B*S*nh*32 f4
    int c4 = (int)(i & 31);
    size_t rest = i >> 5;
    int hh = (int)(rest % nh);
    size_t bs = rest / nh;
    float4 v = ((const float4*)src)[bs * 1024 + (size_t)hh * 32 + c4];
    v.x *= scale; v.y *= scale; v.z *= scale; v.w *= scale;
    __nv_bfloat16 h0 = __float2bfloat16(v.x), h1 = __float2bfloat16(v.y);
    __nv_bfloat16 h2 = __float2bfloat16(v.z), h3 = __float2bfloat16(v.w);
    __nv_bfloat16 l0 = __float2bfloat16(v.x - __bfloat162float(h0));
    __nv_bfloat16 l1 = __float2bfloat16(v.y - __bfloat162float(h1));
    __nv_bfloat16 l2 = __float2bfloat16(v.z - __bfloat162float(h2));
    __nv_bfloat16 l3 = __float2bfloat16(v.w - __bfloat162float(h3));
    int s = (int)(bs % Ssz), b = (int)(bs / Ssz);
    size_t o = ((((size_t)b * nh + hh) * Ssz + s) * 128 + c4 * 4) >> 2;
    ((__nv_bfloat162*)dh)[o * 2] = __nv_bfloat162(h0, h1);
    ((__nv_bfloat162*)dh)[o * 2 + 1] = __nv_bfloat162(h2, h3);
    ((__nv_bfloat162*)dl)[o * 2] = __nv_bfloat162(l0, l1);
    ((__nv_bfloat162*)dl)[o * 2 + 1] = __nv_bfloat162(l2, l3);
}

// V from fused buffer (base already offset to V cols): [B,S,4096-strided KV*128]
// -> Vt hi/lo [B*KV, 128, S] bf16
__global__ __launch_bounds__(256) void conv_vt(
    const float* __restrict__ v, __nv_bfloat16* __restrict__ th,
    __nv_bfloat16* __restrict__ tl)
{
    __shared__ float ts[32][33];
    int s0 = blockIdx.x * 32, d0 = blockIdx.y * 32;
    int bk = blockIdx.z;
    int b = bk >> 3, kv = bk & 7;
    int tx = threadIdx.x & 31, ty = threadIdx.x >> 5;
    #pragma unroll
    for (int r = 0; r < 4; ++r)
        ts[ty + r * 8][tx] =
            v[(size_t)(b * Ssz + s0 + ty + r * 8) * 4096 + kv * 128 + d0 + tx];
    __syncthreads();
    #pragma unroll
    for (int r = 0; r < 4; ++r) {
        float x = ts[tx][ty + r * 8];
        __nv_bfloat16 hi = __float2bfloat16(x);
        __nv_bfloat16 lo = __float2bfloat16(x - __bfloat162float(hi));
        size_t o = ((size_t)bk * 128 + d0 + ty + r * 8) * Ssz + s0 + tx;
        th[o] = hi; tl[o] = lo;
    }
}

// ====================== HMMA bf16 GEMM (3-stage, 1 barrier/chunk) ===========
__global__ __launch_bounds__(256, 2) void gemm_mma(
    const __nv_bfloat16* __restrict__ A, const __nv_bfloat16* __restrict__ Bm,
    float* __restrict__ C, int N)
{
    extern __shared__ __align__(16) char smem[];
    const unsigned sb = smem_u32(smem);
    const int tid = threadIdx.x;
    const int lane = tid & 31;
    const int wid = tid >> 5;
    const int wr = wid >> 1;
    const int wc = wid & 1;
    const int bm = blockIdx.y << 7, bn = blockIdx.x << 7;

    const int lrow = tid >> 3, lcol = tid & 7;
    const __nv_bfloat16* Ag = A + (size_t)(bm + lrow) * KP + lcol * 8;
    const __nv_bfloat16* Bg = Bm + (size_t)(bn + lrow) * KP + lcol * 8;
    const unsigned sOff = lrow * 144 + lcol * 16;

    float acc[2][8][4];
    #pragma unroll
    for (int i = 0; i < 2; ++i)
        #pragma unroll
        for (int j = 0; j < 8; ++j)
            #pragma unroll
            for (int e = 0; e < 4; ++e) acc[i][j][e] = 0.0f;

    const unsigned aBase0 = sb + (32 * wr + (lane & 15)) * 144 + (lane >> 4) * 16;
    const unsigned bBase0 = sb + STG_A + (64 * wc + (lane & 15)) * 144 + (lane >> 4) * 16;

    // prologue: chunks 0,1 into stages 0,1
    #pragma unroll
    for (int c = 0; c < 2; ++c) {
        const unsigned st = c * STG_BYTES;
        const unsigned as = sb + st + sOff, bs = sb + st + STG_A + sOff;
        const __nv_bfloat16* ag = Ag + (size_t)c * 64;
        const __nv_bfloat16* bg = Bg + (size_t)c * 64;
        #pragma unroll
        for (int i = 0; i < 4; ++i) {
            CP16(as + i * 32 * 144, ag + (size_t)(32 * i) * KP);
            CP16(bs + i * 32 * 144, bg + (size_t)(32 * i) * KP);
        }
        CP_COMMIT();
    }

    int stage = 0, nstage = 2;
    for (int c = 0; c < NT; ++c) {
        if (c + 1 < NT) asm volatile("cp.async.wait_group 1;" ::: "memory");
        else            asm volatile("cp.async.wait_group 0;" ::: "memory");
        __syncthreads();

        if (c + 2 < NT) {
            const unsigned st = nstage * STG_BYTES;
            const unsigned as = sb + st + sOff, bs = sb + st + STG_A + sOff;
            const __nv_bfloat16* ag = Ag + (size_t)(c + 2) * 64;
            const __nv_bfloat16* bg = Bg + (size_t)(c + 2) * 64;
            #pragma unroll
            for (int i = 0; i < 4; ++i) {
                CP16(as + i * 32 * 144, ag + (size_t)(32 * i) * KP);
                CP16(bs + i * 32 * 144, bg + (size_t)(32 * i) * KP);
            }
            CP_COMMIT();
            nstage = (nstage == 2) ? 0 : nstage + 1;
        }

        const unsigned st = stage * STG_BYTES;
        stage = (stage == 2) ? 0 : stage + 1;
        const unsigned aB = aBase0 + st, bB = bBase0 + st;
        #pragma unroll
        for (int ks = 0; ks < 4; ++ks) {
            unsigned a[2][4];
            ldsm4(a[0][0], a[0][1], a[0][2], a[0][3], aB + ks * 32);
            ldsm4(a[1][0], a[1][1], a[1][2], a[1][3], aB + 16 * 144 + ks * 32);
            unsigned b[8][2];
            #pragma unroll
            for (int nt = 0; nt < 4; ++nt) {
                unsigned r0, r1, r2, r3;
                ldsm4(r0, r1, r2, r3, bB + nt * 16 * 144 + ks * 32);
                b[nt * 2][0] = r0; b[nt * 2][1] = r2;
                b[nt * 2 + 1][0] = r1; b[nt * 2 + 1][1] = r3;
            }
            #pragma unroll
            for (int mt = 0; mt < 2; ++mt)
                #pragma unroll
                for (int nt = 0; nt < 8; ++nt)
                    mma16816(acc[mt][nt], a[mt], b[nt][0], b[nt][1]);
        }
    }

    #pragma unroll
    for (int mt = 0; mt < 2; ++mt) {
        const int r0 = bm + 32 * wr + 16 * mt + (lane >> 2);
        #pragma unroll
        for (int nt = 0; nt < 8; ++nt) {
            const int col = bn + 64 * wc + 8 * nt + (lane & 3) * 2;
            float2 v0 = make_float2(acc[mt][nt][0], acc[mt][nt][1]);
            float2 v1 = make_float2(acc[mt][nt][2], acc[mt][nt][3]);
            *(float2*)&C[(size_t)r0 * N + col]       = v0;
            *(float2*)&C[(size_t)(r0 + 8) * N + col] = v1;
        }
    }
}

// ---------------- RMSNorm + RoPE (in place, fused-QKV layout) ----------------
// t points at the first head column; token row stride is 4096 floats.
__global__ __launch_bounds__(256) void norm_rope_k(
    float* __restrict__ t, const float* __restrict__ w,
    const float* __restrict__ cs, const float* __restrict__ sn, int nh)
{
    const int warp = blockIdx.x * 8 + (threadIdx.x >> 5);
    const int lane = threadIdx.x & 31;
    const int tok = warp / nh;
    const int head = warp % nh;
    const int s = tok % Ssz;

    float* row = t + (size_t)tok * 4096 + head * Dh;
    float v0 = row[lane];
    float v1 = row[lane + 32];
    float v2 = row[lane + 64];
    float v3 = row[lane + 96];

    float ss = v0 * v0 + v1 * v1 + v2 * v2 + v3 * v3;
    #pragma unroll
    for (int o = 16; o; o >>= 1) ss += __shfl_xor_sync(0xffffffffu, ss, o);
    float r = rsqrtf(ss * (1.0f / 128.0f) + 1e-6f);

    v0 = v0 * r * w[lane];
    v1 = v1 * r * w[lane + 32];
    v2 = v2 * r * w[lane + 64];
    v3 = v3 * r * w[lane + 96];

    const float* cr = cs + (size_t)s * Dh;
    const float* sr = sn + (size_t)s * Dh;
    float o0 = v0 * cr[lane]      - v2 * sr[lane];
    float o1 = v1 * cr[lane + 32] - v3 * sr[lane + 32];
    float o2 = v2 * cr[lane + 64] + v0 * sr[lane + 64];
    float o3 = v3 * cr[lane + 96] + v1 * sr[lane + 96];

    row[lane]      = o0;
    row[lane + 32] = o1;
    row[lane + 64] = o2;
    row[lane + 96] = o3;
}

// ====================== HMMA flash attention (R5 schedule) ==================
__device__ __forceinline__ void load_kv_tile(
    unsigned sbase, int tid,
    const __nv_bfloat16* khp, const __nv_bfloat16* klp,
    const __nv_bfloat16* vthp, const __nv_bfloat16* vtlp, int nBase)
{
    const int r = tid >> 2, c0 = (tid & 3) * 4;
    const char* gk = (const char*)(khp + (size_t)(nBase + r) * 128) + c0 * 16;
    const char* gl = (const char*)(klp + (size_t)(nBase + r) * 128) + c0 * 16;
    const unsigned dk = sbase + r * 272 + c0 * 16;
    #pragma unroll
    for (int i = 0; i < 4; ++i) {
        CP16(dk + i * 16, gk + i * 16);
        CP16(dk + 17408 + i * 16, gl + i * 16);
    }
    const int r2 = tid >> 1, c2 = (tid & 1) * 4;
    const char* gv = (const char*)(vthp + (size_t)r2 * Ssz + nBase) + c2 * 16;
    const char* gw = (const char*)(vtlp + (size_t)r2 * Ssz + nBase) + c2 * 16;
    const unsigned dv = sbase + 34816 + r2 * 144 + c2 * 16;
    #pragma unroll
    for (int i = 0; i < 4; ++i) {
        CP16(dv + i * 16, gv + i * 16);
        CP16(dv + 18432 + i * 16, gw + i * 16);
    }
}

__global__ __launch_bounds__(256, 1) void flash_mma(
    const __nv_bfloat16* __restrict__ qh, const __nv_bfloat16* __restrict__ ql,
    const __nv_bfloat16* __restrict__ kh, const __nv_bfloat16* __restrict__ kl,
    const __nv_bfloat16* __restrict__ vth, const __nv_bfloat16* __restrict__ vtl,
    float* __restrict__ out)
{
    extern __shared__ __align__(16) char smem[];
    const unsigned sb = smem_u32(smem);
    const int tid = threadIdx.x, lane = tid & 31, w = tid >> 5;
    const int qi = 15 - blockIdx.x;
    const int h = blockIdx.y, b = blockIdx.z;
    const int kvh = h >> 1;
    const int mBase = qi << 7;
    const int ntiles = 2 * qi + 2;

    const __nv_bfloat16* qhp = qh + (((size_t)b * Hh + h) * Ssz + mBase) * Dh;
    const __nv_bfloat16* qlp = ql + (((size_t)b * Hh + h) * Ssz + mBase) * Dh;
    const __nv_bfloat16* khp = kh + ((size_t)b * KVh + kvh) * Ssz * Dh;
    const __nv_bfloat16* klp = kl + ((size_t)b * KVh + kvh) * Ssz * Dh;
    const __nv_bfloat16* vthp = vth + ((size_t)b * KVh + kvh) * Dh * Ssz;
    const __nv_bfloat16* vtlp = vtl + ((size_t)b * KVh + kvh) * Dh * Ssz;

    // prologue: Q into stage1 region, KV tile0 into stage0
    {
        const int r = tid >> 1, cb = (tid & 1) * 8;
        const unsigned dq = sb + FL_STAGE + r * 272 + cb * 16;
        const char* gq = (const char*)(qhp + (size_t)r * Dh) + cb * 16;
        const char* gl = (const char*)(qlp + (size_t)r * Dh) + cb * 16;
        #pragma unroll
        for (int i = 0; i < 8; ++i) {
            CP16(dq + i * 16, gq + i * 16);
            CP16(dq + 34816 + i * 16, gl + i * 16);
        }
    }
    load_kv_tile(sb, tid, khp, klp, vthp, vtlp, 0);
    CP_COMMIT();
    asm volatile("cp.async.wait_group 0;" ::: "memory");
    __syncthreads();

    // extract Q fragments to registers
    unsigned qhf[8][4], qlf[8][4];
    {
        const unsigned qB = sb + FL_STAGE + (16 * w + (lane & 15)) * 272 + (lane >> 4) * 16;
        #pragma unroll
        for (int kt = 0; kt < 8; ++kt) {
            ldsm4(qhf[kt][0], qhf[kt][1], qhf[kt][2], qhf[kt][3], qB + kt * 32);
            ldsm4(qlf[kt][0], qlf[kt][1], qlf[kt][2], qlf[kt][3], qB + 34816 + kt * 32);
        }
    }
    __syncthreads();

    float o_[16][4];
    #pragma unroll
    for (int n = 0; n < 16; ++n)
        #pragma unroll
        for (int e = 0; e < 4; ++e) o_[n][e] = 0.0f;
    float m_lo = -1e30f, m_hi = -1e30f, l_lo = 0.0f, l_hi = 0.0f;
    const int gm_lo = mBase + 16 * w + (lane >> 2);
    const int gm_hi = gm_lo + 8;

    for (int t = 0; t < ntiles; ++t) {
        if (t + 1 < ntiles) {
            load_kv_tile(sb + ((t + 1) & 1) * FL_STAGE, tid, khp, klp, vthp, vtlp,
                         (t + 1) * 64);
            CP_COMMIT();
            asm volatile("cp.async.wait_group 1;" ::: "memory");
        } else {
            asm volatile("cp.async.wait_group 0;" ::: "memory");
        }
        __syncthreads();
        const unsigned stb = sb + (t & 1) * FL_STAGE;

        // ---- QK^T (3-term split) ----
        float s_[8][4];
        #pragma unroll
        for (int j = 0; j < 8; ++j)
            #pragma unroll
            for (int e = 0; e < 4; ++e) s_[j][e] = 0.0f;

        const unsigned kB = stb + (lane & 15) * 272 + (lane >> 4) * 16;
        #pragma unroll
        for (int kt = 0; kt < 8; ++kt) {
            #pragma unroll
            for (int nt = 0; nt < 4; ++nt) {
                unsigned r0, r1, r2, r3;
                ldsm4(r0, r1, r2, r3, kB + nt * 16 * 272 + kt * 32);
                mma16816(s_[nt * 2],     qhf[kt], r0, r2);
                mma16816(s_[nt * 2 + 1], qhf[kt], r1, r3);
                mma16816(s_[nt * 2],     qlf[kt], r0, r2);
                mma16816(s_[nt * 2 + 1], qlf[kt], r1, r3);
            }
            #pragma unroll
            for (int nt = 0; nt < 4; ++nt) {
                unsigned r0, r1, r2, r3;
                ldsm4(r0, r1, r2, r3, kB + 17408 + nt * 16 * 272 + kt * 32);
                mma16816(s_[nt * 2],     qhf[kt], r0, r2);
                mma16816(s_[nt * 2 + 1], qhf[kt], r1, r3);
            }
        }

        // ---- mask (last two tiles only) + online softmax ----
        const int nBase = t * 64;
        if (t >= 2 * qi) {
            #pragma unroll
            for (int j = 0; j < 8; ++j) {
                const int gn0 = nBase + 8 * j + (lane & 3) * 2;
                if (gn0 > gm_lo)     s_[j][0] = -1e30f;
                if (gn0 + 1 > gm_lo) s_[j][1] = -1e30f;
                if (gn0 > gm_hi)     s_[j][2] = -1e30f;
                if (gn0 + 1 > gm_hi) s_[j][3] = -1e30f;
            }
        }
        float mx_lo = m_lo, mx_hi = m_hi;
        #pragma unroll
        for (int j = 0; j < 8; ++j) {
            mx_lo = fmaxf(mx_lo, fmaxf(s_[j][0], s_[j][1]));
            mx_hi = fmaxf(mx_hi, fmaxf(s_[j][2], s_[j][3]));
        }
        mx_lo = fmaxf(mx_lo, __shfl_xor_sync(0xffffffffu, mx_lo, 1));
        mx_lo = fmaxf(mx_lo, __shfl_xor_sync(0xffffffffu, mx_lo, 2));
        mx_hi = fmaxf(mx_hi, __shfl_xor_sync(0xffffffffu, mx_hi, 1));
        mx_hi = fmaxf(mx_hi, __shfl_xor_sync(0xffffffffu, mx_hi, 2));

        const float al = __expf(m_lo - mx_lo);
        const float ah = __expf(m_hi - mx_hi);
        m_lo = mx_lo; m_hi = mx_hi;

        float sl = 0.0f, sh = 0.0f;
        #pragma unroll
        for (int j = 0; j < 8; ++j) {
            float p0 = __expf(s_[j][0] - mx_lo);
            float p1 = __expf(s_[j][1] - mx_lo);
            float p2 = __expf(s_[j][2] - mx_hi);
            float p3 = __expf(s_[j][3] - mx_hi);
            s_[j][0] = p0; s_[j][1] = p1; s_[j][2] = p2; s_[j][3] = p3;
            sl += p0 + p1; sh += p2 + p3;
        }
        sl += __shfl_xor_sync(0xffffffffu, sl, 1);
        sl += __shfl_xor_sync(0xffffffffu, sl, 2);
        sh += __shfl_xor_sync(0xffffffffu, sh, 1);
        sh += __shfl_xor_sync(0xffffffffu, sh, 2);
        l_lo = l_lo * al + sl;
        l_hi = l_hi * ah + sh;
        #pragma unroll
        for (int n = 0; n < 16; ++n) {
            o_[n][0] *= al; o_[n][1] *= al;
            o_[n][2] *= ah; o_[n][3] *= ah;
        }

        // ---- PV (3-term split, P from registers) ----
        const unsigned vB = stb + 34816 + (lane & 15) * 144 + (lane >> 4) * 16;
        #pragma unroll
        for (int kt2 = 0; kt2 < 4; ++kt2) {
            const float* pa = s_[2 * kt2];
            const float* pb = s_[2 * kt2 + 1];
            unsigned ahf[4], alf[4];
            ahf[0] = pack2(pa[0], pa[1]); ahf[1] = pack2(pa[2], pa[3]);
            ahf[2] = pack2(pb[0], pb[1]); ahf[3] = pack2(pb[2], pb[3]);
            alf[0] = pack2(bfres(pa[0]), bfres(pa[1]));
            alf[1] = pack2(bfres(pa[2]), bfres(pa[3]));
            alf[2] = pack2(bfres(pb[0]), bfres(pb[1]));
            alf[3] = pack2(bfres(pb[2]), bfres(pb[3]));
            #pragma unroll
            for (int vt = 0; vt < 8; ++vt) {
                unsigned r0, r1, r2, r3;
                ldsm4(r0, r1, r2, r3, vB + vt * 16 * 144 + kt2 * 32);
                mma16816(o_[2 * vt],     ahf, r0, r2);
                mma16816(o_[2 * vt + 1], ahf, r1, r3);
                mma16816(o_[2 * vt],     alf, r0, r2);
                mma16816(o_[2 * vt + 1], alf, r1, r3);
            }
            #pragma unroll
            for (int vt = 0; vt < 8; ++vt) {
                unsigned r0, r1, r2, r3;
                ldsm4(r0, r1, r2, r3, vB + 18432 + vt * 16 * 144 + kt2 * 32);
                mma16816(o_[2 * vt],     ahf, r0, r2);
                mma16816(o_[2 * vt + 1], ahf, r1, r3);
            }
        }
        __syncthreads();
    }

    // ---- epilogue ----
    const float il = 1.0f / l_lo, ih = 1.0f / l_hi;
    float* orl = out + ((size_t)(b * Ssz + gm_lo) * Hh + h) * Dh;
    float* orh = out + ((size_t)(b * Ssz + gm_hi) * Hh + h) * Dh;
    #pragma unroll
    for (int n = 0; n < 16; ++n) {
        const int col = 8 * n + (lane & 3) * 2;
        *(float2*)(orl + col) = make_float2(o_[n][0] * il, o_[n][1] * il);
        *(float2*)(orh + col) = make_float2(o_[n][2] * ih, o_[n][3] * ih);
    }
}

// ---------------- host launch -------------------------------------------------
extern "C" void kernel_launch(void* const* d_in, const int* in_sizes, int n_in,
                              void* d_out, int out_size)
{
    const float* x   = (const float*)d_in[0];
    const float* Wq  = (const float*)d_in[1];
    const float* Wk  = (const float*)d_in[2];
    const float* Wv  = (const float*)d_in[3];
    const float* Wo  = (const float*)d_in[4];
    const float* qnw = (const float*)d_in[5];
    const float* knw = (const float*)d_in[6];
    const float* cs  = (const float*)d_in[7];
    const float* sn  = (const float*)d_in[8];

    float *qkv, *ab;
    __nv_bfloat16 *xp, *ap, *wqkvt, *wot;
    __nv_bfloat16 *qhh, *qll, *khh, *kll, *vth, *vtl;
    cudaGetSymbolAddress((void**)&qkv, g_qkv);
    cudaGetSymbolAddress((void**)&ab, g_att);
    cudaGetSymbolAddress((void**)&xp, g_xp);
    cudaGetSymbolAddress((void**)&ap, g_ap);
    cudaGetSymbolAddress((void**)&wqkvt, g_wqkvt);
    cudaGetSymbolAddress((void**)&wot, g_wot);
    cudaGetSymbolAddress((void**)&qhh, g_qh);
    cudaGetSymbolAddress((void**)&qll, g_ql);
    cudaGetSymbolAddress((void**)&khh, g_kh);
    cudaGetSymbolAddress((void**)&kll, g_kl);
    cudaGetSymbolAddress((void**)&vth, g_vth);
    cudaGetSymbolAddress((void**)&vtl, g_vtl);

    cudaFuncSetAttribute(gemm_mma, cudaFuncAttributeMaxDynamicSharedMemorySize, GEMM_SMEM);
    cudaFuncSetAttribute(flash_mma, cudaFuncAttributeMaxDynamicSharedMemorySize, FL_SMEM);

    // split/convert inputs + weights (QKV weights concatenated along N)
    conv_a<<<8192, 256>>>(x, xp);
    conv_w<<<dim3(64, 64), 256>>>(Wq, wqkvt, 2048);
    conv_w<<<dim3(32, 64), 256>>>(Wk, wqkvt + (size_t)2048 * KP, 1024);
    conv_w<<<dim3(32, 64), 256>>>(Wv, wqkvt + (size_t)3072 * KP, 1024);
    conv_w<<<dim3(64, 64), 256>>>(Wo, wot, 2048);

    // fused QKV projection (bf16x3 HMMA): C = [Q | K | V], [4096, 4096]
    gemm_mma<<<dim3(32, 32), 256, GEMM_SMEM>>>(xp, wqkvt, qkv, 4096);

    // RMSNorm + RoPE in the fused buffer (token stride 4096)
    norm_rope_k<<<(Bsz * Ssz * Hh) / 8, 256>>>(qkv, qnw, cs, sn, Hh);
    norm_rope_k<<<(Bsz * Ssz * KVh) / 8, 256>>>(qkv + 2048, knw, cs, sn, KVh);

    // head-major bf16 splits for flash (Q pre-scaled by 1/sqrt(D))
    conv_qk<<<8192, 256>>>(qkv, qhh, qll, Hh, 0.08838834764831845f);
    conv_qk<<<4096, 256>>>(qkv + 2048, khh, kll, KVh, 1.0f);
    conv_vt<<<dim3(64, 4, 16), 256>>>(qkv + 3072, vth, vtl);

    // flash attention (HMMA, R5 schedule)
    flash_mma<<<dim3(16, Hh, Bsz), 256, FL_SMEM>>>(qhh, qll, khh, kll, vth, vtl, ab);

    // output projection
    conv_a<<<8192, 256>>>(ab, ap);
    gemm_mma<<<dim3(16, 32), 256, GEMM_SMEM>>>(ap, wot, (float*)d_out, 2048);
}

// round 9
// speedup vs baseline: 1.1281x; 1.0101x over previous
#include <cuda_runtime.h>
#include <cuda_bf16.h>
#include <math.h>

#define Bsz 2
#define Ssz 2048
#define HIDs 2048
#define Hh 16
#define KVh 8
#define Dh 128
#define KP 6144              // K' = 3*2048 for bf16x3 split
#define NT 96                // KP / 64 k-chunks
#define STG_A (128 * 72 * 2)            // 18432 B per A tile (stride 144B)
#define STG_BYTES (2 * STG_A)           // 36864
#define GEMM_SMEM (3 * STG_BYTES)       // 3-stage = 110592

// flash smem (R5 layout): per stage Kh[64][136],Kl[64][136],Vth[128][72],Vtl[128][72]
#define FL_STAGE 71680
#define FL_SMEM (2 * FL_STAGE)          // 143360

// ---------------- scratch (static device arrays: no allocs allowed) ----------
__device__ float g_qkv[(size_t)4096 * 4096];          // fused QKV output [M, 4096]

__device__ __align__(16) __nv_bfloat16 g_xp[(size_t)4096 * KP];
__device__ __align__(16) __nv_bfloat16 g_ap[(size_t)4096 * KP];   // att split (flash writes)
__device__ __align__(16) __nv_bfloat16 g_wqkvt[(size_t)4096 * KP];
__device__ __align__(16) __nv_bfloat16 g_wot[(size_t)2048 * KP];

// head-major bf16 splits for flash
__device__ __align__(16) __nv_bfloat16 g_qh[(size_t)Bsz * Hh * Ssz * Dh];
__device__ __align__(16) __nv_bfloat16 g_ql[(size_t)Bsz * Hh * Ssz * Dh];
__device__ __align__(16) __nv_bfloat16 g_kh[(size_t)Bsz * KVh * Ssz * Dh];
__device__ __align__(16) __nv_bfloat16 g_kl[(size_t)Bsz * KVh * Ssz * Dh];
__device__ __align__(16) __nv_bfloat16 g_vth[(size_t)Bsz * KVh * Dh * Ssz];
__device__ __align__(16) __nv_bfloat16 g_vtl[(size_t)Bsz * KVh * Dh * Ssz];

// ====================== PTX helpers =========================================
__device__ __forceinline__ unsigned smem_u32(const void* p) {
    unsigned a;
    asm("{ .reg .u64 t; cvta.to.shared.u64 t, %1; cvt.u32.u64 %0, t; }"
        : "=r"(a) : "l"(p));
    return a;
}
#define CP16(dst, src) \
    asm volatile("cp.async.cg.shared.global [%0], [%1], 16;" :: "r"(dst), "l"(src))
#define CP_COMMIT() asm volatile("cp.async.commit_group;")

__device__ __forceinline__ void ldsm4(unsigned& r0, unsigned& r1,
                                      unsigned& r2, unsigned& r3, unsigned a) {
    asm volatile("ldmatrix.sync.aligned.m8n8.x4.shared.b16 {%0,%1,%2,%3}, [%4];"
                 : "=r"(r0), "=r"(r1), "=r"(r2), "=r"(r3) : "r"(a));
}
__device__ __forceinline__ void mma16816(float* d, const unsigned* a,
                                         unsigned b0, unsigned b1) {
    asm volatile(
        "mma.sync.aligned.m16n8k16.row.col.f32.bf16.bf16.f32 "
        "{%0,%1,%2,%3}, {%4,%5,%6,%7}, {%8,%9}, {%0,%1,%2,%3};"
        : "+f"(d[0]), "+f"(d[1]), "+f"(d[2]), "+f"(d[3])
        : "r"(a[0]), "r"(a[1]), "r"(a[2]), "r"(a[3]), "r"(b0), "r"(b1));
}
__device__ __forceinline__ unsigned pack2(float lo, float hi) {
    unsigned d;
    asm("cvt.rn.bf16x2.f32 %0, %1, %2;" : "=r"(d) : "f"(hi), "f"(lo));
    return d;
}
__device__ __forceinline__ float bfres(float x) {
    return x - __bfloat162float(__float2bfloat16(x));
}
__device__ __forceinline__ float ex2(float x) {
    float r;
    asm("ex2.approx.f32 %0, %1;" : "=f"(r) : "f"(x));
    return r;
}

// ====================== conversion kernels ==================================
// A' = [hi | lo | hi] along K'   (src [M, 2048] fp32 row-major)
__global__ __launch_bounds__(256) void conv_a(
    const float* __restrict__ src, __nv_bfloat16* __restrict__ dst)
{
    size_t i = (size_t)blockIdx.x * 256 + threadIdx.x;
    int m = (int)(i >> 9);
    int k4 = (int)(i & 511);
    float4 v = ((const float4*)(src + (size_t)m * 2048))[k4];
    __nv_bfloat16 h0 = __float2bfloat16(v.x), h1 = __float2bfloat16(v.y);
    __nv_bfloat16 h2 = __float2bfloat16(v.z), h3 = __float2bfloat16(v.w);
    __nv_bfloat16 l0 = __float2bfloat16(v.x - __bfloat162float(h0));
    __nv_bfloat16 l1 = __float2bfloat16(v.y - __bfloat162float(h1));
    __nv_bfloat16 l2 = __float2bfloat16(v.z - __bfloat162float(h2));
    __nv_bfloat16 l3 = __float2bfloat16(v.w - __bfloat162float(h3));
    __nv_bfloat162 hA = __nv_bfloat162(h0, h1), hB = __nv_bfloat162(h2, h3);
    __nv_bfloat162 lA = __nv_bfloat162(l0, l1), lB = __nv_bfloat162(l2, l3);
    __nv_bfloat162* row = (__nv_bfloat162*)(dst + (size_t)m * KP) + k4 * 2;
    row[0] = hA; row[1] = hB;
    row[1024] = lA; row[1025] = lB;
    row[2048] = hA; row[2049] = hB;
}

// B' = W^T split: [n,k]=hi, [n,K+k]=hi, [n,2K+k]=lo.  W is [2048, N] fp32.
__global__ __launch_bounds__(256) void conv_w(
    const float* __restrict__ W, __nv_bfloat16* __restrict__ Bt, int N)
{
    __shared__ float ts[32][33];
    int n0 = blockIdx.x * 32, k0 = blockIdx.y * 32;
    int tx = threadIdx.x & 31, ty = threadIdx.x >> 5;
    #pragma unroll
    for (int r = 0; r < 4; ++r)
        ts[ty + r * 8][tx] = W[(size_t)(k0 + ty + r * 8) * N + n0 + tx];
    __syncthreads();
    #pragma unroll
    for (int r = 0; r < 4; ++r) {
        int n = n0 + ty + r * 8, k = k0 + tx;
        float v = ts[tx][ty + r * 8];
        __nv_bfloat16 hi = __float2bfloat16(v);
        __nv_bfloat16 lo = __float2bfloat16(v - __bfloat162float(hi));
        __nv_bfloat16* row = Bt + (size_t)n * KP;
        row[k] = hi; row[2048 + k] = hi; row[4096 + k] = lo;
    }
}

// fused RMSNorm + RoPE + bf16 hi/lo split + head-major write.
// qkv: [tok, 4096] fp32 at baseCol; one warp per (tok, head).
__global__ __launch_bounds__(256) void norm_rope_split(
    const float* __restrict__ qkv, int baseCol, int nh,
    const float* __restrict__ w,
    const float* __restrict__ cs, const float* __restrict__ sn,
    __nv_bfloat16* __restrict__ dh, __nv_bfloat16* __restrict__ dl,
    float scale)
{
    const int warp = blockIdx.x * 8 + (threadIdx.x >> 5);
    const int lane = threadIdx.x & 31;
    const int tok = warp / nh;          // b*S + s
    const int head = warp % nh;
    const int s = tok % Ssz;
    const int b = tok / Ssz;

    const float* row = qkv + (size_t)tok * 4096 + baseCol + head * Dh;
    float v0 = row[lane];
    float v1 = row[lane + 32];
    float v2 = row[lane + 64];
    float v3 = row[lane + 96];

    float ss = v0 * v0 + v1 * v1 + v2 * v2 + v3 * v3;
    #pragma unroll
    for (int o = 16; o; o >>= 1) ss += __shfl_xor_sync(0xffffffffu, ss, o);
    float r = rsqrtf(ss * (1.0f / 128.0f) + 1e-6f);

    v0 = v0 * r * w[lane];
    v1 = v1 * r * w[lane + 32];
    v2 = v2 * r * w[lane + 64];
    v3 = v3 * r * w[lane + 96];

    const float* cr = cs + (size_t)s * Dh;
    const float* sr = sn + (size_t)s * Dh;
    float o0 = (v0 * cr[lane]      - v2 * sr[lane])      * scale;
    float o1 = (v1 * cr[lane + 32] - v3 * sr[lane + 32]) * scale;
    float o2 = (v2 * cr[lane + 64] + v0 * sr[lane + 64]) * scale;
    float o3 = (v3 * cr[lane + 96] + v1 * sr[lane + 96]) * scale;

    __nv_bfloat16 h0 = __float2bfloat16(o0), h1 = __float2bfloat16(o1);
    __nv_bfloat16 h2 = __float2bfloat16(o2), h3 = __float2bfloat16(o3);
    __nv_bfloat16 e0 = __float2bfloat16(o0 - __bfloat162float(h0));
    __nv_bfloat16 e1 = __float2bfloat16(o1 - __bfloat162float(h1));
    __nv_bfloat16 e2 = __float2bfloat16(o2 - __bfloat162float(h2));
    __nv_bfloat16 e3 = __float2bfloat16(o3 - __bfloat162float(h3));

    size_t o = (((size_t)b * nh + head) * Ssz + s) * 128;
    dh[o + lane]      = h0; dh[o + lane + 32] = h1;
    dh[o + lane + 64] = h2; dh[o + lane + 96] = h3;
    dl[o + lane]      = e0; dl[o + lane + 32] = e1;
    dl[o + lane + 64] = e2; dl[o + lane + 96] = e3;
}

// V from fused buffer (base already offset to V cols) -> Vt hi/lo [B*KV,128,S]
__global__ __launch_bounds__(256) void conv_vt(
    const float* __restrict__ v, __nv_bfloat16* __restrict__ th,
    __nv_bfloat16* __restrict__ tl)
{
    __shared__ float ts[32][33];
    int s0 = blockIdx.x * 32, d0 = blockIdx.y * 32;
    int bk = blockIdx.z;
    int b = bk >> 3, kv = bk & 7;
    int tx = threadIdx.x & 31, ty = threadIdx.x >> 5;
    #pragma unroll
    for (int r = 0; r < 4; ++r)
        ts[ty + r * 8][tx] =
            v[(size_t)(b * Ssz + s0 + ty + r * 8) * 4096 + kv * 128 + d0 + tx];
    __syncthreads();
    #pragma unroll
    for (int r = 0; r < 4; ++r) {
        float x = ts[tx][ty + r * 8];
        __nv_bfloat16 hi = __float2bfloat16(x);
        __nv_bfloat16 lo = __float2bfloat16(x - __bfloat162float(hi));
        size_t o = ((size_t)bk * 128 + d0 + ty + r * 8) * Ssz + s0 + tx;
        th[o] = hi; tl[o] = lo;
    }
}

// ====================== HMMA bf16 GEMM (3-stage, 1 barrier/chunk) ===========
__global__ __launch_bounds__(256, 2) void gemm_mma(
    const __nv_bfloat16* __restrict__ A, const __nv_bfloat16* __restrict__ Bm,
    float* __restrict__ C, int N)
{
    extern __shared__ __align__(16) char smem[];
    const unsigned sb = smem_u32(smem);
    const int tid = threadIdx.x;
    const int lane = tid & 31;
    const int wid = tid >> 5;
    const int wr = wid >> 1;
    const int wc = wid & 1;
    const int bm = blockIdx.y << 7, bn = blockIdx.x << 7;

    const int lrow = tid >> 3, lcol = tid & 7;
    const __nv_bfloat16* Ag = A + (size_t)(bm + lrow) * KP + lcol * 8;
    const __nv_bfloat16* Bg = Bm + (size_t)(bn + lrow) * KP + lcol * 8;
    const unsigned sOff = lrow * 144 + lcol * 16;

    float acc[2][8][4];
    #pragma unroll
    for (int i = 0; i < 2; ++i)
        #pragma unroll
        for (int j = 0; j < 8; ++j)
            #pragma unroll
            for (int e = 0; e < 4; ++e) acc[i][j][e] = 0.0f;

    const unsigned aBase0 = sb + (32 * wr + (lane & 15)) * 144 + (lane >> 4) * 16;
    const unsigned bBase0 = sb + STG_A + (64 * wc + (lane & 15)) * 144 + (lane >> 4) * 16;

    #pragma unroll
    for (int c = 0; c < 2; ++c) {
        const unsigned st = c * STG_BYTES;
        const unsigned as = sb + st + sOff, bs = sb + st + STG_A + sOff;
        const __nv_bfloat16* ag = Ag + (size_t)c * 64;
        const __nv_bfloat16* bg = Bg + (size_t)c * 64;
        #pragma unroll
        for (int i = 0; i < 4; ++i) {
            CP16(as + i * 32 * 144, ag + (size_t)(32 * i) * KP);
            CP16(bs + i * 32 * 144, bg + (size_t)(32 * i) * KP);
        }
        CP_COMMIT();
    }

    int stage = 0, nstage = 2;
    for (int c = 0; c < NT; ++c) {
        if (c + 1 < NT) asm volatile("cp.async.wait_group 1;" ::: "memory");
        else            asm volatile("cp.async.wait_group 0;" ::: "memory");
        __syncthreads();

        if (c + 2 < NT) {
            const unsigned st = nstage * STG_BYTES;
            const unsigned as = sb + st + sOff, bs = sb + st + STG_A + sOff;
            const __nv_bfloat16* ag = Ag + (size_t)(c + 2) * 64;
            const __nv_bfloat16* bg = Bg + (size_t)(c + 2) * 64;
            #pragma unroll
            for (int i = 0; i < 4; ++i) {
                CP16(as + i * 32 * 144, ag + (size_t)(32 * i) * KP);
                CP16(bs + i * 32 * 144, bg + (size_t)(32 * i) * KP);
            }
            CP_COMMIT();
            nstage = (nstage == 2) ? 0 : nstage + 1;
        }

        const unsigned st = stage * STG_BYTES;
        stage = (stage == 2) ? 0 : stage + 1;
        const unsigned aB = aBase0 + st, bB = bBase0 + st;
        #pragma unroll
        for (int ks = 0; ks < 4; ++ks) {
            unsigned a[2][4];
            ldsm4(a[0][0], a[0][1], a[0][2], a[0][3], aB + ks * 32);
            ldsm4(a[1][0], a[1][1], a[1][2], a[1][3], aB + 16 * 144 + ks * 32);
            unsigned b[8][2];
            #pragma unroll
            for (int nt = 0; nt < 4; ++nt) {
                unsigned r0, r1, r2, r3;
                ldsm4(r0, r1, r2, r3, bB + nt * 16 * 144 + ks * 32);
                b[nt * 2][0] = r0; b[nt * 2][1] = r2;
                b[nt * 2 + 1][0] = r1; b[nt * 2 + 1][1] = r3;
            }
            #pragma unroll
            for (int mt = 0; mt < 2; ++mt)
                #pragma unroll
                for (int nt = 0; nt < 8; ++nt)
                    mma16816(acc[mt][nt], a[mt], b[nt][0], b[nt][1]);
        }
    }

    #pragma unroll
    for (int mt = 0; mt < 2; ++mt) {
        const int r0 = bm + 32 * wr + 16 * mt + (lane >> 2);
        #pragma unroll
        for (int nt = 0; nt < 8; ++nt) {
            const int col = bn + 64 * wc + 8 * nt + (lane & 3) * 2;
            float2 v0 = make_float2(acc[mt][nt][0], acc[mt][nt][1]);
            float2 v1 = make_float2(acc[mt][nt][2], acc[mt][nt][3]);
            *(float2*)&C[(size_t)r0 * N + col]       = v0;
            *(float2*)&C[(size_t)(r0 + 8) * N + col] = v1;
        }
    }
}

// ====================== HMMA flash attention (R5 schedule, exp2 domain) =====
__device__ __forceinline__ void load_kv_tile(
    unsigned sbase, int tid,
    const __nv_bfloat16* khp, const __nv_bfloat16* klp,
    const __nv_bfloat16* vthp, const __nv_bfloat16* vtlp, int nBase)
{
    const int r = tid >> 2, c0 = (tid & 3) * 4;
    const char* gk = (const char*)(khp + (size_t)(nBase + r) * 128) + c0 * 16;
    const char* gl = (const char*)(klp + (size_t)(nBase + r) * 128) + c0 * 16;
    const unsigned dk = sbase + r * 272 + c0 * 16;
    #pragma unroll
    for (int i = 0; i < 4; ++i) {
        CP16(dk + i * 16, gk + i * 16);
        CP16(dk + 17408 + i * 16, gl + i * 16);
    }
    const int r2 = tid >> 1, c2 = (tid & 1) * 4;
    const char* gv = (const char*)(vthp + (size_t)r2 * Ssz + nBase) + c2 * 16;
    const char* gw = (const char*)(vtlp + (size_t)r2 * Ssz + nBase) + c2 * 16;
    const unsigned dv = sbase + 34816 + r2 * 144 + c2 * 16;
    #pragma unroll
    for (int i = 0; i < 4; ++i) {
        CP16(dv + i * 16, gv + i * 16);
        CP16(dv + 18432 + i * 16, gw + i * 16);
    }
}

__global__ __launch_bounds__(256, 1) void flash_mma(
    const __nv_bfloat16* __restrict__ qh, const __nv_bfloat16* __restrict__ ql,
    const __nv_bfloat16* __restrict__ kh, const __nv_bfloat16* __restrict__ kl,
    const __nv_bfloat16* __restrict__ vth, const __nv_bfloat16* __restrict__ vtl,
    __nv_bfloat16* __restrict__ outp)     // split [M, KP] hi|lo|hi
{
    extern __shared__ __align__(16) char smem[];
    const unsigned sb = smem_u32(smem);
    const int tid = threadIdx.x, lane = tid & 31, w = tid >> 5;
    const int qi = 15 - blockIdx.x;
    const int h = blockIdx.y, b = blockIdx.z;
    const int kvh = h >> 1;
    const int mBase = qi << 7;
    const int ntiles = 2 * qi + 2;

    const __nv_bfloat16* qhp = qh + (((size_t)b * Hh + h) * Ssz + mBase) * Dh;
    const __nv_bfloat16* qlp = ql + (((size_t)b * Hh + h) * Ssz + mBase) * Dh;
    const __nv_bfloat16* khp = kh + ((size_t)b * KVh + kvh) * Ssz * Dh;
    const __nv_bfloat16* klp = kl + ((size_t)b * KVh + kvh) * Ssz * Dh;
    const __nv_bfloat16* vthp = vth + ((size_t)b * KVh + kvh) * Dh * Ssz;
    const __nv_bfloat16* vtlp = vtl + ((size_t)b * KVh + kvh) * Dh * Ssz;

    // prologue: Q into stage1 region, KV tile0 into stage0
    {
        const int r = tid >> 1, cb = (tid & 1) * 8;
        const unsigned dq = sb + FL_STAGE + r * 272 + cb * 16;
        const char* gq = (const char*)(qhp + (size_t)r * Dh) + cb * 16;
        const char* gl = (const char*)(qlp + (size_t)r * Dh) + cb * 16;
        #pragma unroll
        for (int i = 0; i < 8; ++i) {
            CP16(dq + i * 16, gq + i * 16);
            CP16(dq + 34816 + i * 16, gl + i * 16);
        }
    }
    load_kv_tile(sb, tid, khp, klp, vthp, vtlp, 0);
    CP_COMMIT();
    asm volatile("cp.async.wait_group 0;" ::: "memory");
    __syncthreads();

    unsigned qhf[8][4], qlf[8][4];
    {
        const unsigned qB = sb + FL_STAGE + (16 * w + (lane & 15)) * 272 + (lane >> 4) * 16;
        #pragma unroll
        for (int kt = 0; kt < 8; ++kt) {
            ldsm4(qhf[kt][0], qhf[kt][1], qhf[kt][2], qhf[kt][3], qB + kt * 32);
            ldsm4(qlf[kt][0], qlf[kt][1], qlf[kt][2], qlf[kt][3], qB + 34816 + kt * 32);
        }
    }
    __syncthreads();

    float o_[16][4];
    #pragma unroll
    for (int n = 0; n < 16; ++n)
        #pragma unroll
        for (int e = 0; e < 4; ++e) o_[n][e] = 0.0f;
    float m_lo = -1e30f, m_hi = -1e30f, l_lo = 0.0f, l_hi = 0.0f;
    const int gm_lo = mBase + 16 * w + (lane >> 2);
    const int gm_hi = gm_lo + 8;

    for (int t = 0; t < ntiles; ++t) {
        if (t + 1 < ntiles) {
            load_kv_tile(sb + ((t + 1) & 1) * FL_STAGE, tid, khp, klp, vthp, vtlp,
                         (t + 1) * 64);
            CP_COMMIT();
            asm volatile("cp.async.wait_group 1;" ::: "memory");
        } else {
            asm volatile("cp.async.wait_group 0;" ::: "memory");
        }
        __syncthreads();
        const unsigned stb = sb + (t & 1) * FL_STAGE;

        // ---- QK^T (3-term split); scores already in log2 domain ----
        float s_[8][4];
        #pragma unroll
        for (int j = 0; j < 8; ++j)
            #pragma unroll
            for (int e = 0; e < 4; ++e) s_[j][e] = 0.0f;

        const unsigned kB = stb + (lane & 15) * 272 + (lane >> 4) * 16;
        #pragma unroll
        for (int kt = 0; kt < 8; ++kt) {
            #pragma unroll
            for (int nt = 0; nt < 4; ++nt) {
                unsigned r0, r1, r2, r3;
                ldsm4(r0, r1, r2, r3, kB + nt * 16 * 272 + kt * 32);
                mma16816(s_[nt * 2],     qhf[kt], r0, r2);
                mma16816(s_[nt * 2 + 1], qhf[kt], r1, r3);
                mma16816(s_[nt * 2],     qlf[kt], r0, r2);
                mma16816(s_[nt * 2 + 1], qlf[kt], r1, r3);
            }
            #pragma unroll
            for (int nt = 0; nt < 4; ++nt) {
                unsigned r0, r1, r2, r3;
                ldsm4(r0, r1, r2, r3, kB + 17408 + nt * 16 * 272 + kt * 32);
                mma16816(s_[nt * 2],     qhf[kt], r0, r2);
                mma16816(s_[nt * 2 + 1], qhf[kt], r1, r3);
            }
        }

        // ---- mask (last two tiles only) + online softmax (base-2) ----
        const int nBase = t * 64;
        if (t >= 2 * qi) {
            #pragma unroll
            for (int j = 0; j < 8; ++j) {
                const int gn0 = nBase + 8 * j + (lane & 3) * 2;
                if (gn0 > gm_lo)     s_[j][0] = -1e30f;
                if (gn0 + 1 > gm_lo) s_[j][1] = -1e30f;
                if (gn0 > gm_hi)     s_[j][2] = -1e30f;
                if (gn0 + 1 > gm_hi) s_[j][3] = -1e30f;
            }
        }
        float mx_lo = m_lo, mx_hi = m_hi;
        #pragma unroll
        for (int j = 0; j < 8; ++j) {
            mx_lo = fmaxf(mx_lo, fmaxf(s_[j][0], s_[j][1]));
            mx_hi = fmaxf(mx_hi, fmaxf(s_[j][2], s_[j][3]));
        }
        mx_lo = fmaxf(mx_lo, __shfl_xor_sync(0xffffffffu, mx_lo, 1));
        mx_lo = fmaxf(mx_lo, __shfl_xor_sync(0xffffffffu, mx_lo, 2));
        mx_hi = fmaxf(mx_hi, __shfl_xor_sync(0xffffffffu, mx_hi, 1));
        mx_hi = fmaxf(mx_hi, __shfl_xor_sync(0xffffffffu, mx_hi, 2));

        const float al = ex2(m_lo - mx_lo);
        const float ah = ex2(m_hi - mx_hi);
        m_lo = mx_lo; m_hi = mx_hi;

        float sl = 0.0f, sh = 0.0f;
        #pragma unroll
        for (int j = 0; j < 8; ++j) {
            float p0 = ex2(s_[j][0] - mx_lo);
            float p1 = ex2(s_[j][1] - mx_lo);
            float p2 = ex2(s_[j][2] - mx_hi);
            float p3 = ex2(s_[j][3] - mx_hi);
            s_[j][0] = p0; s_[j][1] = p1; s_[j][2] = p2; s_[j][3] = p3;
            sl += p0 + p1; sh += p2 + p3;
        }
        sl += __shfl_xor_sync(0xffffffffu, sl, 1);
        sl += __shfl_xor_sync(0xffffffffu, sl, 2);
        sh += __shfl_xor_sync(0xffffffffu, sh, 1);
        sh += __shfl_xor_sync(0xffffffffu, sh, 2);
        l_lo = l_lo * al + sl;
        l_hi = l_hi * ah + sh;
        #pragma unroll
        for (int n = 0; n < 16; ++n) {
            o_[n][0] *= al; o_[n][1] *= al;
            o_[n][2] *= ah; o_[n][3] *= ah;
        }

        // ---- PV (3-term split, P from registers) ----
        const unsigned vB = stb + 34816 + (lane & 15) * 144 + (lane >> 4) * 16;
        #pragma unroll
        for (int kt2 = 0; kt2 < 4; ++kt2) {
            const float* pa = s_[2 * kt2];
            const float* pb = s_[2 * kt2 + 1];
            unsigned ahf[4], alf[4];
            ahf[0] = pack2(pa[0], pa[1]); ahf[1] = pack2(pa[2], pa[3]);
            ahf[2] = pack2(pb[0], pb[1]); ahf[3] = pack2(pb[2], pb[3]);
            alf[0] = pack2(bfres(pa[0]), bfres(pa[1]));
            alf[1] = pack2(bfres(pa[2]), bfres(pa[3]));
            alf[2] = pack2(bfres(pb[0]), bfres(pb[1]));
            alf[3] = pack2(bfres(pb[2]), bfres(pb[3]));
            #pragma unroll
            for (int vt = 0; vt < 8; ++vt) {
                unsigned r0, r1, r2, r3;
                ldsm4(r0, r1, r2, r3, vB + vt * 16 * 144 + kt2 * 32);
                mma16816(o_[2 * vt],     ahf, r0, r2);
                mma16816(o_[2 * vt + 1], ahf, r1, r3);
                mma16816(o_[2 * vt],     alf, r0, r2);
                mma16816(o_[2 * vt + 1], alf, r1, r3);
            }
            #pragma unroll
            for (int vt = 0; vt < 8; ++vt) {
                unsigned r0, r1, r2, r3;
                ldsm4(r0, r1, r2, r3, vB + 18432 + vt * 16 * 144 + kt2 * 32);
                mma16816(o_[2 * vt],     ahf, r0, r2);
                mma16816(o_[2 * vt + 1], ahf, r1, r3);
            }
        }
        __syncthreads();
    }

    // ---- epilogue: write split bf16 [M,KP] directly (hi | lo | hi) ----
    const float il = 1.0f / l_lo, ih = 1.0f / l_hi;
    __nv_bfloat16* arl = outp + (size_t)(b * Ssz + gm_lo) * KP + h * Dh;
    __nv_bfloat16* arh = outp + (size_t)(b * Ssz + gm_hi) * KP + h * Dh;
    #pragma unroll
    for (int n = 0; n < 16; ++n) {
        const int col = 8 * n + (lane & 3) * 2;
        float a0 = o_[n][0] * il, a1 = o_[n][1] * il;
        float b0 = o_[n][2] * ih, b1 = o_[n][3] * ih;
        __nv_bfloat16 ah0 = __float2bfloat16(a0), ah1 = __float2bfloat16(a1);
        __nv_bfloat16 bh0 = __float2bfloat16(b0), bh1 = __float2bfloat16(b1);
        __nv_bfloat162 aH = __nv_bfloat162(ah0, ah1);
        __nv_bfloat162 bH = __nv_bfloat162(bh0, bh1);
        __nv_bfloat162 aL = __nv_bfloat162(
            __float2bfloat16(a0 - __bfloat162float(ah0)),
            __float2bfloat16(a1 - __bfloat162float(ah1)));
        __nv_bfloat162 bL = __nv_bfloat162(
            __float2bfloat16(b0 - __bfloat162float(bh0)),
            __float2bfloat16(b1 - __bfloat162float(bh1)));
        *(__nv_bfloat162*)(arl + col)        = aH;
        *(__nv_bfloat162*)(arl + 2048 + col) = aL;
        *(__nv_bfloat162*)(arl + 4096 + col) = aH;
        *(__nv_bfloat162*)(arh + col)        = bH;
        *(__nv_bfloat162*)(arh + 2048 + col) = bL;
        *(__nv_bfloat162*)(arh + 4096 + col) = bH;
    }
}

// ---------------- host launch -------------------------------------------------
extern "C" void kernel_launch(void* const* d_in, const int* in_sizes, int n_in,
                              void* d_out, int out_size)
{
    const float* x   = (const float*)d_in[0];
    const float* Wq  = (const float*)d_in[1];
    const float* Wk  = (const float*)d_in[2];
    const float* Wv  = (const float*)d_in[3];
    const float* Wo  = (const float*)d_in[4];
    const float* qnw = (const float*)d_in[5];
    const float* knw = (const float*)d_in[6];
    const float* cs  = (const float*)d_in[7];
    const float* sn  = (const float*)d_in[8];

    float *qkv;
    __nv_bfloat16 *xp, *ap, *wqkvt, *wot;
    __nv_bfloat16 *qhh, *qll, *khh, *kll, *vth, *vtl;
    cudaGetSymbolAddress((void**)&qkv, g_qkv);
    cudaGetSymbolAddress((void**)&xp, g_xp);
    cudaGetSymbolAddress((void**)&ap, g_ap);
    cudaGetSymbolAddress((void**)&wqkvt, g_wqkvt);
    cudaGetSymbolAddress((void**)&wot, g_wot);
    cudaGetSymbolAddress((void**)&qhh, g_qh);
    cudaGetSymbolAddress((void**)&qll, g_ql);
    cudaGetSymbolAddress((void**)&khh, g_kh);
    cudaGetSymbolAddress((void**)&kll, g_kl);
    cudaGetSymbolAddress((void**)&vth, g_vth);
    cudaGetSymbolAddress((void**)&vtl, g_vtl);

    cudaFuncSetAttribute(gemm_mma, cudaFuncAttributeMaxDynamicSharedMemorySize, GEMM_SMEM);
    cudaFuncSetAttribute(flash_mma, cudaFuncAttributeMaxDynamicSharedMemorySize, FL_SMEM);

    // split/convert inputs + weights (QKV weights concatenated along N)
    conv_a<<<8192, 256>>>(x, xp);
    conv_w<<<dim3(64, 64), 256>>>(Wq, wqkvt, 2048);
    conv_w<<<dim3(32, 64), 256>>>(Wk, wqkvt + (size_t)2048 * KP, 1024);
    conv_w<<<dim3(32, 64), 256>>>(Wv, wqkvt + (size_t)3072 * KP, 1024);
    conv_w<<<dim3(64, 64), 256>>>(Wo, wot, 2048);

    // fused QKV projection (bf16x3 HMMA): C = [Q | K | V], [4096, 4096]
    gemm_mma<<<dim3(32, 32), 256, GEMM_SMEM>>>(xp, wqkvt, qkv, 4096);

    // fused RMSNorm + RoPE + split (Q pre-scaled by SCALE*log2e for exp2 softmax)
    const float qscale = (float)(0.08838834764831845 * 1.4426950408889634);
    norm_rope_split<<<8192, 256>>>(qkv, 0, Hh, qnw, cs, sn, qhh, qll, qscale);
    norm_rope_split<<<4096, 256>>>(qkv, 2048, KVh, knw, cs, sn, khh, kll, 1.0f);
    conv_vt<<<dim3(64, 4, 16), 256>>>(qkv + 3072, vth, vtl);

    // flash attention (HMMA, exp2 domain) -> writes split [M,KP] directly
    flash_mma<<<dim3(16, Hh, Bsz), 256, FL_SMEM>>>(qhh, qll, khh, kll, vth, vtl, ap);

    // output projection
    gemm_mma<<<dim3(16, 32), 256, GEMM_SMEM>>>(ap, wot, (float*)d_out, 2048);
}

// round 10
// speedup vs baseline: 1.1289x; 1.0007x over previous
#include <cuda_runtime.h>
#include <cuda_bf16.h>
#include <math.h>

#define Bsz 2
#define Ssz 2048
#define HIDs 2048
#define Hh 16
#define KVh 8
#define Dh 128
#define KP 6144              // K' = 3*2048 for bf16x3 split
#define NT 96                // KP / 64 k-chunks
#define STG_A (128 * 72 * 2)            // 18432 B per A tile (stride 144B)
#define STG_BYTES (2 * STG_A)           // 36864
#define GEMM_SMEM (3 * STG_BYTES)       // 3-stage = 110592

// flash smem (R5 layout): per stage Kh[64][136],Kl[64][136],Vth[128][72],Vtl[128][72]
#define FL_STAGE 71680
#define FL_SMEM (2 * FL_STAGE)          // 143360

// ---------------- scratch (static device arrays: no allocs allowed) ----------
__device__ float g_qkv[(size_t)4096 * 4096];          // fused QKV output [M, 4096]

__device__ __align__(16) __nv_bfloat16 g_xp[(size_t)4096 * KP];
__device__ __align__(16) __nv_bfloat16 g_ap[(size_t)4096 * KP];   // att split (flash writes)
__device__ __align__(16) __nv_bfloat16 g_wqkvt[(size_t)4096 * KP];
__device__ __align__(16) __nv_bfloat16 g_wot[(size_t)2048 * KP];

// head-major bf16 splits for flash
__device__ __align__(16) __nv_bfloat16 g_qh[(size_t)Bsz * Hh * Ssz * Dh];
__device__ __align__(16) __nv_bfloat16 g_ql[(size_t)Bsz * Hh * Ssz * Dh];
__device__ __align__(16) __nv_bfloat16 g_kh[(size_t)Bsz * KVh * Ssz * Dh];
__device__ __align__(16) __nv_bfloat16 g_kl[(size_t)Bsz * KVh * Ssz * Dh];
__device__ __align__(16) __nv_bfloat16 g_vth[(size_t)Bsz * KVh * Dh * Ssz];
__device__ __align__(16) __nv_bfloat16 g_vtl[(size_t)Bsz * KVh * Dh * Ssz];

// ====================== PTX helpers =========================================
__device__ __forceinline__ unsigned smem_u32(const void* p) {
    unsigned a;
    asm("{ .reg .u64 t; cvta.to.shared.u64 t, %1; cvt.u32.u64 %0, t; }"
        : "=r"(a) : "l"(p));
    return a;
}
#define CP16(dst, src) \
    asm volatile("cp.async.cg.shared.global [%0], [%1], 16;" :: "r"(dst), "l"(src))
#define CP_COMMIT() asm volatile("cp.async.commit_group;")

__device__ __forceinline__ void ldsm4(unsigned& r0, unsigned& r1,
                                      unsigned& r2, unsigned& r3, unsigned a) {
    asm volatile("ldmatrix.sync.aligned.m8n8.x4.shared.b16 {%0,%1,%2,%3}, [%4];"
                 : "=r"(r0), "=r"(r1), "=r"(r2), "=r"(r3) : "r"(a));
}
__device__ __forceinline__ void mma16816(float* d, const unsigned* a,
                                         unsigned b0, unsigned b1) {
    asm volatile(
        "mma.sync.aligned.m16n8k16.row.col.f32.bf16.bf16.f32 "
        "{%0,%1,%2,%3}, {%4,%5,%6,%7}, {%8,%9}, {%0,%1,%2,%3};"
        : "+f"(d[0]), "+f"(d[1]), "+f"(d[2]), "+f"(d[3])
        : "r"(a[0]), "r"(a[1]), "r"(a[2]), "r"(a[3]), "r"(b0), "r"(b1));
}
__device__ __forceinline__ unsigned pack2(float lo, float hi) {
    unsigned d;
    asm("cvt.rn.bf16x2.f32 %0, %1, %2;" : "=r"(d) : "f"(hi), "f"(lo));
    return d;
}
__device__ __forceinline__ float bfres(float x) {
    return x - __bfloat162float(__float2bfloat16(x));
}
__device__ __forceinline__ float ex2(float x) {
    float r;
    asm("ex2.approx.f32 %0, %1;" : "=f"(r) : "f"(x));
    return r;
}

// ====================== conversion kernels ==================================
// A' = [hi | lo | hi] along K'   (src [M, 2048] fp32 row-major)
__global__ __launch_bounds__(256) void conv_a(
    const float* __restrict__ src, __nv_bfloat16* __restrict__ dst)
{
    size_t i = (size_t)blockIdx.x * 256 + threadIdx.x;
    int m = (int)(i >> 9);
    int k4 = (int)(i & 511);
    float4 v = ((const float4*)(src + (size_t)m * 2048))[k4];
    __nv_bfloat16 h0 = __float2bfloat16(v.x), h1 = __float2bfloat16(v.y);
    __nv_bfloat16 h2 = __float2bfloat16(v.z), h3 = __float2bfloat16(v.w);
    __nv_bfloat16 l0 = __float2bfloat16(v.x - __bfloat162float(h0));
    __nv_bfloat16 l1 = __float2bfloat16(v.y - __bfloat162float(h1));
    __nv_bfloat16 l2 = __float2bfloat16(v.z - __bfloat162float(h2));
    __nv_bfloat16 l3 = __float2bfloat16(v.w - __bfloat162float(h3));
    __nv_bfloat162 hA = __nv_bfloat162(h0, h1), hB = __nv_bfloat162(h2, h3);
    __nv_bfloat162 lA = __nv_bfloat162(l0, l1), lB = __nv_bfloat162(l2, l3);
    __nv_bfloat162* row = (__nv_bfloat162*)(dst + (size_t)m * KP) + k4 * 2;
    row[0] = hA; row[1] = hB;
    row[1024] = lA; row[1025] = lB;
    row[2048] = hA; row[2049] = hB;
}

// B' = W^T split: [n,k]=hi, [n,K+k]=hi, [n,2K+k]=lo.  W is [2048, N] fp32.
__global__ __launch_bounds__(256) void conv_w(
    const float* __restrict__ W, __nv_bfloat16* __restrict__ Bt, int N)
{
    __shared__ float ts[32][33];
    int n0 = blockIdx.x * 32, k0 = blockIdx.y * 32;
    int tx = threadIdx.x & 31, ty = threadIdx.x >> 5;
    #pragma unroll
    for (int r = 0; r < 4; ++r)
        ts[ty + r * 8][tx] = W[(size_t)(k0 + ty + r * 8) * N + n0 + tx];
    __syncthreads();
    #pragma unroll
    for (int r = 0; r < 4; ++r) {
        int n = n0 + ty + r * 8, k = k0 + tx;
        float v = ts[tx][ty + r * 8];
        __nv_bfloat16 hi = __float2bfloat16(v);
        __nv_bfloat16 lo = __float2bfloat16(v - __bfloat162float(hi));
        __nv_bfloat16* row = Bt + (size_t)n * KP;
        row[k] = hi; row[2048 + k] = hi; row[4096 + k] = lo;
    }
}

// fused RMSNorm + RoPE + bf16 hi/lo split + head-major write.
__global__ __launch_bounds__(256) void norm_rope_split(
    const float* __restrict__ qkv, int baseCol, int nh,
    const float* __restrict__ w,
    const float* __restrict__ cs, const float* __restrict__ sn,
    __nv_bfloat16* __restrict__ dh, __nv_bfloat16* __restrict__ dl,
    float scale)
{
    const int warp = blockIdx.x * 8 + (threadIdx.x >> 5);
    const int lane = threadIdx.x & 31;
    const int tok = warp / nh;          // b*S + s
    const int head = warp % nh;
    const int s = tok % Ssz;
    const int b = tok / Ssz;

    const float* row = qkv + (size_t)tok * 4096 + baseCol + head * Dh;
    float v0 = row[lane];
    float v1 = row[lane + 32];
    float v2 = row[lane + 64];
    float v3 = row[lane + 96];

    float ss = v0 * v0 + v1 * v1 + v2 * v2 + v3 * v3;
    #pragma unroll
    for (int o = 16; o; o >>= 1) ss += __shfl_xor_sync(0xffffffffu, ss, o);
    float r = rsqrtf(ss * (1.0f / 128.0f) + 1e-6f);

    v0 = v0 * r * w[lane];
    v1 = v1 * r * w[lane + 32];
    v2 = v2 * r * w[lane + 64];
    v3 = v3 * r * w[lane + 96];

    const float* cr = cs + (size_t)s * Dh;
    const float* sr = sn + (size_t)s * Dh;
    float o0 = (v0 * cr[lane]      - v2 * sr[lane])      * scale;
    float o1 = (v1 * cr[lane + 32] - v3 * sr[lane + 32]) * scale;
    float o2 = (v2 * cr[lane + 64] + v0 * sr[lane + 64]) * scale;
    float o3 = (v3 * cr[lane + 96] + v1 * sr[lane + 96]) * scale;

    __nv_bfloat16 h0 = __float2bfloat16(o0), h1 = __float2bfloat16(o1);
    __nv_bfloat16 h2 = __float2bfloat16(o2), h3 = __float2bfloat16(o3);
    __nv_bfloat16 e0 = __float2bfloat16(o0 - __bfloat162float(h0));
    __nv_bfloat16 e1 = __float2bfloat16(o1 - __bfloat162float(h1));
    __nv_bfloat16 e2 = __float2bfloat16(o2 - __bfloat162float(h2));
    __nv_bfloat16 e3 = __float2bfloat16(o3 - __bfloat162float(h3));

    size_t o = (((size_t)b * nh + head) * Ssz + s) * 128;
    dh[o + lane]      = h0; dh[o + lane + 32] = h1;
    dh[o + lane + 64] = h2; dh[o + lane + 96] = h3;
    dl[o + lane]      = e0; dl[o + lane + 32] = e1;
    dl[o + lane + 64] = e2; dl[o + lane + 96] = e3;
}

// V from fused buffer (base already offset to V cols) -> Vt hi/lo [B*KV,128,S]
__global__ __launch_bounds__(256) void conv_vt(
    const float* __restrict__ v, __nv_bfloat16* __restrict__ th,
    __nv_bfloat16* __restrict__ tl)
{
    __shared__ float ts[32][33];
    int s0 = blockIdx.x * 32, d0 = blockIdx.y * 32;
    int bk = blockIdx.z;
    int b = bk >> 3, kv = bk & 7;
    int tx = threadIdx.x & 31, ty = threadIdx.x >> 5;
    #pragma unroll
    for (int r = 0; r < 4; ++r)
        ts[ty + r * 8][tx] =
            v[(size_t)(b * Ssz + s0 + ty + r * 8) * 4096 + kv * 128 + d0 + tx];
    __syncthreads();
    #pragma unroll
    for (int r = 0; r < 4; ++r) {
        float x = ts[tx][ty + r * 8];
        __nv_bfloat16 hi = __float2bfloat16(x);
        __nv_bfloat16 lo = __float2bfloat16(x - __bfloat162float(hi));
        size_t o = ((size_t)bk * 128 + d0 + ty + r * 8) * Ssz + s0 + tx;
        th[o] = hi; tl[o] = lo;
    }
}

// ====================== HMMA bf16 GEMM (3-stage, 1 barrier/chunk) ===========
__global__ __launch_bounds__(256, 2) void gemm_mma(
    const __nv_bfloat16* __restrict__ A, const __nv_bfloat16* __restrict__ Bm,
    float* __restrict__ C, int N)
{
    extern __shared__ __align__(16) char smem[];
    const unsigned sb = smem_u32(smem);
    const int tid = threadIdx.x;
    const int lane = tid & 31;
    const int wid = tid >> 5;
    const int wr = wid >> 1;
    const int wc = wid & 1;
    const int bm = blockIdx.y << 7, bn = blockIdx.x << 7;

    const int lrow = tid >> 3, lcol = tid & 7;
    const __nv_bfloat16* Ag = A + (size_t)(bm + lrow) * KP + lcol * 8;
    const __nv_bfloat16* Bg = Bm + (size_t)(bn + lrow) * KP + lcol * 8;
    const unsigned sOff = lrow * 144 + lcol * 16;

    float acc[2][8][4];
    #pragma unroll
    for (int i = 0; i < 2; ++i)
        #pragma unroll
        for (int j = 0; j < 8; ++j)
            #pragma unroll
            for (int e = 0; e < 4; ++e) acc[i][j][e] = 0.0f;

    const unsigned aBase0 = sb + (32 * wr + (lane & 15)) * 144 + (lane >> 4) * 16;
    const unsigned bBase0 = sb + STG_A + (64 * wc + (lane & 15)) * 144 + (lane >> 4) * 16;

    #pragma unroll
    for (int c = 0; c < 2; ++c) {
        const unsigned st = c * STG_BYTES;
        const unsigned as = sb + st + sOff, bs = sb + st + STG_A + sOff;
        const __nv_bfloat16* ag = Ag + (size_t)c * 64;
        const __nv_bfloat16* bg = Bg + (size_t)c * 64;
        #pragma unroll
        for (int i = 0; i < 4; ++i) {
            CP16(as + i * 32 * 144, ag + (size_t)(32 * i) * KP);
            CP16(bs + i * 32 * 144, bg + (size_t)(32 * i) * KP);
        }
        CP_COMMIT();
    }

    int stage = 0, nstage = 2;
    for (int c = 0; c < NT; ++c) {
        if (c + 1 < NT) asm volatile("cp.async.wait_group 1;" ::: "memory");
        else            asm volatile("cp.async.wait_group 0;" ::: "memory");
        __syncthreads();

        if (c + 2 < NT) {
            const unsigned st = nstage * STG_BYTES;
            const unsigned as = sb + st + sOff, bs = sb + st + STG_A + sOff;
            const __nv_bfloat16* ag = Ag + (size_t)(c + 2) * 64;
            const __nv_bfloat16* bg = Bg + (size_t)(c + 2) * 64;
            #pragma unroll
            for (int i = 0; i < 4; ++i) {
                CP16(as + i * 32 * 144, ag + (size_t)(32 * i) * KP);
                CP16(bs + i * 32 * 144, bg + (size_t)(32 * i) * KP);
            }
            CP_COMMIT();
            nstage = (nstage == 2) ? 0 : nstage + 1;
        }

        const unsigned st = stage * STG_BYTES;
        stage = (stage == 2) ? 0 : stage + 1;
        const unsigned aB = aBase0 + st, bB = bBase0 + st;
        #pragma unroll
        for (int ks = 0; ks < 4; ++ks) {
            unsigned a[2][4];
            ldsm4(a[0][0], a[0][1], a[0][2], a[0][3], aB + ks * 32);
            ldsm4(a[1][0], a[1][1], a[1][2], a[1][3], aB + 16 * 144 + ks * 32);
            unsigned b[8][2];
            #pragma unroll
            for (int nt = 0; nt < 4; ++nt) {
                unsigned r0, r1, r2, r3;
                ldsm4(r0, r1, r2, r3, bB + nt * 16 * 144 + ks * 32);
                b[nt * 2][0] = r0; b[nt * 2][1] = r2;
                b[nt * 2 + 1][0] = r1; b[nt * 2 + 1][1] = r3;
            }
            #pragma unroll
            for (int mt = 0; mt < 2; ++mt)
                #pragma unroll
                for (int nt = 0; nt < 8; ++nt)
                    mma16816(acc[mt][nt], a[mt], b[nt][0], b[nt][1]);
        }
    }

    #pragma unroll
    for (int mt = 0; mt < 2; ++mt) {
        const int r0 = bm + 32 * wr + 16 * mt + (lane >> 2);
        #pragma unroll
        for (int nt = 0; nt < 8; ++nt) {
            const int col = bn + 64 * wc + 8 * nt + (lane & 3) * 2;
            float2 v0 = make_float2(acc[mt][nt][0], acc[mt][nt][1]);
            float2 v1 = make_float2(acc[mt][nt][2], acc[mt][nt][3]);
            *(float2*)&C[(size_t)r0 * N + col]       = v0;
            *(float2*)&C[(size_t)(r0 + 8) * N + col] = v1;
        }
    }
}

// ====================== HMMA flash attention ================================
// No-running-max softmax: RMSNorm bounds |score*scale*log2e| <= 16.34, so
// p = ex2(s) directly (no overflow/underflow); l accumulated per-thread,
// reduced once at the epilogue. No shuffles or o-rescale in the main loop.
__device__ __forceinline__ void load_kv_tile(
    unsigned sbase, int tid,
    const __nv_bfloat16* khp, const __nv_bfloat16* klp,
    const __nv_bfloat16* vthp, const __nv_bfloat16* vtlp, int nBase)
{
    const int r = tid >> 2, c0 = (tid & 3) * 4;
    const char* gk = (const char*)(khp + (size_t)(nBase + r) * 128) + c0 * 16;
    const char* gl = (const char*)(klp + (size_t)(nBase + r) * 128) + c0 * 16;
    const unsigned dk = sbase + r * 272 + c0 * 16;
    #pragma unroll
    for (int i = 0; i < 4; ++i) {
        CP16(dk + i * 16, gk + i * 16);
        CP16(dk + 17408 + i * 16, gl + i * 16);
    }
    const int r2 = tid >> 1, c2 = (tid & 1) * 4;
    const char* gv = (const char*)(vthp + (size_t)r2 * Ssz + nBase) + c2 * 16;
    const char* gw = (const char*)(vtlp + (size_t)r2 * Ssz + nBase) + c2 * 16;
    const unsigned dv = sbase + 34816 + r2 * 144 + c2 * 16;
    #pragma unroll
    for (int i = 0; i < 4; ++i) {
        CP16(dv + i * 16, gv + i * 16);
        CP16(dv + 18432 + i * 16, gw + i * 16);
    }
}

__global__ __launch_bounds__(256, 1) void flash_mma(
    const __nv_bfloat16* __restrict__ qh, const __nv_bfloat16* __restrict__ ql,
    const __nv_bfloat16* __restrict__ kh, const __nv_bfloat16* __restrict__ kl,
    const __nv_bfloat16* __restrict__ vth, const __nv_bfloat16* __restrict__ vtl,
    __nv_bfloat16* __restrict__ outp)     // split [M, KP] hi|lo|hi
{
    extern __shared__ __align__(16) char smem[];
    const unsigned sb = smem_u32(smem);
    const int tid = threadIdx.x, lane = tid & 31, w = tid >> 5;
    const int qi = 15 - blockIdx.x;
    const int h = blockIdx.y, b = blockIdx.z;
    const int kvh = h >> 1;
    const int mBase = qi << 7;
    const int ntiles = 2 * qi + 2;

    const __nv_bfloat16* qhp = qh + (((size_t)b * Hh + h) * Ssz + mBase) * Dh;
    const __nv_bfloat16* qlp = ql + (((size_t)b * Hh + h) * Ssz + mBase) * Dh;
    const __nv_bfloat16* khp = kh + ((size_t)b * KVh + kvh) * Ssz * Dh;
    const __nv_bfloat16* klp = kl + ((size_t)b * KVh + kvh) * Ssz * Dh;
    const __nv_bfloat16* vthp = vth + ((size_t)b * KVh + kvh) * Dh * Ssz;
    const __nv_bfloat16* vtlp = vtl + ((size_t)b * KVh + kvh) * Dh * Ssz;

    // prologue: Q into stage1 region, KV tile0 into stage0
    {
        const int r = tid >> 1, cb = (tid & 1) * 8;
        const unsigned dq = sb + FL_STAGE + r * 272 + cb * 16;
        const char* gq = (const char*)(qhp + (size_t)r * Dh) + cb * 16;
        const char* gl = (const char*)(qlp + (size_t)r * Dh) + cb * 16;
        #pragma unroll
        for (int i = 0; i < 8; ++i) {
            CP16(dq + i * 16, gq + i * 16);
            CP16(dq + 34816 + i * 16, gl + i * 16);
        }
    }
    load_kv_tile(sb, tid, khp, klp, vthp, vtlp, 0);
    CP_COMMIT();
    asm volatile("cp.async.wait_group 0;" ::: "memory");
    __syncthreads();

    unsigned qhf[8][4], qlf[8][4];
    {
        const unsigned qB = sb + FL_STAGE + (16 * w + (lane & 15)) * 272 + (lane >> 4) * 16;
        #pragma unroll
        for (int kt = 0; kt < 8; ++kt) {
            ldsm4(qhf[kt][0], qhf[kt][1], qhf[kt][2], qhf[kt][3], qB + kt * 32);
            ldsm4(qlf[kt][0], qlf[kt][1], qlf[kt][2], qlf[kt][3], qB + 34816 + kt * 32);
        }
    }
    __syncthreads();

    float o_[16][4];
    #pragma unroll
    for (int n = 0; n < 16; ++n)
        #pragma unroll
        for (int e = 0; e < 4; ++e) o_[n][e] = 0.0f;
    float l_lo = 0.0f, l_hi = 0.0f;      // thread-local partial row sums
    const int gm_lo = mBase + 16 * w + (lane >> 2);
    const int gm_hi = gm_lo + 8;

    for (int t = 0; t < ntiles; ++t) {
        if (t + 1 < ntiles) {
            load_kv_tile(sb + ((t + 1) & 1) * FL_STAGE, tid, khp, klp, vthp, vtlp,
                         (t + 1) * 64);
            CP_COMMIT();
            asm volatile("cp.async.wait_group 1;" ::: "memory");
        } else {
            asm volatile("cp.async.wait_group 0;" ::: "memory");
        }
        __syncthreads();
        const unsigned stb = sb + (t & 1) * FL_STAGE;

        // ---- QK^T (3-term split); scores in log2 domain ----
        float s_[8][4];
        #pragma unroll
        for (int j = 0; j < 8; ++j)
            #pragma unroll
            for (int e = 0; e < 4; ++e) s_[j][e] = 0.0f;

        const unsigned kB = stb + (lane & 15) * 272 + (lane >> 4) * 16;
        #pragma unroll
        for (int kt = 0; kt < 8; ++kt) {
            #pragma unroll
            for (int nt = 0; nt < 4; ++nt) {
                unsigned r0, r1, r2, r3;
                ldsm4(r0, r1, r2, r3, kB + nt * 16 * 272 + kt * 32);
                mma16816(s_[nt * 2],     qhf[kt], r0, r2);
                mma16816(s_[nt * 2 + 1], qhf[kt], r1, r3);
                mma16816(s_[nt * 2],     qlf[kt], r0, r2);
                mma16816(s_[nt * 2 + 1], qlf[kt], r1, r3);
            }
            #pragma unroll
            for (int nt = 0; nt < 4; ++nt) {
                unsigned r0, r1, r2, r3;
                ldsm4(r0, r1, r2, r3, kB + 17408 + nt * 16 * 272 + kt * 32);
                mma16816(s_[nt * 2],     qhf[kt], r0, r2);
                mma16816(s_[nt * 2 + 1], qhf[kt], r1, r3);
            }
        }

        // ---- mask (last two tiles only) + fixed-shift softmax ----
        const int nBase = t * 64;
        if (t >= 2 * qi) {
            #pragma unroll
            for (int j = 0; j < 8; ++j) {
                const int gn0 = nBase + 8 * j + (lane & 3) * 2;
                if (gn0 > gm_lo)     s_[j][0] = -1e30f;
                if (gn0 + 1 > gm_lo) s_[j][1] = -1e30f;
                if (gn0 > gm_hi)     s_[j][2] = -1e30f;
                if (gn0 + 1 > gm_hi) s_[j][3] = -1e30f;
            }
        }
        #pragma unroll
        for (int j = 0; j < 8; ++j) {
            float p0 = ex2(s_[j][0]);
            float p1 = ex2(s_[j][1]);
            float p2 = ex2(s_[j][2]);
            float p3 = ex2(s_[j][3]);
            s_[j][0] = p0; s_[j][1] = p1; s_[j][2] = p2; s_[j][3] = p3;
            l_lo += p0 + p1; l_hi += p2 + p3;
        }

        // ---- PV (3-term split, P from registers) ----
        const unsigned vB = stb + 34816 + (lane & 15) * 144 + (lane >> 4) * 16;
        #pragma unroll
        for (int kt2 = 0; kt2 < 4; ++kt2) {
            const float* pa = s_[2 * kt2];
            const float* pb = s_[2 * kt2 + 1];
            unsigned ahf[4], alf[4];
            ahf[0] = pack2(pa[0], pa[1]); ahf[1] = pack2(pa[2], pa[3]);
            ahf[2] = pack2(pb[0], pb[1]); ahf[3] = pack2(pb[2], pb[3]);
            alf[0] = pack2(bfres(pa[0]), bfres(pa[1]));
            alf[1] = pack2(bfres(pa[2]), bfres(pa[3]));
            alf[2] = pack2(bfres(pb[0]), bfres(pb[1]));
            alf[3] = pack2(bfres(pb[2]), bfres(pb[3]));
            #pragma unroll
            for (int vt = 0; vt < 8; ++vt) {
                unsigned r0, r1, r2, r3;
                ldsm4(r0, r1, r2, r3, vB + vt * 16 * 144 + kt2 * 32);
                mma16816(o_[2 * vt],     ahf, r0, r2);
                mma16816(o_[2 * vt + 1], ahf, r1, r3);
                mma16816(o_[2 * vt],     alf, r0, r2);
                mma16816(o_[2 * vt + 1], alf, r1, r3);
            }
            #pragma unroll
            for (int vt = 0; vt < 8; ++vt) {
                unsigned r0, r1, r2, r3;
                ldsm4(r0, r1, r2, r3, vB + 18432 + vt * 16 * 144 + kt2 * 32);
                mma16816(o_[2 * vt],     ahf, r0, r2);
                mma16816(o_[2 * vt + 1], ahf, r1, r3);
            }
        }
        __syncthreads();
    }

    // ---- epilogue: reduce l across the 4-lane quad, normalize, split-write --
    l_lo += __shfl_xor_sync(0xffffffffu, l_lo, 1);
    l_lo += __shfl_xor_sync(0xffffffffu, l_lo, 2);
    l_hi += __shfl_xor_sync(0xffffffffu, l_hi, 1);
    l_hi += __shfl_xor_sync(0xffffffffu, l_hi, 2);
    const float il = 1.0f / l_lo, ih = 1.0f / l_hi;
    __nv_bfloat16* arl = outp + (size_t)(b * Ssz + gm_lo) * KP + h * Dh;
    __nv_bfloat16* arh = outp + (size_t)(b * Ssz + gm_hi) * KP + h * Dh;
    #pragma unroll
    for (int n = 0; n < 16; ++n) {
        const int col = 8 * n + (lane & 3) * 2;
        float a0 = o_[n][0] * il, a1 = o_[n][1] * il;
        float b0 = o_[n][2] * ih, b1 = o_[n][3] * ih;
        __nv_bfloat16 ah0 = __float2bfloat16(a0), ah1 = __float2bfloat16(a1);
        __nv_bfloat16 bh0 = __float2bfloat16(b0), bh1 = __float2bfloat16(b1);
        __nv_bfloat162 aH = __nv_bfloat162(ah0, ah1);
        __nv_bfloat162 bH = __nv_bfloat162(bh0, bh1);
        __nv_bfloat162 aL = __nv_bfloat162(
            __float2bfloat16(a0 - __bfloat162float(ah0)),
            __float2bfloat16(a1 - __bfloat162float(ah1)));
        __nv_bfloat162 bL = __nv_bfloat162(
            __float2bfloat16(b0 - __bfloat162float(bh0)),
            __float2bfloat16(b1 - __bfloat162float(bh1)));
        *(__nv_bfloat162*)(arl + col)        = aH;
        *(__nv_bfloat162*)(arl + 2048 + col) = aL;
        *(__nv_bfloat162*)(arl + 4096 + col) = aH;
        *(__nv_bfloat162*)(arh + col)        = bH;
        *(__nv_bfloat162*)(arh + 2048 + col) = bL;
        *(__nv_bfloat162*)(arh + 4096 + col) = bH;
    }
}

// ---------------- host launch -------------------------------------------------
extern "C" void kernel_launch(void* const* d_in, const int* in_sizes, int n_in,
                              void* d_out, int out_size)
{
    const float* x   = (const float*)d_in[0];
    const float* Wq  = (const float*)d_in[1];
    const float* Wk  = (const float*)d_in[2];
    const float* Wv  = (const float*)d_in[3];
    const float* Wo  = (const float*)d_in[4];
    const float* qnw = (const float*)d_in[5];
    const float* knw = (const float*)d_in[6];
    const float* cs  = (const float*)d_in[7];
    const float* sn  = (const float*)d_in[8];

    float *qkv;
    __nv_bfloat16 *xp, *ap, *wqkvt, *wot;
    __nv_bfloat16 *qhh, *qll, *khh, *kll, *vth, *vtl;
    cudaGetSymbolAddress((void**)&qkv, g_qkv);
    cudaGetSymbolAddress((void**)&xp, g_xp);
    cudaGetSymbolAddress((void**)&ap, g_ap);
    cudaGetSymbolAddress((void**)&wqkvt, g_wqkvt);
    cudaGetSymbolAddress((void**)&wot, g_wot);
    cudaGetSymbolAddress((void**)&qhh, g_qh);
    cudaGetSymbolAddress((void**)&qll, g_ql);
    cudaGetSymbolAddress((void**)&khh, g_kh);
    cudaGetSymbolAddress((void**)&kll, g_kl);
    cudaGetSymbolAddress((void**)&vth, g_vth);
    cudaGetSymbolAddress((void**)&vtl, g_vtl);

    cudaFuncSetAttribute(gemm_mma, cudaFuncAttributeMaxDynamicSharedMemorySize, GEMM_SMEM);
    cudaFuncSetAttribute(flash_mma, cudaFuncAttributeMaxDynamicSharedMemorySize, FL_SMEM);

    // split/convert inputs + weights (QKV weights concatenated along N)
    conv_a<<<8192, 256>>>(x, xp);
    conv_w<<<dim3(64, 64), 256>>>(Wq, wqkvt, 2048);
    conv_w<<<dim3(32, 64), 256>>>(Wk, wqkvt + (size_t)2048 * KP, 1024);
    conv_w<<<dim3(32, 64), 256>>>(Wv, wqkvt + (size_t)3072 * KP, 1024);
    conv_w<<<dim3(64, 64), 256>>>(Wo, wot, 2048);

    // fused QKV projection (bf16x3 HMMA): C = [Q | K | V], [4096, 4096]
    gemm_mma<<<dim3(32, 32), 256, GEMM_SMEM>>>(xp, wqkvt, qkv, 4096);

    // fused RMSNorm + RoPE + split (Q pre-scaled by SCALE*log2e for exp2 softmax)
    const float qscale = (float)(0.08838834764831845 * 1.4426950408889634);
    norm_rope_split<<<8192, 256>>>(qkv, 0, Hh, qnw, cs, sn, qhh, qll, qscale);
    norm_rope_split<<<4096, 256>>>(qkv, 2048, KVh, knw, cs, sn, khh, kll, 1.0f);
    conv_vt<<<dim3(64, 4, 16), 256>>>(qkv + 3072, vth, vtl);

    // flash attention (HMMA, no-running-max exp2 softmax)
    flash_mma<<<dim3(16, Hh, Bsz), 256, FL_SMEM>>>(qhh, qll, khh, kll, vth, vtl, ap);

    // output projection
    gemm_mma<<<dim3(16, 32), 256, GEMM_SMEM>>>(ap, wot, (float*)d_out, 2048);
}

// round 11
// speedup vs baseline: 1.4531x; 1.2871x over previous
#include <cuda_runtime.h>
#include <cuda_bf16.h>
#include <cuda_fp16.h>
#include <math.h>

#define Bsz 2
#define Ssz 2048
#define HIDs 2048
#define Hh 16
#define KVh 8
#define Dh 128
#define KP 4096              // K' = 2*2048 for f16 2-term split
#define NT 64                // KP / 64 k-chunks
#define STG_A (128 * 72 * 2)            // 18432 B per A tile (stride 144B)
#define STG_BYTES (2 * STG_A)           // 36864
#define GEMM_SMEM (3 * STG_BYTES)       // 3-stage = 110592

// flash smem (R5 layout): per stage Kh[64][136],Kl[64][136],Vth[128][72],Vtl[128][72]
#define FL_STAGE 71680
#define FL_SMEM (2 * FL_STAGE)          // 143360

// ---------------- scratch (static device arrays: no allocs allowed) ----------
__device__ float g_qkv[(size_t)4096 * 4096];          // fused QKV output [M, 4096]

__device__ __align__(16) __half g_xp[(size_t)4096 * KP];
__device__ __align__(16) __half g_ap[(size_t)4096 * KP];   // att split (flash writes)
__device__ __align__(16) __half g_wqkvt[(size_t)4096 * KP];
__device__ __align__(16) __half g_wot[(size_t)2048 * KP];

// head-major bf16 splits for flash (unchanged)
__device__ __align__(16) __nv_bfloat16 g_qh[(size_t)Bsz * Hh * Ssz * Dh];
__device__ __align__(16) __nv_bfloat16 g_ql[(size_t)Bsz * Hh * Ssz * Dh];
__device__ __align__(16) __nv_bfloat16 g_kh[(size_t)Bsz * KVh * Ssz * Dh];
__device__ __align__(16) __nv_bfloat16 g_kl[(size_t)Bsz * KVh * Ssz * Dh];
__device__ __align__(16) __nv_bfloat16 g_vth[(size_t)Bsz * KVh * Dh * Ssz];
__device__ __align__(16) __nv_bfloat16 g_vtl[(size_t)Bsz * KVh * Dh * Ssz];

// ====================== PTX helpers =========================================
__device__ __forceinline__ unsigned smem_u32(const void* p) {
    unsigned a;
    asm("{ .reg .u64 t; cvta.to.shared.u64 t, %1; cvt.u32.u64 %0, t; }"
        : "=r"(a) : "l"(p));
    return a;
}
#define CP16(dst, src) \
    asm volatile("cp.async.cg.shared.global [%0], [%1], 16;" :: "r"(dst), "l"(src))
#define CP_COMMIT() asm volatile("cp.async.commit_group;")

__device__ __forceinline__ void ldsm4(unsigned& r0, unsigned& r1,
                                      unsigned& r2, unsigned& r3, unsigned a) {
    asm volatile("ldmatrix.sync.aligned.m8n8.x4.shared.b16 {%0,%1,%2,%3}, [%4];"
                 : "=r"(r0), "=r"(r1), "=r"(r2), "=r"(r3) : "r"(a));
}
// bf16 mma (flash)
__device__ __forceinline__ void mma16816(float* d, const unsigned* a,
                                         unsigned b0, unsigned b1) {
    asm volatile(
        "mma.sync.aligned.m16n8k16.row.col.f32.bf16.bf16.f32 "
        "{%0,%1,%2,%3}, {%4,%5,%6,%7}, {%8,%9}, {%0,%1,%2,%3};"
        : "+f"(d[0]), "+f"(d[1]), "+f"(d[2]), "+f"(d[3])
        : "r"(a[0]), "r"(a[1]), "r"(a[2]), "r"(a[3]), "r"(b0), "r"(b1));
}
// f16 mma (GEMMs)
__device__ __forceinline__ void mma16816h(float* d, const unsigned* a,
                                          unsigned b0, unsigned b1) {
    asm volatile(
        "mma.sync.aligned.m16n8k16.row.col.f32.f16.f16.f32 "
        "{%0,%1,%2,%3}, {%4,%5,%6,%7}, {%8,%9}, {%0,%1,%2,%3};"
        : "+f"(d[0]), "+f"(d[1]), "+f"(d[2]), "+f"(d[3])
        : "r"(a[0]), "r"(a[1]), "r"(a[2]), "r"(a[3]), "r"(b0), "r"(b1));
}
__device__ __forceinline__ unsigned pack2(float lo, float hi) {
    unsigned d;
    asm("cvt.rn.bf16x2.f32 %0, %1, %2;" : "=r"(d) : "f"(hi), "f"(lo));
    return d;
}
__device__ __forceinline__ float bfres(float x) {
    return x - __bfloat162float(__float2bfloat16(x));
}
__device__ __forceinline__ float ex2(float x) {
    float r;
    asm("ex2.approx.f32 %0, %1;" : "=f"(r) : "f"(x));
    return r;
}

// ====================== conversion kernels ==================================
// A' = [hi | lo] f16 along K'   (src [M, 2048] fp32 row-major)
__global__ __launch_bounds__(256) void conv_a(
    const float* __restrict__ src, __half* __restrict__ dst)
{
    size_t i = (size_t)blockIdx.x * 256 + threadIdx.x;
    int m = (int)(i >> 9);
    int k4 = (int)(i & 511);
    float4 v = ((const float4*)(src + (size_t)m * 2048))[k4];
    __half h0 = __float2half(v.x), h1 = __float2half(v.y);
    __half h2 = __float2half(v.z), h3 = __float2half(v.w);
    __half l0 = __float2half(v.x - __half2float(h0));
    __half l1 = __float2half(v.y - __half2float(h1));
    __half l2 = __float2half(v.z - __half2float(h2));
    __half l3 = __float2half(v.w - __half2float(h3));
    __half2* row = (__half2*)(dst + (size_t)m * KP) + k4 * 2;
    row[0] = __halves2half2(h0, h1);
    row[1] = __halves2half2(h2, h3);
    row[1024] = __halves2half2(l0, l1);
    row[1025] = __halves2half2(l2, l3);
}

// B' = W^T f16: [n,k]=hi, [n,2048+k]=hi (duplicated).  W is [2048, N] fp32.
__global__ __launch_bounds__(256) void conv_w(
    const float* __restrict__ W, __half* __restrict__ Bt, int N)
{
    __shared__ float ts[32][33];
    int n0 = blockIdx.x * 32, k0 = blockIdx.y * 32;
    int tx = threadIdx.x & 31, ty = threadIdx.x >> 5;
    #pragma unroll
    for (int r = 0; r < 4; ++r)
        ts[ty + r * 8][tx] = W[(size_t)(k0 + ty + r * 8) * N + n0 + tx];
    __syncthreads();
    #pragma unroll
    for (int r = 0; r < 4; ++r) {
        int n = n0 + ty + r * 8, k = k0 + tx;
        __half hi = __float2half(ts[tx][ty + r * 8]);
        __half* row = Bt + (size_t)n * KP;
        row[k] = hi; row[2048 + k] = hi;
    }
}

// fused RMSNorm + RoPE + bf16 hi/lo split + head-major write (flash inputs).
__global__ __launch_bounds__(256) void norm_rope_split(
    const float* __restrict__ qkv, int baseCol, int nh,
    const float* __restrict__ w,
    const float* __restrict__ cs, const float* __restrict__ sn,
    __nv_bfloat16* __restrict__ dh, __nv_bfloat16* __restrict__ dl,
    float scale)
{
    const int warp = blockIdx.x * 8 + (threadIdx.x >> 5);
    const int lane = threadIdx.x & 31;
    const int tok = warp / nh;          // b*S + s
    const int head = warp % nh;
    const int s = tok % Ssz;
    const int b = tok / Ssz;

    const float* row = qkv + (size_t)tok * 4096 + baseCol + head * Dh;
    float v0 = row[lane];
    float v1 = row[lane + 32];
    float v2 = row[lane + 64];
    float v3 = row[lane + 96];

    float ss = v0 * v0 + v1 * v1 + v2 * v2 + v3 * v3;
    #pragma unroll
    for (int o = 16; o; o >>= 1) ss += __shfl_xor_sync(0xffffffffu, ss, o);
    float r = rsqrtf(ss * (1.0f / 128.0f) + 1e-6f);

    v0 = v0 * r * w[lane];
    v1 = v1 * r * w[lane + 32];
    v2 = v2 * r * w[lane + 64];
    v3 = v3 * r * w[lane + 96];

    const float* cr = cs + (size_t)s * Dh;
    const float* sr = sn + (size_t)s * Dh;
    float o0 = (v0 * cr[lane]      - v2 * sr[lane])      * scale;
    float o1 = (v1 * cr[lane + 32] - v3 * sr[lane + 32]) * scale;
    float o2 = (v2 * cr[lane + 64] + v0 * sr[lane + 64]) * scale;
    float o3 = (v3 * cr[lane + 96] + v1 * sr[lane + 96]) * scale;

    __nv_bfloat16 h0 = __float2bfloat16(o0), h1 = __float2bfloat16(o1);
    __nv_bfloat16 h2 = __float2bfloat16(o2), h3 = __float2bfloat16(o3);
    __nv_bfloat16 e0 = __float2bfloat16(o0 - __bfloat162float(h0));
    __nv_bfloat16 e1 = __float2bfloat16(o1 - __bfloat162float(h1));
    __nv_bfloat16 e2 = __float2bfloat16(o2 - __bfloat162float(h2));
    __nv_bfloat16 e3 = __float2bfloat16(o3 - __bfloat162float(h3));

    size_t o = (((size_t)b * nh + head) * Ssz + s) * 128;
    dh[o + lane]      = h0; dh[o + lane + 32] = h1;
    dh[o + lane + 64] = h2; dh[o + lane + 96] = h3;
    dl[o + lane]      = e0; dl[o + lane + 32] = e1;
    dl[o + lane + 64] = e2; dl[o + lane + 96] = e3;
}

// V from fused buffer (base already offset to V cols) -> Vt hi/lo [B*KV,128,S]
__global__ __launch_bounds__(256) void conv_vt(
    const float* __restrict__ v, __nv_bfloat16* __restrict__ th,
    __nv_bfloat16* __restrict__ tl)
{
    __shared__ float ts[32][33];
    int s0 = blockIdx.x * 32, d0 = blockIdx.y * 32;
    int bk = blockIdx.z;
    int b = bk >> 3, kv = bk & 7;
    int tx = threadIdx.x & 31, ty = threadIdx.x >> 5;
    #pragma unroll
    for (int r = 0; r < 4; ++r)
        ts[ty + r * 8][tx] =
            v[(size_t)(b * Ssz + s0 + ty + r * 8) * 4096 + kv * 128 + d0 + tx];
    __syncthreads();
    #pragma unroll
    for (int r = 0; r < 4; ++r) {
        float x = ts[tx][ty + r * 8];
        __nv_bfloat16 hi = __float2bfloat16(x);
        __nv_bfloat16 lo = __float2bfloat16(x - __bfloat162float(hi));
        size_t o = ((size_t)bk * 128 + d0 + ty + r * 8) * Ssz + s0 + tx;
        th[o] = hi; tl[o] = lo;
    }
}

// ====================== f16 GEMM (3-stage, 1 barrier/chunk) =================
// C[M,N] fp32 = A'[M,K'] f16 x B'[N,K'] f16, both K-major, K'=4096.
__global__ __launch_bounds__(256, 2) void gemm_mma(
    const __half* __restrict__ A, const __half* __restrict__ Bm,
    float* __restrict__ C, int N)
{
    extern __shared__ __align__(16) char smem[];
    const unsigned sb = smem_u32(smem);
    const int tid = threadIdx.x;
    const int lane = tid & 31;
    const int wid = tid >> 5;
    const int wr = wid >> 1;
    const int wc = wid & 1;
    const int bm = blockIdx.y << 7, bn = blockIdx.x << 7;

    const int lrow = tid >> 3, lcol = tid & 7;
    const __half* Ag = A + (size_t)(bm + lrow) * KP + lcol * 8;
    const __half* Bg = Bm + (size_t)(bn + lrow) * KP + lcol * 8;
    const unsigned sOff = lrow * 144 + lcol * 16;

    float acc[2][8][4];
    #pragma unroll
    for (int i = 0; i < 2; ++i)
        #pragma unroll
        for (int j = 0; j < 8; ++j)
            #pragma unroll
            for (int e = 0; e < 4; ++e) acc[i][j][e] = 0.0f;

    const unsigned aBase0 = sb + (32 * wr + (lane & 15)) * 144 + (lane >> 4) * 16;
    const unsigned bBase0 = sb + STG_A + (64 * wc + (lane & 15)) * 144 + (lane >> 4) * 16;

    #pragma unroll
    for (int c = 0; c < 2; ++c) {
        const unsigned st = c * STG_BYTES;
        const unsigned as = sb + st + sOff, bs = sb + st + STG_A + sOff;
        const __half* ag = Ag + (size_t)c * 64;
        const __half* bg = Bg + (size_t)c * 64;
        #pragma unroll
        for (int i = 0; i < 4; ++i) {
            CP16(as + i * 32 * 144, ag + (size_t)(32 * i) * KP);
            CP16(bs + i * 32 * 144, bg + (size_t)(32 * i) * KP);
        }
        CP_COMMIT();
    }

    int stage = 0, nstage = 2;
    for (int c = 0; c < NT; ++c) {
        if (c + 1 < NT) asm volatile("cp.async.wait_group 1;" ::: "memory");
        else            asm volatile("cp.async.wait_group 0;" ::: "memory");
        __syncthreads();

        if (c + 2 < NT) {
            const unsigned st = nstage * STG_BYTES;
            const unsigned as = sb + st + sOff, bs = sb + st + STG_A + sOff;
            const __half* ag = Ag + (size_t)(c + 2) * 64;
            const __half* bg = Bg + (size_t)(c + 2) * 64;
            #pragma unroll
            for (int i = 0; i < 4; ++i) {
                CP16(as + i * 32 * 144, ag + (size_t)(32 * i) * KP);
                CP16(bs + i * 32 * 144, bg + (size_t)(32 * i) * KP);
            }
            CP_COMMIT();
            nstage = (nstage == 2) ? 0 : nstage + 1;
        }

        const unsigned st = stage * STG_BYTES;
        stage = (stage == 2) ? 0 : stage + 1;
        const unsigned aB = aBase0 + st, bB = bBase0 + st;
        #pragma unroll
        for (int ks = 0; ks < 4; ++ks) {
            unsigned a[2][4];
            ldsm4(a[0][0], a[0][1], a[0][2], a[0][3], aB + ks * 32);
            ldsm4(a[1][0], a[1][1], a[1][2], a[1][3], aB + 16 * 144 + ks * 32);
            unsigned b[8][2];
            #pragma unroll
            for (int nt = 0; nt < 4; ++nt) {
                unsigned r0, r1, r2, r3;
                ldsm4(r0, r1, r2, r3, bB + nt * 16 * 144 + ks * 32);
                b[nt * 2][0] = r0; b[nt * 2][1] = r2;
                b[nt * 2 + 1][0] = r1; b[nt * 2 + 1][1] = r3;
            }
            #pragma unroll
            for (int mt = 0; mt < 2; ++mt)
                #pragma unroll
                for (int nt = 0; nt < 8; ++nt)
                    mma16816h(acc[mt][nt], a[mt], b[nt][0], b[nt][1]);
        }
    }

    #pragma unroll
    for (int mt = 0; mt < 2; ++mt) {
        const int r0 = bm + 32 * wr + 16 * mt + (lane >> 2);
        #pragma unroll
        for (int nt = 0; nt < 8; ++nt) {
            const int col = bn + 64 * wc + 8 * nt + (lane & 3) * 2;
            float2 v0 = make_float2(acc[mt][nt][0], acc[mt][nt][1]);
            float2 v1 = make_float2(acc[mt][nt][2], acc[mt][nt][3]);
            *(float2*)&C[(size_t)r0 * N + col]       = v0;
            *(float2*)&C[(size_t)(r0 + 8) * N + col] = v1;
        }
    }
}

// ====================== HMMA flash attention (bf16, unchanged core) =========
__device__ __forceinline__ void load_kv_tile(
    unsigned sbase, int tid,
    const __nv_bfloat16* khp, const __nv_bfloat16* klp,
    const __nv_bfloat16* vthp, const __nv_bfloat16* vtlp, int nBase)
{
    const int r = tid >> 2, c0 = (tid & 3) * 4;
    const char* gk = (const char*)(khp + (size_t)(nBase + r) * 128) + c0 * 16;
    const char* gl = (const char*)(klp + (size_t)(nBase + r) * 128) + c0 * 16;
    const unsigned dk = sbase + r * 272 + c0 * 16;
    #pragma unroll
    for (int i = 0; i < 4; ++i) {
        CP16(dk + i * 16, gk + i * 16);
        CP16(dk + 17408 + i * 16, gl + i * 16);
    }
    const int r2 = tid >> 1, c2 = (tid & 1) * 4;
    const char* gv = (const char*)(vthp + (size_t)r2 * Ssz + nBase) + c2 * 16;
    const char* gw = (const char*)(vtlp + (size_t)r2 * Ssz + nBase) + c2 * 16;
    const unsigned dv = sbase + 34816 + r2 * 144 + c2 * 16;
    #pragma unroll
    for (int i = 0; i < 4; ++i) {
        CP16(dv + i * 16, gv + i * 16);
        CP16(dv + 18432 + i * 16, gw + i * 16);
    }
}

__global__ __launch_bounds__(256, 1) void flash_mma(
    const __nv_bfloat16* __restrict__ qh, const __nv_bfloat16* __restrict__ ql,
    const __nv_bfloat16* __restrict__ kh, const __nv_bfloat16* __restrict__ kl,
    const __nv_bfloat16* __restrict__ vth, const __nv_bfloat16* __restrict__ vtl,
    __half* __restrict__ outp)           // split f16 [M, KP] hi|lo
{
    extern __shared__ __align__(16) char smem[];
    const unsigned sb = smem_u32(smem);
    const int tid = threadIdx.x, lane = tid & 31, w = tid >> 5;
    const int qi = 15 - blockIdx.x;
    const int h = blockIdx.y, b = blockIdx.z;
    const int kvh = h >> 1;
    const int mBase = qi << 7;
    const int ntiles = 2 * qi + 2;

    const __nv_bfloat16* qhp = qh + (((size_t)b * Hh + h) * Ssz + mBase) * Dh;
    const __nv_bfloat16* qlp = ql + (((size_t)b * Hh + h) * Ssz + mBase) * Dh;
    const __nv_bfloat16* khp = kh + ((size_t)b * KVh + kvh) * Ssz * Dh;
    const __nv_bfloat16* klp = kl + ((size_t)b * KVh + kvh) * Ssz * Dh;
    const __nv_bfloat16* vthp = vth + ((size_t)b * KVh + kvh) * Dh * Ssz;
    const __nv_bfloat16* vtlp = vtl + ((size_t)b * KVh + kvh) * Dh * Ssz;

    // prologue: Q into stage1 region, KV tile0 into stage0
    {
        const int r = tid >> 1, cb = (tid & 1) * 8;
        const unsigned dq = sb + FL_STAGE + r * 272 + cb * 16;
        const char* gq = (const char*)(qhp + (size_t)r * Dh) + cb * 16;
        const char* gl = (const char*)(qlp + (size_t)r * Dh) + cb * 16;
        #pragma unroll
        for (int i = 0; i < 8; ++i) {
            CP16(dq + i * 16, gq + i * 16);
            CP16(dq + 34816 + i * 16, gl + i * 16);
        }
    }
    load_kv_tile(sb, tid, khp, klp, vthp, vtlp, 0);
    CP_COMMIT();
    asm volatile("cp.async.wait_group 0;" ::: "memory");
    __syncthreads();

    unsigned qhf[8][4], qlf[8][4];
    {
        const unsigned qB = sb + FL_STAGE + (16 * w + (lane & 15)) * 272 + (lane >> 4) * 16;
        #pragma unroll
        for (int kt = 0; kt < 8; ++kt) {
            ldsm4(qhf[kt][0], qhf[kt][1], qhf[kt][2], qhf[kt][3], qB + kt * 32);
            ldsm4(qlf[kt][0], qlf[kt][1], qlf[kt][2], qlf[kt][3], qB + 34816 + kt * 32);
        }
    }
    __syncthreads();

    float o_[16][4];
    #pragma unroll
    for (int n = 0; n < 16; ++n)
        #pragma unroll
        for (int e = 0; e < 4; ++e) o_[n][e] = 0.0f;
    float l_lo = 0.0f, l_hi = 0.0f;
    const int gm_lo = mBase + 16 * w + (lane >> 2);
    const int gm_hi = gm_lo + 8;

    for (int t = 0; t < ntiles; ++t) {
        if (t + 1 < ntiles) {
            load_kv_tile(sb + ((t + 1) & 1) * FL_STAGE, tid, khp, klp, vthp, vtlp,
                         (t + 1) * 64);
            CP_COMMIT();
            asm volatile("cp.async.wait_group 1;" ::: "memory");
        } else {
            asm volatile("cp.async.wait_group 0;" ::: "memory");
        }
        __syncthreads();
        const unsigned stb = sb + (t & 1) * FL_STAGE;

        // ---- QK^T (3-term split); scores in log2 domain ----
        float s_[8][4];
        #pragma unroll
        for (int j = 0; j < 8; ++j)
            #pragma unroll
            for (int e = 0; e < 4; ++e) s_[j][e] = 0.0f;

        const unsigned kB = stb + (lane & 15) * 272 + (lane >> 4) * 16;
        #pragma unroll
        for (int kt = 0; kt < 8; ++kt) {
            #pragma unroll
            for (int nt = 0; nt < 4; ++nt) {
                unsigned r0, r1, r2, r3;
                ldsm4(r0, r1, r2, r3, kB + nt * 16 * 272 + kt * 32);
                mma16816(s_[nt * 2],     qhf[kt], r0, r2);
                mma16816(s_[nt * 2 + 1], qhf[kt], r1, r3);
                mma16816(s_[nt * 2],     qlf[kt], r0, r2);
                mma16816(s_[nt * 2 + 1], qlf[kt], r1, r3);
            }
            #pragma unroll
            for (int nt = 0; nt < 4; ++nt) {
                unsigned r0, r1, r2, r3;
                ldsm4(r0, r1, r2, r3, kB + 17408 + nt * 16 * 272 + kt * 32);
                mma16816(s_[nt * 2],     qhf[kt], r0, r2);
                mma16816(s_[nt * 2 + 1], qhf[kt], r1, r3);
            }
        }

        // ---- mask (last two tiles only) + fixed-shift softmax ----
        const int nBase = t * 64;
        if (t >= 2 * qi) {
            #pragma unroll
            for (int j = 0; j < 8; ++j) {
                const int gn0 = nBase + 8 * j + (lane & 3) * 2;
                if (gn0 > gm_lo)     s_[j][0] = -1e30f;
                if (gn0 + 1 > gm_lo) s_[j][1] = -1e30f;
                if (gn0 > gm_hi)     s_[j][2] = -1e30f;
                if (gn0 + 1 > gm_hi) s_[j][3] = -1e30f;
            }
        }
        #pragma unroll
        for (int j = 0; j < 8; ++j) {
            float p0 = ex2(s_[j][0]);
            float p1 = ex2(s_[j][1]);
            float p2 = ex2(s_[j][2]);
            float p3 = ex2(s_[j][3]);
            s_[j][0] = p0; s_[j][1] = p1; s_[j][2] = p2; s_[j][3] = p3;
            l_lo += p0 + p1; l_hi += p2 + p3;
        }

        // ---- PV (3-term split, P from registers) ----
        const unsigned vB = stb + 34816 + (lane & 15) * 144 + (lane >> 4) * 16;
        #pragma unroll
        for (int kt2 = 0; kt2 < 4; ++kt2) {
            const float* pa = s_[2 * kt2];
            const float* pb = s_[2 * kt2 + 1];
            unsigned ahf[4], alf[4];
            ahf[0] = pack2(pa[0], pa[1]); ahf[1] = pack2(pa[2], pa[3]);
            ahf[2] = pack2(pb[0], pb[1]); ahf[3] = pack2(pb[2], pb[3]);
            alf[0] = pack2(bfres(pa[0]), bfres(pa[1]));
            alf[1] = pack2(bfres(pa[2]), bfres(pa[3]));
            alf[2] = pack2(bfres(pb[0]), bfres(pb[1]));
            alf[3] = pack2(bfres(pb[2]), bfres(pb[3]));
            #pragma unroll
            for (int vt = 0; vt < 8; ++vt) {
                unsigned r0, r1, r2, r3;
                ldsm4(r0, r1, r2, r3, vB + vt * 16 * 144 + kt2 * 32);
                mma16816(o_[2 * vt],     ahf, r0, r2);
                mma16816(o_[2 * vt + 1], ahf, r1, r3);
                mma16816(o_[2 * vt],     alf, r0, r2);
                mma16816(o_[2 * vt + 1], alf, r1, r3);
            }
            #pragma unroll
            for (int vt = 0; vt < 8; ++vt) {
                unsigned r0, r1, r2, r3;
                ldsm4(r0, r1, r2, r3, vB + 18432 + vt * 16 * 144 + kt2 * 32);
                mma16816(o_[2 * vt],     ahf, r0, r2);
                mma16816(o_[2 * vt + 1], ahf, r1, r3);
            }
        }
        __syncthreads();
    }

    // ---- epilogue: reduce l across quad, normalize, write f16 [hi|lo] ----
    l_lo += __shfl_xor_sync(0xffffffffu, l_lo, 1);
    l_lo += __shfl_xor_sync(0xffffffffu, l_lo, 2);
    l_hi += __shfl_xor_sync(0xffffffffu, l_hi, 1);
    l_hi += __shfl_xor_sync(0xffffffffu, l_hi, 2);
    const float il = 1.0f / l_lo, ih = 1.0f / l_hi;
    __half* arl = outp + (size_t)(b * Ssz + gm_lo) * KP + h * Dh;
    __half* arh = outp + (size_t)(b * Ssz + gm_hi) * KP + h * Dh;
    #pragma unroll
    for (int n = 0; n < 16; ++n) {
        const int col = 8 * n + (lane & 3) * 2;
        float a0 = o_[n][0] * il, a1 = o_[n][1] * il;
        float b0 = o_[n][2] * ih, b1 = o_[n][3] * ih;
        __half ah0 = __float2half(a0), ah1 = __float2half(a1);
        __half bh0 = __float2half(b0), bh1 = __float2half(b1);
        __half2 aH = __halves2half2(ah0, ah1);
        __half2 bH = __halves2half2(bh0, bh1);
        __half2 aL = __halves2half2(
            __float2half(a0 - __half2float(ah0)),
            __float2half(a1 - __half2float(ah1)));
        __half2 bL = __halves2half2(
            __float2half(b0 - __half2float(bh0)),
            __float2half(b1 - __half2float(bh1)));
        *(__half2*)(arl + col)        = aH;
        *(__half2*)(arl + 2048 + col) = aL;
        *(__half2*)(arh + col)        = bH;
        *(__half2*)(arh + 2048 + col) = bL;
    }
}

// ---------------- host launch -------------------------------------------------
extern "C" void kernel_launch(void* const* d_in, const int* in_sizes, int n_in,
                              void* d_out, int out_size)
{
    const float* x   = (const float*)d_in[0];
    const float* Wq  = (const float*)d_in[1];
    const float* Wk  = (const float*)d_in[2];
    const float* Wv  = (const float*)d_in[3];
    const float* Wo  = (const float*)d_in[4];
    const float* qnw = (const float*)d_in[5];
    const float* knw = (const float*)d_in[6];
    const float* cs  = (const float*)d_in[7];
    const float* sn  = (const float*)d_in[8];

    float *qkv;
    __half *xp, *ap, *wqkvt, *wot;
    __nv_bfloat16 *qhh, *qll, *khh, *kll, *vth, *vtl;
    cudaGetSymbolAddress((void**)&qkv, g_qkv);
    cudaGetSymbolAddress((void**)&xp, g_xp);
    cudaGetSymbolAddress((void**)&ap, g_ap);
    cudaGetSymbolAddress((void**)&wqkvt, g_wqkvt);
    cudaGetSymbolAddress((void**)&wot, g_wot);
    cudaGetSymbolAddress((void**)&qhh, g_qh);
    cudaGetSymbolAddress((void**)&qll, g_ql);
    cudaGetSymbolAddress((void**)&khh, g_kh);
    cudaGetSymbolAddress((void**)&kll, g_kl);
    cudaGetSymbolAddress((void**)&vth, g_vth);
    cudaGetSymbolAddress((void**)&vtl, g_vtl);

    cudaFuncSetAttribute(gemm_mma, cudaFuncAttributeMaxDynamicSharedMemorySize, GEMM_SMEM);
    cudaFuncSetAttribute(flash_mma, cudaFuncAttributeMaxDynamicSharedMemorySize, FL_SMEM);

    // split/convert inputs + weights (QKV weights concatenated along N)
    conv_a<<<8192, 256>>>(x, xp);
    conv_w<<<dim3(64, 64), 256>>>(Wq, wqkvt, 2048);
    conv_w<<<dim3(32, 64), 256>>>(Wk, wqkvt + (size_t)2048 * KP, 1024);
    conv_w<<<dim3(32, 64), 256>>>(Wv, wqkvt + (size_t)3072 * KP, 1024);
    conv_w<<<dim3(64, 64), 256>>>(Wo, wot, 2048);

    // fused QKV projection (f16 2-term HMMA): C = [Q | K | V], [4096, 4096]
    gemm_mma<<<dim3(32, 32), 256, GEMM_SMEM>>>(xp, wqkvt, qkv, 4096);

    // fused RMSNorm + RoPE + split (Q pre-scaled by SCALE*log2e for exp2 softmax)
    const float qscale = (float)(0.08838834764831845 * 1.4426950408889634);
    norm_rope_split<<<8192, 256>>>(qkv, 0, Hh, qnw, cs, sn, qhh, qll, qscale);
    norm_rope_split<<<4096, 256>>>(qkv, 2048, KVh, knw, cs, sn, khh, kll, 1.0f);
    conv_vt<<<dim3(64, 4, 16), 256>>>(qkv + 3072, vth, vtl);

    // flash attention (HMMA bf16, no-running-max exp2 softmax)
    flash_mma<<<dim3(16, Hh, Bsz), 256, FL_SMEM>>>(qhh, qll, khh, kll, vth, vtl, ap);

    // output projection (f16 2-term)
    gemm_mma<<<dim3(16, 32), 256, GEMM_SMEM>>>(ap, wot, (float*)d_out, 2048);
}

// round 12
// speedup vs baseline: 1.6338x; 1.1244x over previous
#include <cuda_runtime.h>
#include <cuda_bf16.h>
#include <cuda_fp16.h>
#include <math.h>

#define Bsz 2
#define Ssz 2048
#define HIDs 2048
#define Hh 16
#define KVh 8
#define Dh 128
#define KP 4096              // K' = 2*2048 for f16 2-term split
#define NT 64                // KP / 64 k-chunks
#define STG_A (128 * 72 * 2)            // 18432 B per A tile (stride 144B)
#define STG_BYTES (2 * STG_A)           // 36864
#define GEMM_SMEM (3 * STG_BYTES)       // 3-stage = 110592

// flash smem: per stage K[64][136] f16 + Vh[128][72] + Vl[128][72]
#define FKT 17408
#define FVT 18432
#define FLSTG (FKT + 2 * FVT)           // 54272
#define FL_SMEM (2 * FLSTG)             // 108544

// ---------------- scratch (static device arrays: no allocs allowed) ----------
__device__ float g_qkv[(size_t)4096 * 4096];          // fused QKV output [M, 4096]

__device__ __align__(16) __half g_xp[(size_t)4096 * KP];
__device__ __align__(16) __half g_ap[(size_t)4096 * KP];   // att split (flash writes)
__device__ __align__(16) __half g_wqkvt[(size_t)4096 * KP];
__device__ __align__(16) __half g_wot[(size_t)2048 * KP];

// head-major f16 splits for flash
__device__ __align__(16) __half g_qh[(size_t)Bsz * Hh * Ssz * Dh];
__device__ __align__(16) __half g_ql[(size_t)Bsz * Hh * Ssz * Dh];
__device__ __align__(16) __half g_kh[(size_t)Bsz * KVh * Ssz * Dh];
__device__ __align__(16) __half g_kl[(size_t)Bsz * KVh * Ssz * Dh];   // written, unused
__device__ __align__(16) __half g_vth[(size_t)Bsz * KVh * Dh * Ssz];
__device__ __align__(16) __half g_vtl[(size_t)Bsz * KVh * Dh * Ssz];

// ====================== PTX helpers =========================================
__device__ __forceinline__ unsigned smem_u32(const void* p) {
    unsigned a;
    asm("{ .reg .u64 t; cvta.to.shared.u64 t, %1; cvt.u32.u64 %0, t; }"
        : "=r"(a) : "l"(p));
    return a;
}
#define CP16(dst, src) \
    asm volatile("cp.async.cg.shared.global [%0], [%1], 16;" :: "r"(dst), "l"(src))
#define CP_COMMIT() asm volatile("cp.async.commit_group;")

__device__ __forceinline__ void ldsm4(unsigned& r0, unsigned& r1,
                                      unsigned& r2, unsigned& r3, unsigned a) {
    asm volatile("ldmatrix.sync.aligned.m8n8.x4.shared.b16 {%0,%1,%2,%3}, [%4];"
                 : "=r"(r0), "=r"(r1), "=r"(r2), "=r"(r3) : "r"(a));
}
// f16 mma
__device__ __forceinline__ void mma16816h(float* d, const unsigned* a,
                                          unsigned b0, unsigned b1) {
    asm volatile(
        "mma.sync.aligned.m16n8k16.row.col.f32.f16.f16.f32 "
        "{%0,%1,%2,%3}, {%4,%5,%6,%7}, {%8,%9}, {%0,%1,%2,%3};"
        : "+f"(d[0]), "+f"(d[1]), "+f"(d[2]), "+f"(d[3])
        : "r"(a[0]), "r"(a[1]), "r"(a[2]), "r"(a[3]), "r"(b0), "r"(b1));
}
__device__ __forceinline__ unsigned pack2h(float lo, float hi) {
    unsigned d;
    asm("cvt.rn.f16x2.f32 %0, %1, %2;" : "=r"(d) : "f"(hi), "f"(lo));
    return d;
}
__device__ __forceinline__ float ex2(float x) {
    float r;
    asm("ex2.approx.f32 %0, %1;" : "=f"(r) : "f"(x));
    return r;
}

// ====================== conversion kernels ==================================
// A' = [hi | lo] f16 along K'   (src [M, 2048] fp32 row-major)
__global__ __launch_bounds__(256) void conv_a(
    const float* __restrict__ src, __half* __restrict__ dst)
{
    size_t i = (size_t)blockIdx.x * 256 + threadIdx.x;
    int m = (int)(i >> 9);
    int k4 = (int)(i & 511);
    float4 v = ((const float4*)(src + (size_t)m * 2048))[k4];
    __half h0 = __float2half(v.x), h1 = __float2half(v.y);
    __half h2 = __float2half(v.z), h3 = __float2half(v.w);
    __half l0 = __float2half(v.x - __half2float(h0));
    __half l1 = __float2half(v.y - __half2float(h1));
    __half l2 = __float2half(v.z - __half2float(h2));
    __half l3 = __float2half(v.w - __half2float(h3));
    __half2* row = (__half2*)(dst + (size_t)m * KP) + k4 * 2;
    row[0] = __halves2half2(h0, h1);
    row[1] = __halves2half2(h2, h3);
    row[1024] = __halves2half2(l0, l1);
    row[1025] = __halves2half2(l2, l3);
}

// B' = W^T f16: [n,k]=hi, [n,2048+k]=hi (duplicated).  W is [2048, N] fp32.
__global__ __launch_bounds__(256) void conv_w(
    const float* __restrict__ W, __half* __restrict__ Bt, int N)
{
    __shared__ float ts[32][33];
    int n0 = blockIdx.x * 32, k0 = blockIdx.y * 32;
    int tx = threadIdx.x & 31, ty = threadIdx.x >> 5;
    #pragma unroll
    for (int r = 0; r < 4; ++r)
        ts[ty + r * 8][tx] = W[(size_t)(k0 + ty + r * 8) * N + n0 + tx];
    __syncthreads();
    #pragma unroll
    for (int r = 0; r < 4; ++r) {
        int n = n0 + ty + r * 8, k = k0 + tx;
        __half hi = __float2half(ts[tx][ty + r * 8]);
        __half* row = Bt + (size_t)n * KP;
        row[k] = hi; row[2048 + k] = hi;
    }
}

// fused RMSNorm + RoPE + f16 hi/lo split + head-major write (flash inputs).
__global__ __launch_bounds__(256) void norm_rope_split(
    const float* __restrict__ qkv, int baseCol, int nh,
    const float* __restrict__ w,
    const float* __restrict__ cs, const float* __restrict__ sn,
    __half* __restrict__ dh, __half* __restrict__ dl,
    float scale)
{
    const int warp = blockIdx.x * 8 + (threadIdx.x >> 5);
    const int lane = threadIdx.x & 31;
    const int tok = warp / nh;          // b*S + s
    const int head = warp % nh;
    const int s = tok % Ssz;
    const int b = tok / Ssz;

    const float* row = qkv + (size_t)tok * 4096 + baseCol + head * Dh;
    float v0 = row[lane];
    float v1 = row[lane + 32];
    float v2 = row[lane + 64];
    float v3 = row[lane + 96];

    float ss = v0 * v0 + v1 * v1 + v2 * v2 + v3 * v3;
    #pragma unroll
    for (int o = 16; o; o >>= 1) ss += __shfl_xor_sync(0xffffffffu, ss, o);
    float r = rsqrtf(ss * (1.0f / 128.0f) + 1e-6f);

    v0 = v0 * r * w[lane];
    v1 = v1 * r * w[lane + 32];
    v2 = v2 * r * w[lane + 64];
    v3 = v3 * r * w[lane + 96];

    const float* cr = cs + (size_t)s * Dh;
    const float* sr = sn + (size_t)s * Dh;
    float o0 = (v0 * cr[lane]      - v2 * sr[lane])      * scale;
    float o1 = (v1 * cr[lane + 32] - v3 * sr[lane + 32]) * scale;
    float o2 = (v2 * cr[lane + 64] + v0 * sr[lane + 64]) * scale;
    float o3 = (v3 * cr[lane + 96] + v1 * sr[lane + 96]) * scale;

    __half h0 = __float2half(o0), h1 = __float2half(o1);
    __half h2 = __float2half(o2), h3 = __float2half(o3);
    __half e0 = __float2half(o0 - __half2float(h0));
    __half e1 = __float2half(o1 - __half2float(h1));
    __half e2 = __float2half(o2 - __half2float(h2));
    __half e3 = __float2half(o3 - __half2float(h3));

    size_t o = (((size_t)b * nh + head) * Ssz + s) * 128;
    dh[o + lane]      = h0; dh[o + lane + 32] = h1;
    dh[o + lane + 64] = h2; dh[o + lane + 96] = h3;
    dl[o + lane]      = e0; dl[o + lane + 32] = e1;
    dl[o + lane + 64] = e2; dl[o + lane + 96] = e3;
}

// V from fused buffer (base already offset to V cols) -> Vt hi/lo f16 [B*KV,128,S]
__global__ __launch_bounds__(256) void conv_vt(
    const float* __restrict__ v, __half* __restrict__ th,
    __half* __restrict__ tl)
{
    __shared__ float ts[32][33];
    int s0 = blockIdx.x * 32, d0 = blockIdx.y * 32;
    int bk = blockIdx.z;
    int b = bk >> 3, kv = bk & 7;
    int tx = threadIdx.x & 31, ty = threadIdx.x >> 5;
    #pragma unroll
    for (int r = 0; r < 4; ++r)
        ts[ty + r * 8][tx] =
            v[(size_t)(b * Ssz + s0 + ty + r * 8) * 4096 + kv * 128 + d0 + tx];
    __syncthreads();
    #pragma unroll
    for (int r = 0; r < 4; ++r) {
        float x = ts[tx][ty + r * 8];
        __half hi = __float2half(x);
        __half lo = __float2half(x - __half2float(hi));
        size_t o = ((size_t)bk * 128 + d0 + ty + r * 8) * Ssz + s0 + tx;
        th[o] = hi; tl[o] = lo;
    }
}

// ====================== f16 GEMM (3-stage, 1 barrier/chunk) =================
__global__ __launch_bounds__(256, 2) void gemm_mma(
    const __half* __restrict__ A, const __half* __restrict__ Bm,
    float* __restrict__ C, int N)
{
    extern __shared__ __align__(16) char smem[];
    const unsigned sb = smem_u32(smem);
    const int tid = threadIdx.x;
    const int lane = tid & 31;
    const int wid = tid >> 5;
    const int wr = wid >> 1;
    const int wc = wid & 1;
    const int bm = blockIdx.y << 7, bn = blockIdx.x << 7;

    const int lrow = tid >> 3, lcol = tid & 7;
    const __half* Ag = A + (size_t)(bm + lrow) * KP + lcol * 8;
    const __half* Bg = Bm + (size_t)(bn + lrow) * KP + lcol * 8;
    const unsigned sOff = lrow * 144 + lcol * 16;

    float acc[2][8][4];
    #pragma unroll
    for (int i = 0; i < 2; ++i)
        #pragma unroll
        for (int j = 0; j < 8; ++j)
            #pragma unroll
            for (int e = 0; e < 4; ++e) acc[i][j][e] = 0.0f;

    const unsigned aBase0 = sb + (32 * wr + (lane & 15)) * 144 + (lane >> 4) * 16;
    const unsigned bBase0 = sb + STG_A + (64 * wc + (lane & 15)) * 144 + (lane >> 4) * 16;

    #pragma unroll
    for (int c = 0; c < 2; ++c) {
        const unsigned st = c * STG_BYTES;
        const unsigned as = sb + st + sOff, bs = sb + st + STG_A + sOff;
        const __half* ag = Ag + (size_t)c * 64;
        const __half* bg = Bg + (size_t)c * 64;
        #pragma unroll
        for (int i = 0; i < 4; ++i) {
            CP16(as + i * 32 * 144, ag + (size_t)(32 * i) * KP);
            CP16(bs + i * 32 * 144, bg + (size_t)(32 * i) * KP);
        }
        CP_COMMIT();
    }

    int stage = 0, nstage = 2;
    for (int c = 0; c < NT; ++c) {
        if (c + 1 < NT) asm volatile("cp.async.wait_group 1;" ::: "memory");
        else            asm volatile("cp.async.wait_group 0;" ::: "memory");
        __syncthreads();

        if (c + 2 < NT) {
            const unsigned st = nstage * STG_BYTES;
            const unsigned as = sb + st + sOff, bs = sb + st + STG_A + sOff;
            const __half* ag = Ag + (size_t)(c + 2) * 64;
            const __half* bg = Bg + (size_t)(c + 2) * 64;
            #pragma unroll
            for (int i = 0; i < 4; ++i) {
                CP16(as + i * 32 * 144, ag + (size_t)(32 * i) * KP);
                CP16(bs + i * 32 * 144, bg + (size_t)(32 * i) * KP);
            }
            CP_COMMIT();
            nstage = (nstage == 2) ? 0 : nstage + 1;
        }

        const unsigned st = stage * STG_BYTES;
        stage = (stage == 2) ? 0 : stage + 1;
        const unsigned aB = aBase0 + st, bB = bBase0 + st;
        #pragma unroll
        for (int ks = 0; ks < 4; ++ks) {
            unsigned a[2][4];
            ldsm4(a[0][0], a[0][1], a[0][2], a[0][3], aB + ks * 32);
            ldsm4(a[1][0], a[1][1], a[1][2], a[1][3], aB + 16 * 144 + ks * 32);
            unsigned b[8][2];
            #pragma unroll
            for (int nt = 0; nt < 4; ++nt) {
                unsigned r0, r1, r2, r3;
                ldsm4(r0, r1, r2, r3, bB + nt * 16 * 144 + ks * 32);
                b[nt * 2][0] = r0; b[nt * 2][1] = r2;
                b[nt * 2 + 1][0] = r1; b[nt * 2 + 1][1] = r3;
            }
            #pragma unroll
            for (int mt = 0; mt < 2; ++mt)
                #pragma unroll
                for (int nt = 0; nt < 8; ++nt)
                    mma16816h(acc[mt][nt], a[mt], b[nt][0], b[nt][1]);
        }
    }

    #pragma unroll
    for (int mt = 0; mt < 2; ++mt) {
        const int r0 = bm + 32 * wr + 16 * mt + (lane >> 2);
        #pragma unroll
        for (int nt = 0; nt < 8; ++nt) {
            const int col = bn + 64 * wc + 8 * nt + (lane & 3) * 2;
            float2 v0 = make_float2(acc[mt][nt][0], acc[mt][nt][1]);
            float2 v1 = make_float2(acc[mt][nt][2], acc[mt][nt][3]);
            *(float2*)&C[(size_t)r0 * N + col]       = v0;
            *(float2*)&C[(size_t)(r0 + 8) * N + col] = v1;
        }
    }
}

// ====================== f16 flash attention (2-term QK, 2-term PV) ==========
// Per stage: K f16 [64][136] + Vh [128][72] + Vl [128][72].
__device__ __forceinline__ void load_kv_tile(
    unsigned sbase, int tid,
    const __half* khp, const __half* vthp, const __half* vtlp, int nBase)
{
    // K: 64 rows x 256B, 4 threads/row x 64B
    const int r = tid >> 2, c0 = (tid & 3) * 4;
    const char* gk = (const char*)(khp + (size_t)(nBase + r) * 128) + c0 * 16;
    const unsigned dk = sbase + r * 272 + c0 * 16;
    #pragma unroll
    for (int i = 0; i < 4; ++i) CP16(dk + i * 16, gk + i * 16);
    // V hi/lo: 128 rows x 128B each, 2 threads/row x 64B
    const int r2 = tid >> 1, c2 = (tid & 1) * 4;
    const char* gv = (const char*)(vthp + (size_t)r2 * Ssz + nBase) + c2 * 16;
    const char* gw = (const char*)(vtlp + (size_t)r2 * Ssz + nBase) + c2 * 16;
    const unsigned dv = sbase + FKT + r2 * 144 + c2 * 16;
    #pragma unroll
    for (int i = 0; i < 4; ++i) {
        CP16(dv + i * 16, gv + i * 16);
        CP16(dv + FVT + i * 16, gw + i * 16);
    }
}

__global__ __launch_bounds__(256, 1) void flash_mma(
    const __half* __restrict__ qh, const __half* __restrict__ ql,
    const __half* __restrict__ kh,
    const __half* __restrict__ vth, const __half* __restrict__ vtl,
    __half* __restrict__ outp)           // split f16 [M, KP] hi|lo
{
    extern __shared__ __align__(16) char smem[];
    const unsigned sb = smem_u32(smem);
    const int tid = threadIdx.x, lane = tid & 31, w = tid >> 5;
    const int qi = 15 - blockIdx.x;
    const int h = blockIdx.y, b = blockIdx.z;
    const int kvh = h >> 1;
    const int mBase = qi << 7;
    const int ntiles = 2 * qi + 2;

    const __half* qhp = qh + (((size_t)b * Hh + h) * Ssz + mBase) * Dh;
    const __half* qlp = ql + (((size_t)b * Hh + h) * Ssz + mBase) * Dh;
    const __half* khp = kh + ((size_t)b * KVh + kvh) * Ssz * Dh;
    const __half* vthp = vth + ((size_t)b * KVh + kvh) * Dh * Ssz;
    const __half* vtlp = vtl + ((size_t)b * KVh + kvh) * Dh * Ssz;

    // prologue: stage Q (hi at sb, lo at sb+34816), extract, then KV tile0
    {
        const int r = tid >> 1, cb = (tid & 1) * 8;
        const unsigned dq = sb + r * 272 + cb * 16;
        const char* gq = (const char*)(qhp + (size_t)r * Dh) + cb * 16;
        const char* gl = (const char*)(qlp + (size_t)r * Dh) + cb * 16;
        #pragma unroll
        for (int i = 0; i < 8; ++i) {
            CP16(dq + i * 16, gq + i * 16);
            CP16(dq + 34816 + i * 16, gl + i * 16);
        }
    }
    CP_COMMIT();
    asm volatile("cp.async.wait_group 0;" ::: "memory");
    __syncthreads();

    unsigned qhf[8][4], qlf[8][4];
    {
        const unsigned qB = sb + (16 * w + (lane & 15)) * 272 + (lane >> 4) * 16;
        #pragma unroll
        for (int kt = 0; kt < 8; ++kt) {
            ldsm4(qhf[kt][0], qhf[kt][1], qhf[kt][2], qhf[kt][3], qB + kt * 32);
            ldsm4(qlf[kt][0], qlf[kt][1], qlf[kt][2], qlf[kt][3], qB + 34816 + kt * 32);
        }
    }
    __syncthreads();        // Q fully extracted before overwriting with tile0

    load_kv_tile(sb, tid, khp, vthp, vtlp, 0);
    CP_COMMIT();

    float o_[16][4];
    #pragma unroll
    for (int n = 0; n < 16; ++n)
        #pragma unroll
        for (int e = 0; e < 4; ++e) o_[n][e] = 0.0f;
    float l_lo = 0.0f, l_hi = 0.0f;
    const int gm_lo = mBase + 16 * w + (lane >> 2);
    const int gm_hi = gm_lo + 8;

    for (int t = 0; t < ntiles; ++t) {
        if (t + 1 < ntiles) {
            load_kv_tile(sb + ((t + 1) & 1) * FLSTG, tid, khp, vthp, vtlp,
                         (t + 1) * 64);
            CP_COMMIT();
            asm volatile("cp.async.wait_group 1;" ::: "memory");
        } else {
            asm volatile("cp.async.wait_group 0;" ::: "memory");
        }
        __syncthreads();
        const unsigned stb = sb + (t & 1) * FLSTG;

        // ---- QK^T (2-term: Qh*K + Ql*K); scores in log2 domain ----
        float s_[8][4];
        #pragma unroll
        for (int j = 0; j < 8; ++j)
            #pragma unroll
            for (int e = 0; e < 4; ++e) s_[j][e] = 0.0f;

        const unsigned kB = stb + (lane & 15) * 272 + (lane >> 4) * 16;
        #pragma unroll
        for (int kt = 0; kt < 8; ++kt) {
            #pragma unroll
            for (int nt = 0; nt < 4; ++nt) {
                unsigned r0, r1, r2, r3;
                ldsm4(r0, r1, r2, r3, kB + nt * 16 * 272 + kt * 32);
                mma16816h(s_[nt * 2],     qhf[kt], r0, r2);
                mma16816h(s_[nt * 2 + 1], qhf[kt], r1, r3);
                mma16816h(s_[nt * 2],     qlf[kt], r0, r2);
                mma16816h(s_[nt * 2 + 1], qlf[kt], r1, r3);
            }
        }

        // ---- mask (last two tiles only) + fixed-shift softmax ----
        const int nBase = t * 64;
        if (t >= 2 * qi) {
            #pragma unroll
            for (int j = 0; j < 8; ++j) {
                const int gn0 = nBase + 8 * j + (lane & 3) * 2;
                if (gn0 > gm_lo)     s_[j][0] = -1e30f;
                if (gn0 + 1 > gm_lo) s_[j][1] = -1e30f;
                if (gn0 > gm_hi)     s_[j][2] = -1e30f;
                if (gn0 + 1 > gm_hi) s_[j][3] = -1e30f;
            }
        }
        #pragma unroll
        for (int j = 0; j < 8; ++j) {
            float p0 = ex2(s_[j][0]);
            float p1 = ex2(s_[j][1]);
            float p2 = ex2(s_[j][2]);
            float p3 = ex2(s_[j][3]);
            s_[j][0] = p0; s_[j][1] = p1; s_[j][2] = p2; s_[j][3] = p3;
            l_lo += p0 + p1; l_hi += p2 + p3;
        }

        // ---- PV (2-term: Ph*Vh + Ph*Vl, P from registers) ----
        const unsigned vB = stb + FKT + (lane & 15) * 144 + (lane >> 4) * 16;
        #pragma unroll
        for (int kt2 = 0; kt2 < 4; ++kt2) {
            const float* pa = s_[2 * kt2];
            const float* pb = s_[2 * kt2 + 1];
            unsigned ahf[4];
            ahf[0] = pack2h(pa[0], pa[1]); ahf[1] = pack2h(pa[2], pa[3]);
            ahf[2] = pack2h(pb[0], pb[1]); ahf[3] = pack2h(pb[2], pb[3]);
            #pragma unroll
            for (int vt = 0; vt < 8; ++vt) {
                unsigned r0, r1, r2, r3;
                ldsm4(r0, r1, r2, r3, vB + vt * 16 * 144 + kt2 * 32);
                mma16816h(o_[2 * vt],     ahf, r0, r2);
                mma16816h(o_[2 * vt + 1], ahf, r1, r3);
            }
            #pragma unroll
            for (int vt = 0; vt < 8; ++vt) {
                unsigned r0, r1, r2, r3;
                ldsm4(r0, r1, r2, r3, vB + FVT + vt * 16 * 144 + kt2 * 32);
                mma16816h(o_[2 * vt],     ahf, r0, r2);
                mma16816h(o_[2 * vt + 1], ahf, r1, r3);
            }
        }
        __syncthreads();
    }

    // ---- epilogue: reduce l across quad, normalize, write f16 [hi|lo] ----
    l_lo += __shfl_xor_sync(0xffffffffu, l_lo, 1);
    l_lo += __shfl_xor_sync(0xffffffffu, l_lo, 2);
    l_hi += __shfl_xor_sync(0xffffffffu, l_hi, 1);
    l_hi += __shfl_xor_sync(0xffffffffu, l_hi, 2);
    const float il = 1.0f / l_lo, ih = 1.0f / l_hi;
    __half* arl = outp + (size_t)(b * Ssz + gm_lo) * KP + h * Dh;
    __half* arh = outp + (size_t)(b * Ssz + gm_hi) * KP + h * Dh;
    #pragma unroll
    for (int n = 0; n < 16; ++n) {
        const int col = 8 * n + (lane & 3) * 2;
        float a0 = o_[n][0] * il, a1 = o_[n][1] * il;
        float b0 = o_[n][2] * ih, b1 = o_[n][3] * ih;
        __half ah0 = __float2half(a0), ah1 = __float2half(a1);
        __half bh0 = __float2half(b0), bh1 = __float2half(b1);
        __half2 aH = __halves2half2(ah0, ah1);
        __half2 bH = __halves2half2(bh0, bh1);
        __half2 aL = __halves2half2(
            __float2half(a0 - __half2float(ah0)),
            __float2half(a1 - __half2float(ah1)));
        __half2 bL = __halves2half2(
            __float2half(b0 - __half2float(bh0)),
            __float2half(b1 - __half2float(bh1)));
        *(__half2*)(arl + col)        = aH;
        *(__half2*)(arl + 2048 + col) = aL;
        *(__half2*)(arh + col)        = bH;
        *(__half2*)(arh + 2048 + col) = bL;
    }
}

// ---------------- host launch -------------------------------------------------
extern "C" void kernel_launch(void* const* d_in, const int* in_sizes, int n_in,
                              void* d_out, int out_size)
{
    const float* x   = (const float*)d_in[0];
    const float* Wq  = (const float*)d_in[1];
    const float* Wk  = (const float*)d_in[2];
    const float* Wv  = (const float*)d_in[3];
    const float* Wo  = (const float*)d_in[4];
    const float* qnw = (const float*)d_in[5];
    const float* knw = (const float*)d_in[6];
    const float* cs  = (const float*)d_in[7];
    const float* sn  = (const float*)d_in[8];

    float *qkv;
    __half *xp, *ap, *wqkvt, *wot;
    __half *qhh, *qll, *khh, *kll, *vth, *vtl;
    cudaGetSymbolAddress((void**)&qkv, g_qkv);
    cudaGetSymbolAddress((void**)&xp, g_xp);
    cudaGetSymbolAddress((void**)&ap, g_ap);
    cudaGetSymbolAddress((void**)&wqkvt, g_wqkvt);
    cudaGetSymbolAddress((void**)&wot, g_wot);
    cudaGetSymbolAddress((void**)&qhh, g_qh);
    cudaGetSymbolAddress((void**)&qll, g_ql);
    cudaGetSymbolAddress((void**)&khh, g_kh);
    cudaGetSymbolAddress((void**)&kll, g_kl);
    cudaGetSymbolAddress((void**)&vth, g_vth);
    cudaGetSymbolAddress((void**)&vtl, g_vtl);

    cudaFuncSetAttribute(gemm_mma, cudaFuncAttributeMaxDynamicSharedMemorySize, GEMM_SMEM);
    cudaFuncSetAttribute(flash_mma, cudaFuncAttributeMaxDynamicSharedMemorySize, FL_SMEM);

    // split/convert inputs + weights (QKV weights concatenated along N)
    conv_a<<<8192, 256>>>(x, xp);
    conv_w<<<dim3(64, 64), 256>>>(Wq, wqkvt, 2048);
    conv_w<<<dim3(32, 64), 256>>>(Wk, wqkvt + (size_t)2048 * KP, 1024);
    conv_w<<<dim3(32, 64), 256>>>(Wv, wqkvt + (size_t)3072 * KP, 1024);
    conv_w<<<dim3(64, 64), 256>>>(Wo, wot, 2048);

    // fused QKV projection (f16 2-term HMMA): C = [Q | K | V], [4096, 4096]
    gemm_mma<<<dim3(32, 32), 256, GEMM_SMEM>>>(xp, wqkvt, qkv, 4096);

    // fused RMSNorm + RoPE + split (Q pre-scaled by SCALE*log2e for exp2 softmax)
    const float qscale = (float)(0.08838834764831845 * 1.4426950408889634);
    norm_rope_split<<<8192, 256>>>(qkv, 0, Hh, qnw, cs, sn, qhh, qll, qscale);
    norm_rope_split<<<4096, 256>>>(qkv, 2048, KVh, knw, cs, sn, khh, kll, 1.0f);
    conv_vt<<<dim3(64, 4, 16), 256>>>(qkv + 3072, vth, vtl);

    // flash attention (f16 2-term QK / 2-term PV, no-running-max exp2 softmax)
    flash_mma<<<dim3(16, Hh, Bsz), 256, FL_SMEM>>>(qhh, qll, khh, vth, vtl, ap);

    // output projection (f16 2-term)
    gemm_mma<<<dim3(16, 32), 256, GEMM_SMEM>>>(ap, wot, (float*)d_out, 2048);
}

// round 13
// speedup vs baseline: 2.3493x; 1.4380x over previous
#include <cuda_runtime.h>
#include <cuda_bf16.h>
#include <cuda_fp16.h>
#include <math.h>

#define Bsz 2
#define Ssz 2048
#define HIDs 2048
#define Hh 16
#define KVh 8
#define Dh 128
#define KP 2048              // single-f16 GEMM: K' = K = 2048
#define NT 32                // KP / 64 k-chunks
#define STG_A (128 * 72 * 2)            // 18432 B per A tile (stride 144B)
#define STG_BYTES (2 * STG_A)           // 36864
#define GEMM_SMEM (3 * STG_BYTES)       // 3-stage = 110592

// flash smem: per stage K[64][136] f16 + Vh[128][72] + Vl[128][72]
#define FKT 17408
#define FVT 18432
#define FLSTG (FKT + 2 * FVT)           // 54272
#define FL_SMEM (2 * FLSTG)             // 108544

// ---------------- scratch (static device arrays: no allocs allowed) ----------
__device__ float g_qkv[(size_t)4096 * 4096];          // fused QKV output [M, 4096]

__device__ __align__(16) __half g_xp[(size_t)4096 * KP];
__device__ __align__(16) __half g_ap[(size_t)4096 * KP];   // att f16 (flash writes)
__device__ __align__(16) __half g_wqkvt[(size_t)4096 * KP];
__device__ __align__(16) __half g_wot[(size_t)2048 * KP];

// head-major f16 splits for flash
__device__ __align__(16) __half g_qh[(size_t)Bsz * Hh * Ssz * Dh];
__device__ __align__(16) __half g_ql[(size_t)Bsz * Hh * Ssz * Dh];
__device__ __align__(16) __half g_kh[(size_t)Bsz * KVh * Ssz * Dh];
__device__ __align__(16) __half g_kl[(size_t)Bsz * KVh * Ssz * Dh];   // written, unused
__device__ __align__(16) __half g_vth[(size_t)Bsz * KVh * Dh * Ssz];
__device__ __align__(16) __half g_vtl[(size_t)Bsz * KVh * Dh * Ssz];

// ====================== PTX helpers =========================================
__device__ __forceinline__ unsigned smem_u32(const void* p) {
    unsigned a;
    asm("{ .reg .u64 t; cvta.to.shared.u64 t, %1; cvt.u32.u64 %0, t; }"
        : "=r"(a) : "l"(p));
    return a;
}
#define CP16(dst, src) \
    asm volatile("cp.async.cg.shared.global [%0], [%1], 16;" :: "r"(dst), "l"(src))
#define CP_COMMIT() asm volatile("cp.async.commit_group;")

__device__ __forceinline__ void ldsm4(unsigned& r0, unsigned& r1,
                                      unsigned& r2, unsigned& r3, unsigned a) {
    asm volatile("ldmatrix.sync.aligned.m8n8.x4.shared.b16 {%0,%1,%2,%3}, [%4];"
                 : "=r"(r0), "=r"(r1), "=r"(r2), "=r"(r3) : "r"(a));
}
// f16 mma
__device__ __forceinline__ void mma16816h(float* d, const unsigned* a,
                                          unsigned b0, unsigned b1) {
    asm volatile(
        "mma.sync.aligned.m16n8k16.row.col.f32.f16.f16.f32 "
        "{%0,%1,%2,%3}, {%4,%5,%6,%7}, {%8,%9}, {%0,%1,%2,%3};"
        : "+f"(d[0]), "+f"(d[1]), "+f"(d[2]), "+f"(d[3])
        : "r"(a[0]), "r"(a[1]), "r"(a[2]), "r"(a[3]), "r"(b0), "r"(b1));
}
__device__ __forceinline__ unsigned pack2h(float lo, float hi) {
    unsigned d;
    asm("cvt.rn.f16x2.f32 %0, %1, %2;" : "=r"(d) : "f"(hi), "f"(lo));
    return d;
}
__device__ __forceinline__ float ex2(float x) {
    float r;
    asm("ex2.approx.f32 %0, %1;" : "=f"(r) : "f"(x));
    return r;
}

// ====================== conversion kernels ==================================
// A' = f16 copy of src [M, 2048] fp32 row-major (single term)
__global__ __launch_bounds__(256) void conv_a(
    const float* __restrict__ src, __half* __restrict__ dst)
{
    size_t i = (size_t)blockIdx.x * 256 + threadIdx.x;   // over M*512 float4
    float4 v = ((const float4*)src)[i];
    __half2* d = (__half2*)dst + i * 2;
    d[0] = __floats2half2_rn(v.x, v.y);
    d[1] = __floats2half2_rn(v.z, v.w);
}

// B' = W^T f16 single [N, 2048].  W is [2048, N] fp32.
__global__ __launch_bounds__(256) void conv_w(
    const float* __restrict__ W, __half* __restrict__ Bt, int N)
{
    __shared__ float ts[32][33];
    int n0 = blockIdx.x * 32, k0 = blockIdx.y * 32;
    int tx = threadIdx.x & 31, ty = threadIdx.x >> 5;
    #pragma unroll
    for (int r = 0; r < 4; ++r)
        ts[ty + r * 8][tx] = W[(size_t)(k0 + ty + r * 8) * N + n0 + tx];
    __syncthreads();
    #pragma unroll
    for (int r = 0; r < 4; ++r) {
        int n = n0 + ty + r * 8, k = k0 + tx;
        Bt[(size_t)n * KP + k] = __float2half(ts[tx][ty + r * 8]);
    }
}

// fused RMSNorm + RoPE + f16 hi/lo split + head-major write (flash inputs).
__global__ __launch_bounds__(256) void norm_rope_split(
    const float* __restrict__ qkv, int baseCol, int nh,
    const float* __restrict__ w,
    const float* __restrict__ cs, const float* __restrict__ sn,
    __half* __restrict__ dh, __half* __restrict__ dl,
    float scale)
{
    const int warp = blockIdx.x * 8 + (threadIdx.x >> 5);
    const int lane = threadIdx.x & 31;
    const int tok = warp / nh;          // b*S + s
    const int head = warp % nh;
    const int s = tok % Ssz;
    const int b = tok / Ssz;

    const float* row = qkv + (size_t)tok * 4096 + baseCol + head * Dh;
    float v0 = row[lane];
    float v1 = row[lane + 32];
    float v2 = row[lane + 64];
    float v3 = row[lane + 96];

    float ss = v0 * v0 + v1 * v1 + v2 * v2 + v3 * v3;
    #pragma unroll
    for (int o = 16; o; o >>= 1) ss += __shfl_xor_sync(0xffffffffu, ss, o);
    float r = rsqrtf(ss * (1.0f / 128.0f) + 1e-6f);

    v0 = v0 * r * w[lane];
    v1 = v1 * r * w[lane + 32];
    v2 = v2 * r * w[lane + 64];
    v3 = v3 * r * w[lane + 96];

    const float* cr = cs + (size_t)s * Dh;
    const float* sr = sn + (size_t)s * Dh;
    float o0 = (v0 * cr[lane]      - v2 * sr[lane])      * scale;
    float o1 = (v1 * cr[lane + 32] - v3 * sr[lane + 32]) * scale;
    float o2 = (v2 * cr[lane + 64] + v0 * sr[lane + 64]) * scale;
    float o3 = (v3 * cr[lane + 96] + v1 * sr[lane + 96]) * scale;

    __half h0 = __float2half(o0), h1 = __float2half(o1);
    __half h2 = __float2half(o2), h3 = __float2half(o3);
    __half e0 = __float2half(o0 - __half2float(h0));
    __half e1 = __float2half(o1 - __half2float(h1));
    __half e2 = __float2half(o2 - __half2float(h2));
    __half e3 = __float2half(o3 - __half2float(h3));

    size_t o = (((size_t)b * nh + head) * Ssz + s) * 128;
    dh[o + lane]      = h0; dh[o + lane + 32] = h1;
    dh[o + lane + 64] = h2; dh[o + lane + 96] = h3;
    dl[o + lane]      = e0; dl[o + lane + 32] = e1;
    dl[o + lane + 64] = e2; dl[o + lane + 96] = e3;
}

// V from fused buffer (base already offset to V cols) -> Vt hi/lo f16 [B*KV,128,S]
__global__ __launch_bounds__(256) void conv_vt(
    const float* __restrict__ v, __half* __restrict__ th,
    __half* __restrict__ tl)
{
    __shared__ float ts[32][33];
    int s0 = blockIdx.x * 32, d0 = blockIdx.y * 32;
    int bk = blockIdx.z;
    int b = bk >> 3, kv = bk & 7;
    int tx = threadIdx.x & 31, ty = threadIdx.x >> 5;
    #pragma unroll
    for (int r = 0; r < 4; ++r)
        ts[ty + r * 8][tx] =
            v[(size_t)(b * Ssz + s0 + ty + r * 8) * 4096 + kv * 128 + d0 + tx];
    __syncthreads();
    #pragma unroll
    for (int r = 0; r < 4; ++r) {
        float x = ts[tx][ty + r * 8];
        __half hi = __float2half(x);
        __half lo = __float2half(x - __half2float(hi));
        size_t o = ((size_t)bk * 128 + d0 + ty + r * 8) * Ssz + s0 + tx;
        th[o] = hi; tl[o] = lo;
    }
}

// ====================== f16 GEMM (3-stage, 1 barrier/chunk) =================
// C[M,N] fp32 = A[M,2048] f16 x B[N,2048] f16, both K-major.
__global__ __launch_bounds__(256, 2) void gemm_mma(
    const __half* __restrict__ A, const __half* __restrict__ Bm,
    float* __restrict__ C, int N)
{
    extern __shared__ __align__(16) char smem[];
    const unsigned sb = smem_u32(smem);
    const int tid = threadIdx.x;
    const int lane = tid & 31;
    const int wid = tid >> 5;
    const int wr = wid >> 1;
    const int wc = wid & 1;
    const int bm = blockIdx.y << 7, bn = blockIdx.x << 7;

    const int lrow = tid >> 3, lcol = tid & 7;
    const __half* Ag = A + (size_t)(bm + lrow) * KP + lcol * 8;
    const __half* Bg = Bm + (size_t)(bn + lrow) * KP + lcol * 8;
    const unsigned sOff = lrow * 144 + lcol * 16;

    float acc[2][8][4];
    #pragma unroll
    for (int i = 0; i < 2; ++i)
        #pragma unroll
        for (int j = 0; j < 8; ++j)
            #pragma unroll
            for (int e = 0; e < 4; ++e) acc[i][j][e] = 0.0f;

    const unsigned aBase0 = sb + (32 * wr + (lane & 15)) * 144 + (lane >> 4) * 16;
    const unsigned bBase0 = sb + STG_A + (64 * wc + (lane & 15)) * 144 + (lane >> 4) * 16;

    #pragma unroll
    for (int c = 0; c < 2; ++c) {
        const unsigned st = c * STG_BYTES;
        const unsigned as = sb + st + sOff, bs = sb + st + STG_A + sOff;
        const __half* ag = Ag + (size_t)c * 64;
        const __half* bg = Bg + (size_t)c * 64;
        #pragma unroll
        for (int i = 0; i < 4; ++i) {
            CP16(as + i * 32 * 144, ag + (size_t)(32 * i) * KP);
            CP16(bs + i * 32 * 144, bg + (size_t)(32 * i) * KP);
        }
        CP_COMMIT();
    }

    int stage = 0, nstage = 2;
    for (int c = 0; c < NT; ++c) {
        if (c + 1 < NT) asm volatile("cp.async.wait_group 1;" ::: "memory");
        else            asm volatile("cp.async.wait_group 0;" ::: "memory");
        __syncthreads();

        if (c + 2 < NT) {
            const unsigned st = nstage * STG_BYTES;
            const unsigned as = sb + st + sOff, bs = sb + st + STG_A + sOff;
            const __half* ag = Ag + (size_t)(c + 2) * 64;
            const __half* bg = Bg + (size_t)(c + 2) * 64;
            #pragma unroll
            for (int i = 0; i < 4; ++i) {
                CP16(as + i * 32 * 144, ag + (size_t)(32 * i) * KP);
                CP16(bs + i * 32 * 144, bg + (size_t)(32 * i) * KP);
            }
            CP_COMMIT();
            nstage = (nstage == 2) ? 0 : nstage + 1;
        }

        const unsigned st = stage * STG_BYTES;
        stage = (stage == 2) ? 0 : stage + 1;
        const unsigned aB = aBase0 + st, bB = bBase0 + st;
        #pragma unroll
        for (int ks = 0; ks < 4; ++ks) {
            unsigned a[2][4];
            ldsm4(a[0][0], a[0][1], a[0][2], a[0][3], aB + ks * 32);
            ldsm4(a[1][0], a[1][1], a[1][2], a[1][3], aB + 16 * 144 + ks * 32);
            unsigned b[8][2];
            #pragma unroll
            for (int nt = 0; nt < 4; ++nt) {
                unsigned r0, r1, r2, r3;
                ldsm4(r0, r1, r2, r3, bB + nt * 16 * 144 + ks * 32);
                b[nt * 2][0] = r0; b[nt * 2][1] = r2;
                b[nt * 2 + 1][0] = r1; b[nt * 2 + 1][1] = r3;
            }
            #pragma unroll
            for (int mt = 0; mt < 2; ++mt)
                #pragma unroll
                for (int nt = 0; nt < 8; ++nt)
                    mma16816h(acc[mt][nt], a[mt], b[nt][0], b[nt][1]);
        }
    }

    #pragma unroll
    for (int mt = 0; mt < 2; ++mt) {
        const int r0 = bm + 32 * wr + 16 * mt + (lane >> 2);
        #pragma unroll
        for (int nt = 0; nt < 8; ++nt) {
            const int col = bn + 64 * wc + 8 * nt + (lane & 3) * 2;
            float2 v0 = make_float2(acc[mt][nt][0], acc[mt][nt][1]);
            float2 v1 = make_float2(acc[mt][nt][2], acc[mt][nt][3]);
            *(float2*)&C[(size_t)r0 * N + col]       = v0;
            *(float2*)&C[(size_t)(r0 + 8) * N + col] = v1;
        }
    }
}

// ====================== f16 flash attention (2-term QK, 2-term PV) ==========
// Per stage: K f16 [64][136] + Vh [128][72] + Vl [128][72].
__device__ __forceinline__ void load_kv_tile(
    unsigned sbase, int tid,
    const __half* khp, const __half* vthp, const __half* vtlp, int nBase)
{
    // K: 64 rows x 256B, 4 threads/row x 64B
    const int r = tid >> 2, c0 = (tid & 3) * 4;
    const char* gk = (const char*)(khp + (size_t)(nBase + r) * 128) + c0 * 16;
    const unsigned dk = sbase + r * 272 + c0 * 16;
    #pragma unroll
    for (int i = 0; i < 4; ++i) CP16(dk + i * 16, gk + i * 16);
    // V hi/lo: 128 rows x 128B each, 2 threads/row x 64B
    const int r2 = tid >> 1, c2 = (tid & 1) * 4;
    const char* gv = (const char*)(vthp + (size_t)r2 * Ssz + nBase) + c2 * 16;
    const char* gw = (const char*)(vtlp + (size_t)r2 * Ssz + nBase) + c2 * 16;
    const unsigned dv = sbase + FKT + r2 * 144 + c2 * 16;
    #pragma unroll
    for (int i = 0; i < 4; ++i) {
        CP16(dv + i * 16, gv + i * 16);
        CP16(dv + FVT + i * 16, gw + i * 16);
    }
}

__global__ __launch_bounds__(256, 1) void flash_mma(
    const __half* __restrict__ qh, const __half* __restrict__ ql,
    const __half* __restrict__ kh,
    const __half* __restrict__ vth, const __half* __restrict__ vtl,
    __half* __restrict__ outp)           // f16 [M, 2048]
{
    extern __shared__ __align__(16) char smem[];
    const unsigned sb = smem_u32(smem);
    const int tid = threadIdx.x, lane = tid & 31, w = tid >> 5;
    const int qi = 15 - blockIdx.x;
    const int h = blockIdx.y, b = blockIdx.z;
    const int kvh = h >> 1;
    const int mBase = qi << 7;
    const int ntiles = 2 * qi + 2;

    const __half* qhp = qh + (((size_t)b * Hh + h) * Ssz + mBase) * Dh;
    const __half* qlp = ql + (((size_t)b * Hh + h) * Ssz + mBase) * Dh;
    const __half* khp = kh + ((size_t)b * KVh + kvh) * Ssz * Dh;
    const __half* vthp = vth + ((size_t)b * KVh + kvh) * Dh * Ssz;
    const __half* vtlp = vtl + ((size_t)b * KVh + kvh) * Dh * Ssz;

    // prologue: stage Q (hi at sb, lo at sb+34816), extract, then KV tile0
    {
        const int r = tid >> 1, cb = (tid & 1) * 8;
        const unsigned dq = sb + r * 272 + cb * 16;
        const char* gq = (const char*)(qhp + (size_t)r * Dh) + cb * 16;
        const char* gl = (const char*)(qlp + (size_t)r * Dh) + cb * 16;
        #pragma unroll
        for (int i = 0; i < 8; ++i) {
            CP16(dq + i * 16, gq + i * 16);
            CP16(dq + 34816 + i * 16, gl + i * 16);
        }
    }
    CP_COMMIT();
    asm volatile("cp.async.wait_group 0;" ::: "memory");
    __syncthreads();

    unsigned qhf[8][4], qlf[8][4];
    {
        const unsigned qB = sb + (16 * w + (lane & 15)) * 272 + (lane >> 4) * 16;
        #pragma unroll
        for (int kt = 0; kt < 8; ++kt) {
            ldsm4(qhf[kt][0], qhf[kt][1], qhf[kt][2], qhf[kt][3], qB + kt * 32);
            ldsm4(qlf[kt][0], qlf[kt][1], qlf[kt][2], qlf[kt][3], qB + 34816 + kt * 32);
        }
    }
    __syncthreads();        // Q fully extracted before overwriting with tile0

    load_kv_tile(sb, tid, khp, vthp, vtlp, 0);
    CP_COMMIT();

    float o_[16][4];
    #pragma unroll
    for (int n = 0; n < 16; ++n)
        #pragma unroll
        for (int e = 0; e < 4; ++e) o_[n][e] = 0.0f;
    float l_lo = 0.0f, l_hi = 0.0f;
    const int gm_lo = mBase + 16 * w + (lane >> 2);
    const int gm_hi = gm_lo + 8;

    for (int t = 0; t < ntiles; ++t) {
        if (t + 1 < ntiles) {
            load_kv_tile(sb + ((t + 1) & 1) * FLSTG, tid, khp, vthp, vtlp,
                         (t + 1) * 64);
            CP_COMMIT();
            asm volatile("cp.async.wait_group 1;" ::: "memory");
        } else {
            asm volatile("cp.async.wait_group 0;" ::: "memory");
        }
        __syncthreads();
        const unsigned stb = sb + (t & 1) * FLSTG;

        // ---- QK^T (2-term: Qh*K + Ql*K); scores in log2 domain ----
        float s_[8][4];
        #pragma unroll
        for (int j = 0; j < 8; ++j)
            #pragma unroll
            for (int e = 0; e < 4; ++e) s_[j][e] = 0.0f;

        const unsigned kB = stb + (lane & 15) * 272 + (lane >> 4) * 16;
        #pragma unroll
        for (int kt = 0; kt < 8; ++kt) {
            #pragma unroll
            for (int nt = 0; nt < 4; ++nt) {
                unsigned r0, r1, r2, r3;
                ldsm4(r0, r1, r2, r3, kB + nt * 16 * 272 + kt * 32);
                mma16816h(s_[nt * 2],     qhf[kt], r0, r2);
                mma16816h(s_[nt * 2 + 1], qhf[kt], r1, r3);
                mma16816h(s_[nt * 2],     qlf[kt], r0, r2);
                mma16816h(s_[nt * 2 + 1], qlf[kt], r1, r3);
            }
        }

        // ---- mask (last two tiles only) + fixed-shift softmax ----
        const int nBase = t * 64;
        if (t >= 2 * qi) {
            #pragma unroll
            for (int j = 0; j < 8; ++j) {
                const int gn0 = nBase + 8 * j + (lane & 3) * 2;
                if (gn0 > gm_lo)     s_[j][0] = -1e30f;
                if (gn0 + 1 > gm_lo) s_[j][1] = -1e30f;
                if (gn0 > gm_hi)     s_[j][2] = -1e30f;
                if (gn0 + 1 > gm_hi) s_[j][3] = -1e30f;
            }
        }
        #pragma unroll
        for (int j = 0; j < 8; ++j) {
            float p0 = ex2(s_[j][0]);
            float p1 = ex2(s_[j][1]);
            float p2 = ex2(s_[j][2]);
            float p3 = ex2(s_[j][3]);
            s_[j][0] = p0; s_[j][1] = p1; s_[j][2] = p2; s_[j][3] = p3;
            l_lo += p0 + p1; l_hi += p2 + p3;
        }

        // ---- PV (2-term: Ph*Vh + Ph*Vl, P from registers) ----
        const unsigned vB = stb + FKT + (lane & 15) * 144 + (lane >> 4) * 16;
        #pragma unroll
        for (int kt2 = 0; kt2 < 4; ++kt2) {
            const float* pa = s_[2 * kt2];
            const float* pb = s_[2 * kt2 + 1];
            unsigned ahf[4];
            ahf[0] = pack2h(pa[0], pa[1]); ahf[1] = pack2h(pa[2], pa[3]);
            ahf[2] = pack2h(pb[0], pb[1]); ahf[3] = pack2h(pb[2], pb[3]);
            #pragma unroll
            for (int vt = 0; vt < 8; ++vt) {
                unsigned r0, r1, r2, r3;
                ldsm4(r0, r1, r2, r3, vB + vt * 16 * 144 + kt2 * 32);
                mma16816h(o_[2 * vt],     ahf, r0, r2);
                mma16816h(o_[2 * vt + 1], ahf, r1, r3);
            }
            #pragma unroll
            for (int vt = 0; vt < 8; ++vt) {
                unsigned r0, r1, r2, r3;
                ldsm4(r0, r1, r2, r3, vB + FVT + vt * 16 * 144 + kt2 * 32);
                mma16816h(o_[2 * vt],     ahf, r0, r2);
                mma16816h(o_[2 * vt + 1], ahf, r1, r3);
            }
        }
        __syncthreads();
    }

    // ---- epilogue: reduce l across quad, normalize, write f16 ----
    l_lo += __shfl_xor_sync(0xffffffffu, l_lo, 1);
    l_lo += __shfl_xor_sync(0xffffffffu, l_lo, 2);
    l_hi += __shfl_xor_sync(0xffffffffu, l_hi, 1);
    l_hi += __shfl_xor_sync(0xffffffffu, l_hi, 2);
    const float il = 1.0f / l_lo, ih = 1.0f / l_hi;
    __half* arl = outp + (size_t)(b * Ssz + gm_lo) * KP + h * Dh;
    __half* arh = outp + (size_t)(b * Ssz + gm_hi) * KP + h * Dh;
    #pragma unroll
    for (int n = 0; n < 16; ++n) {
        const int col = 8 * n + (lane & 3) * 2;
        *(__half2*)(arl + col) = __floats2half2_rn(o_[n][0] * il, o_[n][1] * il);
        *(__half2*)(arh + col) = __floats2half2_rn(o_[n][2] * ih, o_[n][3] * ih);
    }
}

// ---------------- host launch -------------------------------------------------
extern "C" void kernel_launch(void* const* d_in, const int* in_sizes, int n_in,
                              void* d_out, int out_size)
{
    const float* x   = (const float*)d_in[0];
    const float* Wq  = (const float*)d_in[1];
    const float* Wk  = (const float*)d_in[2];
    const float* Wv  = (const float*)d_in[3];
    const float* Wo  = (const float*)d_in[4];
    const float* qnw = (const float*)d_in[5];
    const float* knw = (const float*)d_in[6];
    const float* cs  = (const float*)d_in[7];
    const float* sn  = (const float*)d_in[8];

    float *qkv;
    __half *xp, *ap, *wqkvt, *wot;
    __half *qhh, *qll, *khh, *kll, *vth, *vtl;
    cudaGetSymbolAddress((void**)&qkv, g_qkv);
    cudaGetSymbolAddress((void**)&xp, g_xp);
    cudaGetSymbolAddress((void**)&ap, g_ap);
    cudaGetSymbolAddress((void**)&wqkvt, g_wqkvt);
    cudaGetSymbolAddress((void**)&wot, g_wot);
    cudaGetSymbolAddress((void**)&qhh, g_qh);
    cudaGetSymbolAddress((void**)&qll, g_ql);
    cudaGetSymbolAddress((void**)&khh, g_kh);
    cudaGetSymbolAddress((void**)&kll, g_kl);
    cudaGetSymbolAddress((void**)&vth, g_vth);
    cudaGetSymbolAddress((void**)&vtl, g_vtl);

    cudaFuncSetAttribute(gemm_mma, cudaFuncAttributeMaxDynamicSharedMemorySize, GEMM_SMEM);
    cudaFuncSetAttribute(flash_mma, cudaFuncAttributeMaxDynamicSharedMemorySize, FL_SMEM);

    // convert inputs + weights (QKV weights concatenated along N)
    conv_a<<<8192, 256>>>(x, xp);
    conv_w<<<dim3(64, 64), 256>>>(Wq, wqkvt, 2048);
    conv_w<<<dim3(32, 64), 256>>>(Wk, wqkvt + (size_t)2048 * KP, 1024);
    conv_w<<<dim3(32, 64), 256>>>(Wv, wqkvt + (size_t)3072 * KP, 1024);
    conv_w<<<dim3(64, 64), 256>>>(Wo, wot, 2048);

    // fused QKV projection (single-f16 HMMA): C = [Q | K | V], [4096, 4096]
    gemm_mma<<<dim3(32, 32), 256, GEMM_SMEM>>>(xp, wqkvt, qkv, 4096);

    // fused RMSNorm + RoPE + split (Q pre-scaled by SCALE*log2e for exp2 softmax)
    const float qscale = (float)(0.08838834764831845 * 1.4426950408889634);
    norm_rope_split<<<8192, 256>>>(qkv, 0, Hh, qnw, cs, sn, qhh, qll, qscale);
    norm_rope_split<<<4096, 256>>>(qkv, 2048, KVh, knw, cs, sn, khh, kll, 1.0f);
    conv_vt<<<dim3(64, 4, 16), 256>>>(qkv + 3072, vth, vtl);

    // flash attention (f16 2-term QK / 2-term PV, no-running-max exp2 softmax)
    flash_mma<<<dim3(16, Hh, Bsz), 256, FL_SMEM>>>(qhh, qll, khh, vth, vtl, ap);

    // output projection (single-f16)
    gemm_mma<<<dim3(16, 32), 256, GEMM_SMEM>>>(ap, wot, (float*)d_out, 2048);
}

// round 14
// speedup vs baseline: 2.8986x; 1.2338x over previous
#include <cuda_runtime.h>
#include <cuda_bf16.h>
#include <cuda_fp16.h>
#include <math.h>

#define Bsz 2
#define Ssz 2048
#define HIDs 2048
#define Hh 16
#define KVh 8
#define Dh 128
#define KP 2048              // single-f16 GEMM: K' = K = 2048
#define NT 32                // KP / 64 k-chunks
#define STG_A (128 * 72 * 2)            // 18432 B per A tile (stride 144B)
#define STG_BYTES (2 * STG_A)           // 36864
#define GEMM_SMEM (3 * STG_BYTES)       // 3-stage = 110592

// flash smem: per stage K[64][136] f16 + V[128][72] f16
#define FKT 17408
#define FVT 18432
#define FLSTG (FKT + FVT)               // 35840
#define FL_SMEM (2 * FLSTG)             // 71680

// ---------------- scratch (static device arrays: no allocs allowed) ----------
__device__ float g_qkv[(size_t)4096 * 4096];          // fused QKV output [M, 4096]

__device__ __align__(16) __half g_xp[(size_t)4096 * KP];
__device__ __align__(16) __half g_ap[(size_t)4096 * KP];   // att f16 (flash writes)
__device__ __align__(16) __half g_wqkvt[(size_t)4096 * KP];
__device__ __align__(16) __half g_wot[(size_t)2048 * KP];

// head-major f16 for flash (single precision images)
__device__ __align__(16) __half g_qh[(size_t)Bsz * Hh * Ssz * Dh];
__device__ __align__(16) __half g_kh[(size_t)Bsz * KVh * Ssz * Dh];
__device__ __align__(16) __half g_vth[(size_t)Bsz * KVh * Dh * Ssz];

// ====================== PTX helpers =========================================
__device__ __forceinline__ unsigned smem_u32(const void* p) {
    unsigned a;
    asm("{ .reg .u64 t; cvta.to.shared.u64 t, %1; cvt.u32.u64 %0, t; }"
        : "=r"(a) : "l"(p));
    return a;
}
#define CP16(dst, src) \
    asm volatile("cp.async.cg.shared.global [%0], [%1], 16;" :: "r"(dst), "l"(src))
#define CP_COMMIT() asm volatile("cp.async.commit_group;")

__device__ __forceinline__ void ldsm4(unsigned& r0, unsigned& r1,
                                      unsigned& r2, unsigned& r3, unsigned a) {
    asm volatile("ldmatrix.sync.aligned.m8n8.x4.shared.b16 {%0,%1,%2,%3}, [%4];"
                 : "=r"(r0), "=r"(r1), "=r"(r2), "=r"(r3) : "r"(a));
}
// f16 mma
__device__ __forceinline__ void mma16816h(float* d, const unsigned* a,
                                          unsigned b0, unsigned b1) {
    asm volatile(
        "mma.sync.aligned.m16n8k16.row.col.f32.f16.f16.f32 "
        "{%0,%1,%2,%3}, {%4,%5,%6,%7}, {%8,%9}, {%0,%1,%2,%3};"
        : "+f"(d[0]), "+f"(d[1]), "+f"(d[2]), "+f"(d[3])
        : "r"(a[0]), "r"(a[1]), "r"(a[2]), "r"(a[3]), "r"(b0), "r"(b1));
}
__device__ __forceinline__ unsigned pack2h(float lo, float hi) {
    unsigned d;
    asm("cvt.rn.f16x2.f32 %0, %1, %2;" : "=r"(d) : "f"(hi), "f"(lo));
    return d;
}
__device__ __forceinline__ float ex2(float x) {
    float r;
    asm("ex2.approx.f32 %0, %1;" : "=f"(r) : "f"(x));
    return r;
}

// ====================== conversion kernels ==================================
// A' = f16 copy of src [M, 2048] fp32 row-major (single term)
__global__ __launch_bounds__(256) void conv_a(
    const float* __restrict__ src, __half* __restrict__ dst)
{
    size_t i = (size_t)blockIdx.x * 256 + threadIdx.x;   // over M*512 float4
    float4 v = ((const float4*)src)[i];
    __half2* d = (__half2*)dst + i * 2;
    d[0] = __floats2half2_rn(v.x, v.y);
    d[1] = __floats2half2_rn(v.z, v.w);
}

// B' = W^T f16 single [N, 2048].  W is [2048, N] fp32.
__global__ __launch_bounds__(256) void conv_w(
    const float* __restrict__ W, __half* __restrict__ Bt, int N)
{
    __shared__ float ts[32][33];
    int n0 = blockIdx.x * 32, k0 = blockIdx.y * 32;
    int tx = threadIdx.x & 31, ty = threadIdx.x >> 5;
    #pragma unroll
    for (int r = 0; r < 4; ++r)
        ts[ty + r * 8][tx] = W[(size_t)(k0 + ty + r * 8) * N + n0 + tx];
    __syncthreads();
    #pragma unroll
    for (int r = 0; r < 4; ++r) {
        int n = n0 + ty + r * 8, k = k0 + tx;
        Bt[(size_t)n * KP + k] = __float2half(ts[tx][ty + r * 8]);
    }
}

// fused RMSNorm + RoPE + f16 + head-major write (flash inputs, single term).
__global__ __launch_bounds__(256) void norm_rope_split(
    const float* __restrict__ qkv, int baseCol, int nh,
    const float* __restrict__ w,
    const float* __restrict__ cs, const float* __restrict__ sn,
    __half* __restrict__ dh, float scale)
{
    const int warp = blockIdx.x * 8 + (threadIdx.x >> 5);
    const int lane = threadIdx.x & 31;
    const int tok = warp / nh;          // b*S + s
    const int head = warp % nh;
    const int s = tok % Ssz;
    const int b = tok / Ssz;

    const float* row = qkv + (size_t)tok * 4096 + baseCol + head * Dh;
    float v0 = row[lane];
    float v1 = row[lane + 32];
    float v2 = row[lane + 64];
    float v3 = row[lane + 96];

    float ss = v0 * v0 + v1 * v1 + v2 * v2 + v3 * v3;
    #pragma unroll
    for (int o = 16; o; o >>= 1) ss += __shfl_xor_sync(0xffffffffu, ss, o);
    float r = rsqrtf(ss * (1.0f / 128.0f) + 1e-6f);

    v0 = v0 * r * w[lane];
    v1 = v1 * r * w[lane + 32];
    v2 = v2 * r * w[lane + 64];
    v3 = v3 * r * w[lane + 96];

    const float* cr = cs + (size_t)s * Dh;
    const float* sr = sn + (size_t)s * Dh;
    float o0 = (v0 * cr[lane]      - v2 * sr[lane])      * scale;
    float o1 = (v1 * cr[lane + 32] - v3 * sr[lane + 32]) * scale;
    float o2 = (v2 * cr[lane + 64] + v0 * sr[lane + 64]) * scale;
    float o3 = (v3 * cr[lane + 96] + v1 * sr[lane + 96]) * scale;

    size_t o = (((size_t)b * nh + head) * Ssz + s) * 128;
    dh[o + lane]      = __float2half(o0);
    dh[o + lane + 32] = __float2half(o1);
    dh[o + lane + 64] = __float2half(o2);
    dh[o + lane + 96] = __float2half(o3);
}

// V from fused buffer (base offset to V cols) -> Vt f16 [B*KV,128,S]
__global__ __launch_bounds__(256) void conv_vt(
    const float* __restrict__ v, __half* __restrict__ th)
{
    __shared__ float ts[32][33];
    int s0 = blockIdx.x * 32, d0 = blockIdx.y * 32;
    int bk = blockIdx.z;
    int b = bk >> 3, kv = bk & 7;
    int tx = threadIdx.x & 31, ty = threadIdx.x >> 5;
    #pragma unroll
    for (int r = 0; r < 4; ++r)
        ts[ty + r * 8][tx] =
            v[(size_t)(b * Ssz + s0 + ty + r * 8) * 4096 + kv * 128 + d0 + tx];
    __syncthreads();
    #pragma unroll
    for (int r = 0; r < 4; ++r) {
        size_t o = ((size_t)bk * 128 + d0 + ty + r * 8) * Ssz + s0 + tx;
        th[o] = __float2half(ts[tx][ty + r * 8]);
    }
}

// ====================== f16 GEMM (3-stage, 1 barrier/chunk) =================
// C[M,N] fp32 = A[M,2048] f16 x B[N,2048] f16, both K-major.
__global__ __launch_bounds__(256, 2) void gemm_mma(
    const __half* __restrict__ A, const __half* __restrict__ Bm,
    float* __restrict__ C, int N)
{
    extern __shared__ __align__(16) char smem[];
    const unsigned sb = smem_u32(smem);
    const int tid = threadIdx.x;
    const int lane = tid & 31;
    const int wid = tid >> 5;
    const int wr = wid >> 1;
    const int wc = wid & 1;
    const int bm = blockIdx.y << 7, bn = blockIdx.x << 7;

    const int lrow = tid >> 3, lcol = tid & 7;
    const __half* Ag = A + (size_t)(bm + lrow) * KP + lcol * 8;
    const __half* Bg = Bm + (size_t)(bn + lrow) * KP + lcol * 8;
    const unsigned sOff = lrow * 144 + lcol * 16;

    float acc[2][8][4];
    #pragma unroll
    for (int i = 0; i < 2; ++i)
        #pragma unroll
        for (int j = 0; j < 8; ++j)
            #pragma unroll
            for (int e = 0; e < 4; ++e) acc[i][j][e] = 0.0f;

    const unsigned aBase0 = sb + (32 * wr + (lane & 15)) * 144 + (lane >> 4) * 16;
    const unsigned bBase0 = sb + STG_A + (64 * wc + (lane & 15)) * 144 + (lane >> 4) * 16;

    #pragma unroll
    for (int c = 0; c < 2; ++c) {
        const unsigned st = c * STG_BYTES;
        const unsigned as = sb + st + sOff, bs = sb + st + STG_A + sOff;
        const __half* ag = Ag + (size_t)c * 64;
        const __half* bg = Bg + (size_t)c * 64;
        #pragma unroll
        for (int i = 0; i < 4; ++i) {
            CP16(as + i * 32 * 144, ag + (size_t)(32 * i) * KP);
            CP16(bs + i * 32 * 144, bg + (size_t)(32 * i) * KP);
        }
        CP_COMMIT();
    }

    int stage = 0, nstage = 2;
    for (int c = 0; c < NT; ++c) {
        if (c + 1 < NT) asm volatile("cp.async.wait_group 1;" ::: "memory");
        else            asm volatile("cp.async.wait_group 0;" ::: "memory");
        __syncthreads();

        if (c + 2 < NT) {
            const unsigned st = nstage * STG_BYTES;
            const unsigned as = sb + st + sOff, bs = sb + st + STG_A + sOff;
            const __half* ag = Ag + (size_t)(c + 2) * 64;
            const __half* bg = Bg + (size_t)(c + 2) * 64;
            #pragma unroll
            for (int i = 0; i < 4; ++i) {
                CP16(as + i * 32 * 144, ag + (size_t)(32 * i) * KP);
                CP16(bs + i * 32 * 144, bg + (size_t)(32 * i) * KP);
            }
            CP_COMMIT();
            nstage = (nstage == 2) ? 0 : nstage + 1;
        }

        const unsigned st = stage * STG_BYTES;
        stage = (stage == 2) ? 0 : stage + 1;
        const unsigned aB = aBase0 + st, bB = bBase0 + st;
        #pragma unroll
        for (int ks = 0; ks < 4; ++ks) {
            unsigned a[2][4];
            ldsm4(a[0][0], a[0][1], a[0][2], a[0][3], aB + ks * 32);
            ldsm4(a[1][0], a[1][1], a[1][2], a[1][3], aB + 16 * 144 + ks * 32);
            unsigned b[8][2];
            #pragma unroll
            for (int nt = 0; nt < 4; ++nt) {
                unsigned r0, r1, r2, r3;
                ldsm4(r0, r1, r2, r3, bB + nt * 16 * 144 + ks * 32);
                b[nt * 2][0] = r0; b[nt * 2][1] = r2;
                b[nt * 2 + 1][0] = r1; b[nt * 2 + 1][1] = r3;
            }
            #pragma unroll
            for (int mt = 0; mt < 2; ++mt)
                #pragma unroll
                for (int nt = 0; nt < 8; ++nt)
                    mma16816h(acc[mt][nt], a[mt], b[nt][0], b[nt][1]);
        }
    }

    #pragma unroll
    for (int mt = 0; mt < 2; ++mt) {
        const int r0 = bm + 32 * wr + 16 * mt + (lane >> 2);
        #pragma unroll
        for (int nt = 0; nt < 8; ++nt) {
            const int col = bn + 64 * wc + 8 * nt + (lane & 3) * 2;
            float2 v0 = make_float2(acc[mt][nt][0], acc[mt][nt][1]);
            float2 v1 = make_float2(acc[mt][nt][2], acc[mt][nt][3]);
            *(float2*)&C[(size_t)r0 * N + col]       = v0;
            *(float2*)&C[(size_t)(r0 + 8) * N + col] = v1;
        }
    }
}

// ====================== f16 flash attention (single-term QK and PV) =========
// Per stage: K f16 [64][136] + V f16 [128][72].
__device__ __forceinline__ void load_kv_tile(
    unsigned sbase, int tid,
    const __half* khp, const __half* vthp, int nBase)
{
    // K: 64 rows x 256B, 4 threads/row x 64B
    const int r = tid >> 2, c0 = (tid & 3) * 4;
    const char* gk = (const char*)(khp + (size_t)(nBase + r) * 128) + c0 * 16;
    const unsigned dk = sbase + r * 272 + c0 * 16;
    #pragma unroll
    for (int i = 0; i < 4; ++i) CP16(dk + i * 16, gk + i * 16);
    // V: 128 rows x 128B, 2 threads/row x 64B
    const int r2 = tid >> 1, c2 = (tid & 1) * 4;
    const char* gv = (const char*)(vthp + (size_t)r2 * Ssz + nBase) + c2 * 16;
    const unsigned dv = sbase + FKT + r2 * 144 + c2 * 16;
    #pragma unroll
    for (int i = 0; i < 4; ++i) CP16(dv + i * 16, gv + i * 16);
}

__global__ __launch_bounds__(256, 1) void flash_mma(
    const __half* __restrict__ qh, const __half* __restrict__ kh,
    const __half* __restrict__ vth,
    __half* __restrict__ outp)           // f16 [M, 2048]
{
    extern __shared__ __align__(16) char smem[];
    const unsigned sb = smem_u32(smem);
    const int tid = threadIdx.x, lane = tid & 31, w = tid >> 5;
    const int qi = 15 - blockIdx.x;
    const int h = blockIdx.y, b = blockIdx.z;
    const int kvh = h >> 1;
    const int mBase = qi << 7;
    const int ntiles = 2 * qi + 2;

    const __half* qhp = qh + (((size_t)b * Hh + h) * Ssz + mBase) * Dh;
    const __half* khp = kh + ((size_t)b * KVh + kvh) * Ssz * Dh;
    const __half* vthp = vth + ((size_t)b * KVh + kvh) * Dh * Ssz;

    // prologue: stage Q at sb, extract, then KV tile0
    {
        const int r = tid >> 1, cb = (tid & 1) * 8;
        const unsigned dq = sb + r * 272 + cb * 16;
        const char* gq = (const char*)(qhp + (size_t)r * Dh) + cb * 16;
        #pragma unroll
        for (int i = 0; i < 8; ++i) CP16(dq + i * 16, gq + i * 16);
    }
    CP_COMMIT();
    asm volatile("cp.async.wait_group 0;" ::: "memory");
    __syncthreads();

    unsigned qhf[8][4];
    {
        const unsigned qB = sb + (16 * w + (lane & 15)) * 272 + (lane >> 4) * 16;
        #pragma unroll
        for (int kt = 0; kt < 8; ++kt)
            ldsm4(qhf[kt][0], qhf[kt][1], qhf[kt][2], qhf[kt][3], qB + kt * 32);
    }
    __syncthreads();        // Q fully extracted before overwriting with tile0

    load_kv_tile(sb, tid, khp, vthp, 0);
    CP_COMMIT();

    float o_[16][4];
    #pragma unroll
    for (int n = 0; n < 16; ++n)
        #pragma unroll
        for (int e = 0; e < 4; ++e) o_[n][e] = 0.0f;
    float l_lo = 0.0f, l_hi = 0.0f;
    const int gm_lo = mBase + 16 * w + (lane >> 2);
    const int gm_hi = gm_lo + 8;

    for (int t = 0; t < ntiles; ++t) {
        if (t + 1 < ntiles) {
            load_kv_tile(sb + ((t + 1) & 1) * FLSTG, tid, khp, vthp, (t + 1) * 64);
            CP_COMMIT();
            asm volatile("cp.async.wait_group 1;" ::: "memory");
        } else {
            asm volatile("cp.async.wait_group 0;" ::: "memory");
        }
        __syncthreads();
        const unsigned stb = sb + (t & 1) * FLSTG;

        // ---- QK^T (single term); scores in log2 domain ----
        float s_[8][4];
        #pragma unroll
        for (int j = 0; j < 8; ++j)
            #pragma unroll
            for (int e = 0; e < 4; ++e) s_[j][e] = 0.0f;

        const unsigned kB = stb + (lane & 15) * 272 + (lane >> 4) * 16;
        #pragma unroll
        for (int kt = 0; kt < 8; ++kt) {
            #pragma unroll
            for (int nt = 0; nt < 4; ++nt) {
                unsigned r0, r1, r2, r3;
                ldsm4(r0, r1, r2, r3, kB + nt * 16 * 272 + kt * 32);
                mma16816h(s_[nt * 2],     qhf[kt], r0, r2);
                mma16816h(s_[nt * 2 + 1], qhf[kt], r1, r3);
            }
        }

        // ---- mask (last two tiles only) + fixed-shift softmax ----
        const int nBase = t * 64;
        if (t >= 2 * qi) {
            #pragma unroll
            for (int j = 0; j < 8; ++j) {
                const int gn0 = nBase + 8 * j + (lane & 3) * 2;
                if (gn0 > gm_lo)     s_[j][0] = -1e30f;
                if (gn0 + 1 > gm_lo) s_[j][1] = -1e30f;
                if (gn0 > gm_hi)     s_[j][2] = -1e30f;
                if (gn0 + 1 > gm_hi) s_[j][3] = -1e30f;
            }
        }
        #pragma unroll
        for (int j = 0; j < 8; ++j) {
            float p0 = ex2(s_[j][0]);
            float p1 = ex2(s_[j][1]);
            float p2 = ex2(s_[j][2]);
            float p3 = ex2(s_[j][3]);
            s_[j][0] = p0; s_[j][1] = p1; s_[j][2] = p2; s_[j][3] = p3;
            l_lo += p0 + p1; l_hi += p2 + p3;
        }

        // ---- PV (single term, P from registers) ----
        const unsigned vB = stb + FKT + (lane & 15) * 144 + (lane >> 4) * 16;
        #pragma unroll
        for (int kt2 = 0; kt2 < 4; ++kt2) {
            const float* pa = s_[2 * kt2];
            const float* pb = s_[2 * kt2 + 1];
            unsigned ahf[4];
            ahf[0] = pack2h(pa[0], pa[1]); ahf[1] = pack2h(pa[2], pa[3]);
            ahf[2] = pack2h(pb[0], pb[1]); ahf[3] = pack2h(pb[2], pb[3]);
            #pragma unroll
            for (int vt = 0; vt < 8; ++vt) {
                unsigned r0, r1, r2, r3;
                ldsm4(r0, r1, r2, r3, vB + vt * 16 * 144 + kt2 * 32);
                mma16816h(o_[2 * vt],     ahf, r0, r2);
                mma16816h(o_[2 * vt + 1], ahf, r1, r3);
            }
        }
        __syncthreads();
    }

    // ---- epilogue: reduce l across quad, normalize, write f16 ----
    l_lo += __shfl_xor_sync(0xffffffffu, l_lo, 1);
    l_lo += __shfl_xor_sync(0xffffffffu, l_lo, 2);
    l_hi += __shfl_xor_sync(0xffffffffu, l_hi, 1);
    l_hi += __shfl_xor_sync(0xffffffffu, l_hi, 2);
    const float il = 1.0f / l_lo, ih = 1.0f / l_hi;
    __half* arl = outp + (size_t)(b * Ssz + gm_lo) * KP + h * Dh;
    __half* arh = outp + (size_t)(b * Ssz + gm_hi) * KP + h * Dh;
    #pragma unroll
    for (int n = 0; n < 16; ++n) {
        const int col = 8 * n + (lane & 3) * 2;
        *(__half2*)(arl + col) = __floats2half2_rn(o_[n][0] * il, o_[n][1] * il);
        *(__half2*)(arh + col) = __floats2half2_rn(o_[n][2] * ih, o_[n][3] * ih);
    }
}

// ---------------- host launch -------------------------------------------------
extern "C" void kernel_launch(void* const* d_in, const int* in_sizes, int n_in,
                              void* d_out, int out_size)
{
    const float* x   = (const float*)d_in[0];
    const float* Wq  = (const float*)d_in[1];
    const float* Wk  = (const float*)d_in[2];
    const float* Wv  = (const float*)d_in[3];
    const float* Wo  = (const float*)d_in[4];
    const float* qnw = (const float*)d_in[5];
    const float* knw = (const float*)d_in[6];
    const float* cs  = (const float*)d_in[7];
    const float* sn  = (const float*)d_in[8];

    float *qkv;
    __half *xp, *ap, *wqkvt, *wot;
    __half *qhh, *khh, *vth;
    cudaGetSymbolAddress((void**)&qkv, g_qkv);
    cudaGetSymbolAddress((void**)&xp, g_xp);
    cudaGetSymbolAddress((void**)&ap, g_ap);
    cudaGetSymbolAddress((void**)&wqkvt, g_wqkvt);
    cudaGetSymbolAddress((void**)&wot, g_wot);
    cudaGetSymbolAddress((void**)&qhh, g_qh);
    cudaGetSymbolAddress((void**)&khh, g_kh);
    cudaGetSymbolAddress((void**)&vth, g_vth);

    cudaFuncSetAttribute(gemm_mma, cudaFuncAttributeMaxDynamicSharedMemorySize, GEMM_SMEM);
    cudaFuncSetAttribute(flash_mma, cudaFuncAttributeMaxDynamicSharedMemorySize, FL_SMEM);

    // convert inputs + weights (QKV weights concatenated along N)
    conv_a<<<8192, 256>>>(x, xp);
    conv_w<<<dim3(64, 64), 256>>>(Wq, wqkvt, 2048);
    conv_w<<<dim3(32, 64), 256>>>(Wk, wqkvt + (size_t)2048 * KP, 1024);
    conv_w<<<dim3(32, 64), 256>>>(Wv, wqkvt + (size_t)3072 * KP, 1024);
    conv_w<<<dim3(64, 64), 256>>>(Wo, wot, 2048);

    // fused QKV projection (single-f16 HMMA): C = [Q | K | V], [4096, 4096]
    gemm_mma<<<dim3(32, 32), 256, GEMM_SMEM>>>(xp, wqkvt, qkv, 4096);

    // fused RMSNorm + RoPE (Q pre-scaled by SCALE*log2e for exp2 softmax)
    const float qscale = (float)(0.08838834764831845 * 1.4426950408889634);
    norm_rope_split<<<8192, 256>>>(qkv, 0, Hh, qnw, cs, sn, qhh, qscale);
    norm_rope_split<<<4096, 256>>>(qkv, 2048, KVh, knw, cs, sn, khh, 1.0f);
    conv_vt<<<dim3(64, 4, 16), 256>>>(qkv + 3072, vth);

    // flash attention (single-f16 QK and PV, no-running-max exp2 softmax)
    flash_mma<<<dim3(16, Hh, Bsz), 256, FL_SMEM>>>(qhh, khh, vth, ap);

    // output projection (single-f16)
    gemm_mma<<<dim3(16, 32), 256, GEMM_SMEM>>>(ap, wot, (float*)d_out, 2048);
}

// round 15
// speedup vs baseline: 2.9113x; 1.0044x over previous
#include <cuda_runtime.h>
#include <cuda_bf16.h>
#include <cuda_fp16.h>
#include <math.h>

#define Bsz 2
#define Ssz 2048
#define HIDs 2048
#define Hh 16
#define KVh 8
#define Dh 128
#define KP 2048              // single-f16 GEMM: K' = K = 2048
#define NT 32                // KP / 64 k-chunks
#define STG_A (128 * 72 * 2)            // 18432 B per A tile (stride 144B)
#define STG_BYTES (2 * STG_A)           // 36864
#define GEMM_SMEM (3 * STG_BYTES)       // 3-stage = 110592

// flash smem: per stage K[64][136] f16 + V[128][72] f16
#define FKT 17408
#define FVT 18432
#define FLSTG (FKT + FVT)               // 35840
#define FL_SMEM (2 * FLSTG)             // 71680

// ---------------- scratch (static device arrays: no allocs allowed) ----------
__device__ __align__(16) __half g_qkvh[(size_t)4096 * 4096];  // fused QKV f16 [M, 4096]

__device__ __align__(16) __half g_xp[(size_t)4096 * KP];
__device__ __align__(16) __half g_ap[(size_t)4096 * KP];   // att f16 (flash writes)
__device__ __align__(16) __half g_wqkvt[(size_t)4096 * KP];
__device__ __align__(16) __half g_wot[(size_t)2048 * KP];

// head-major f16 for flash (single precision images)
__device__ __align__(16) __half g_qh[(size_t)Bsz * Hh * Ssz * Dh];
__device__ __align__(16) __half g_kh[(size_t)Bsz * KVh * Ssz * Dh];
__device__ __align__(16) __half g_vth[(size_t)Bsz * KVh * Dh * Ssz];

// ====================== PTX helpers =========================================
__device__ __forceinline__ unsigned smem_u32(const void* p) {
    unsigned a;
    asm("{ .reg .u64 t; cvta.to.shared.u64 t, %1; cvt.u32.u64 %0, t; }"
        : "=r"(a) : "l"(p));
    return a;
}
#define CP16(dst, src) \
    asm volatile("cp.async.cg.shared.global [%0], [%1], 16;" :: "r"(dst), "l"(src))
#define CP_COMMIT() asm volatile("cp.async.commit_group;")

__device__ __forceinline__ void ldsm4(unsigned& r0, unsigned& r1,
                                      unsigned& r2, unsigned& r3, unsigned a) {
    asm volatile("ldmatrix.sync.aligned.m8n8.x4.shared.b16 {%0,%1,%2,%3}, [%4];"
                 : "=r"(r0), "=r"(r1), "=r"(r2), "=r"(r3) : "r"(a));
}
// f16 mma
__device__ __forceinline__ void mma16816h(float* d, const unsigned* a,
                                          unsigned b0, unsigned b1) {
    asm volatile(
        "mma.sync.aligned.m16n8k16.row.col.f32.f16.f16.f32 "
        "{%0,%1,%2,%3}, {%4,%5,%6,%7}, {%8,%9}, {%0,%1,%2,%3};"
        : "+f"(d[0]), "+f"(d[1]), "+f"(d[2]), "+f"(d[3])
        : "r"(a[0]), "r"(a[1]), "r"(a[2]), "r"(a[3]), "r"(b0), "r"(b1));
}
__device__ __forceinline__ unsigned pack2h(float lo, float hi) {
    unsigned d;
    asm("cvt.rn.f16x2.f32 %0, %1, %2;" : "=r"(d) : "f"(hi), "f"(lo));
    return d;
}
__device__ __forceinline__ float ex2(float x) {
    float r;
    asm("ex2.approx.f32 %0, %1;" : "=f"(r) : "f"(x));
    return r;
}

// ====================== conversion kernels ==================================
// A' = f16 copy of src [M, 2048] fp32 row-major (single term)
__global__ __launch_bounds__(256) void conv_a(
    const float* __restrict__ src, __half* __restrict__ dst)
{
    size_t i = (size_t)blockIdx.x * 256 + threadIdx.x;   // over M*512 float4
    float4 v = ((const float4*)src)[i];
    __half2* d = (__half2*)dst + i * 2;
    d[0] = __floats2half2_rn(v.x, v.y);
    d[1] = __floats2half2_rn(v.z, v.w);
}

// B' = W^T f16 single [N, 2048].  W is [2048, N] fp32.
__global__ __launch_bounds__(256) void conv_w(
    const float* __restrict__ W, __half* __restrict__ Bt, int N)
{
    __shared__ float ts[32][33];
    int n0 = blockIdx.x * 32, k0 = blockIdx.y * 32;
    int tx = threadIdx.x & 31, ty = threadIdx.x >> 5;
    #pragma unroll
    for (int r = 0; r < 4; ++r)
        ts[ty + r * 8][tx] = W[(size_t)(k0 + ty + r * 8) * N + n0 + tx];
    __syncthreads();
    #pragma unroll
    for (int r = 0; r < 4; ++r) {
        int n = n0 + ty + r * 8, k = k0 + tx;
        Bt[(size_t)n * KP + k] = __float2half(ts[tx][ty + r * 8]);
    }
}

// fused RMSNorm + RoPE + head-major f16 write, reading f16 qkv buffer.
__global__ __launch_bounds__(256) void norm_rope_split(
    const __half* __restrict__ qkv, int baseCol, int nh,
    const float* __restrict__ w,
    const float* __restrict__ cs, const float* __restrict__ sn,
    __half* __restrict__ dh, float scale)
{
    const int warp = blockIdx.x * 8 + (threadIdx.x >> 5);
    const int lane = threadIdx.x & 31;
    const int tok = warp / nh;          // b*S + s
    const int head = warp % nh;
    const int s = tok % Ssz;
    const int b = tok / Ssz;

    const __half* row = qkv + (size_t)tok * 4096 + baseCol + head * Dh;
    float v0 = __half2float(row[lane]);
    float v1 = __half2float(row[lane + 32]);
    float v2 = __half2float(row[lane + 64]);
    float v3 = __half2float(row[lane + 96]);

    float ss = v0 * v0 + v1 * v1 + v2 * v2 + v3 * v3;
    #pragma unroll
    for (int o = 16; o; o >>= 1) ss += __shfl_xor_sync(0xffffffffu, ss, o);
    float r = rsqrtf(ss * (1.0f / 128.0f) + 1e-6f);

    v0 = v0 * r * w[lane];
    v1 = v1 * r * w[lane + 32];
    v2 = v2 * r * w[lane + 64];
    v3 = v3 * r * w[lane + 96];

    const float* cr = cs + (size_t)s * Dh;
    const float* sr = sn + (size_t)s * Dh;
    float o0 = (v0 * cr[lane]      - v2 * sr[lane])      * scale;
    float o1 = (v1 * cr[lane + 32] - v3 * sr[lane + 32]) * scale;
    float o2 = (v2 * cr[lane + 64] + v0 * sr[lane + 64]) * scale;
    float o3 = (v3 * cr[lane + 96] + v1 * sr[lane + 96]) * scale;

    size_t o = (((size_t)b * nh + head) * Ssz + s) * 128;
    dh[o + lane]      = __float2half(o0);
    dh[o + lane + 32] = __float2half(o1);
    dh[o + lane + 64] = __float2half(o2);
    dh[o + lane + 96] = __float2half(o3);
}

// V from f16 fused buffer (base offset to V cols) -> Vt f16 [B*KV,128,S]
__global__ __launch_bounds__(256) void conv_vt(
    const __half* __restrict__ v, __half* __restrict__ th)
{
    __shared__ __half ts[32][33];
    int s0 = blockIdx.x * 32, d0 = blockIdx.y * 32;
    int bk = blockIdx.z;
    int b = bk >> 3, kv = bk & 7;
    int tx = threadIdx.x & 31, ty = threadIdx.x >> 5;
    #pragma unroll
    for (int r = 0; r < 4; ++r)
        ts[ty + r * 8][tx] =
            v[(size_t)(b * Ssz + s0 + ty + r * 8) * 4096 + kv * 128 + d0 + tx];
    __syncthreads();
    #pragma unroll
    for (int r = 0; r < 4; ++r) {
        size_t o = ((size_t)bk * 128 + d0 + ty + r * 8) * Ssz + s0 + tx;
        th[o] = ts[tx][ty + r * 8];
    }
}

// ====================== f16 GEMM (3-stage, 1 barrier/chunk) =================
// C fp32 or Ch f16 (Ch non-null selects f16 output).
__global__ __launch_bounds__(256, 2) void gemm_mma(
    const __half* __restrict__ A, const __half* __restrict__ Bm,
    float* __restrict__ C, __half* __restrict__ Ch, int N)
{
    extern __shared__ __align__(16) char smem[];
    const unsigned sb = smem_u32(smem);
    const int tid = threadIdx.x;
    const int lane = tid & 31;
    const int wid = tid >> 5;
    const int wr = wid >> 1;
    const int wc = wid & 1;
    const int bm = blockIdx.y << 7, bn = blockIdx.x << 7;

    const int lrow = tid >> 3, lcol = tid & 7;
    const __half* Ag = A + (size_t)(bm + lrow) * KP + lcol * 8;
    const __half* Bg = Bm + (size_t)(bn + lrow) * KP + lcol * 8;
    const unsigned sOff = lrow * 144 + lcol * 16;

    float acc[2][8][4];
    #pragma unroll
    for (int i = 0; i < 2; ++i)
        #pragma unroll
        for (int j = 0; j < 8; ++j)
            #pragma unroll
            for (int e = 0; e < 4; ++e) acc[i][j][e] = 0.0f;

    const unsigned aBase0 = sb + (32 * wr + (lane & 15)) * 144 + (lane >> 4) * 16;
    const unsigned bBase0 = sb + STG_A + (64 * wc + (lane & 15)) * 144 + (lane >> 4) * 16;

    #pragma unroll
    for (int c = 0; c < 2; ++c) {
        const unsigned st = c * STG_BYTES;
        const unsigned as = sb + st + sOff, bs = sb + st + STG_A + sOff;
        const __half* ag = Ag + (size_t)c * 64;
        const __half* bg = Bg + (size_t)c * 64;
        #pragma unroll
        for (int i = 0; i < 4; ++i) {
            CP16(as + i * 32 * 144, ag + (size_t)(32 * i) * KP);
            CP16(bs + i * 32 * 144, bg + (size_t)(32 * i) * KP);
        }
        CP_COMMIT();
    }

    int stage = 0, nstage = 2;
    for (int c = 0; c < NT; ++c) {
        if (c + 1 < NT) asm volatile("cp.async.wait_group 1;" ::: "memory");
        else            asm volatile("cp.async.wait_group 0;" ::: "memory");
        __syncthreads();

        if (c + 2 < NT) {
            const unsigned st = nstage * STG_BYTES;
            const unsigned as = sb + st + sOff, bs = sb + st + STG_A + sOff;
            const __half* ag = Ag + (size_t)(c + 2) * 64;
            const __half* bg = Bg + (size_t)(c + 2) * 64;
            #pragma unroll
            for (int i = 0; i < 4; ++i) {
                CP16(as + i * 32 * 144, ag + (size_t)(32 * i) * KP);
                CP16(bs + i * 32 * 144, bg + (size_t)(32 * i) * KP);
            }
            CP_COMMIT();
            nstage = (nstage == 2) ? 0 : nstage + 1;
        }

        const unsigned st = stage * STG_BYTES;
        stage = (stage == 2) ? 0 : stage + 1;
        const unsigned aB = aBase0 + st, bB = bBase0 + st;
        #pragma unroll
        for (int ks = 0; ks < 4; ++ks) {
            unsigned a[2][4];
            ldsm4(a[0][0], a[0][1], a[0][2], a[0][3], aB + ks * 32);
            ldsm4(a[1][0], a[1][1], a[1][2], a[1][3], aB + 16 * 144 + ks * 32);
            unsigned b[8][2];
            #pragma unroll
            for (int nt = 0; nt < 4; ++nt) {
                unsigned r0, r1, r2, r3;
                ldsm4(r0, r1, r2, r3, bB + nt * 16 * 144 + ks * 32);
                b[nt * 2][0] = r0; b[nt * 2][1] = r2;
                b[nt * 2 + 1][0] = r1; b[nt * 2 + 1][1] = r3;
            }
            #pragma unroll
            for (int mt = 0; mt < 2; ++mt)
                #pragma unroll
                for (int nt = 0; nt < 8; ++nt)
                    mma16816h(acc[mt][nt], a[mt], b[nt][0], b[nt][1]);
        }
    }

    if (Ch) {
        #pragma unroll
        for (int mt = 0; mt < 2; ++mt) {
            const int r0 = bm + 32 * wr + 16 * mt + (lane >> 2);
            #pragma unroll
            for (int nt = 0; nt < 8; ++nt) {
                const int col = bn + 64 * wc + 8 * nt + (lane & 3) * 2;
                *(__half2*)&Ch[(size_t)r0 * N + col] =
                    __floats2half2_rn(acc[mt][nt][0], acc[mt][nt][1]);
                *(__half2*)&Ch[(size_t)(r0 + 8) * N + col] =
                    __floats2half2_rn(acc[mt][nt][2], acc[mt][nt][3]);
            }
        }
    } else {
        #pragma unroll
        for (int mt = 0; mt < 2; ++mt) {
            const int r0 = bm + 32 * wr + 16 * mt + (lane >> 2);
            #pragma unroll
            for (int nt = 0; nt < 8; ++nt) {
                const int col = bn + 64 * wc + 8 * nt + (lane & 3) * 2;
                float2 v0 = make_float2(acc[mt][nt][0], acc[mt][nt][1]);
                float2 v1 = make_float2(acc[mt][nt][2], acc[mt][nt][3]);
                *(float2*)&C[(size_t)r0 * N + col]       = v0;
                *(float2*)&C[(size_t)(r0 + 8) * N + col] = v1;
            }
        }
    }
}

// ====================== f16 flash attention (single-term QK and PV) =========
// Per stage: K f16 [64][136] + V f16 [128][72].
__device__ __forceinline__ void load_kv_tile(
    unsigned sbase, int tid,
    const __half* khp, const __half* vthp, int nBase)
{
    const int r = tid >> 2, c0 = (tid & 3) * 4;
    const char* gk = (const char*)(khp + (size_t)(nBase + r) * 128) + c0 * 16;
    const unsigned dk = sbase + r * 272 + c0 * 16;
    #pragma unroll
    for (int i = 0; i < 4; ++i) CP16(dk + i * 16, gk + i * 16);
    const int r2 = tid >> 1, c2 = (tid & 1) * 4;
    const char* gv = (const char*)(vthp + (size_t)r2 * Ssz + nBase) + c2 * 16;
    const unsigned dv = sbase + FKT + r2 * 144 + c2 * 16;
    #pragma unroll
    for (int i = 0; i < 4; ++i) CP16(dv + i * 16, gv + i * 16);
}

__global__ __launch_bounds__(256, 1) void flash_mma(
    const __half* __restrict__ qh, const __half* __restrict__ kh,
    const __half* __restrict__ vth,
    __half* __restrict__ outp)           // f16 [M, 2048]
{
    extern __shared__ __align__(16) char smem[];
    const unsigned sb = smem_u32(smem);
    const int tid = threadIdx.x, lane = tid & 31, w = tid >> 5;
    const int qi = 15 - blockIdx.x;
    const int h = blockIdx.y, b = blockIdx.z;
    const int kvh = h >> 1;
    const int mBase = qi << 7;
    const int ntiles = 2 * qi + 2;

    const __half* qhp = qh + (((size_t)b * Hh + h) * Ssz + mBase) * Dh;
    const __half* khp = kh + ((size_t)b * KVh + kvh) * Ssz * Dh;
    const __half* vthp = vth + ((size_t)b * KVh + kvh) * Dh * Ssz;

    // prologue: stage Q at sb, extract, then KV tile0
    {
        const int r = tid >> 1, cb = (tid & 1) * 8;
        const unsigned dq = sb + r * 272 + cb * 16;
        const char* gq = (const char*)(qhp + (size_t)r * Dh) + cb * 16;
        #pragma unroll
        for (int i = 0; i < 8; ++i) CP16(dq + i * 16, gq + i * 16);
    }
    CP_COMMIT();
    asm volatile("cp.async.wait_group 0;" ::: "memory");
    __syncthreads();

    unsigned qhf[8][4];
    {
        const unsigned qB = sb + (16 * w + (lane & 15)) * 272 + (lane >> 4) * 16;
        #pragma unroll
        for (int kt = 0; kt < 8; ++kt)
            ldsm4(qhf[kt][0], qhf[kt][1], qhf[kt][2], qhf[kt][3], qB + kt * 32);
    }
    __syncthreads();        // Q fully extracted before overwriting with tile0

    load_kv_tile(sb, tid, khp, vthp, 0);
    CP_COMMIT();

    float o_[16][4];
    #pragma unroll
    for (int n = 0; n < 16; ++n)
        #pragma unroll
        for (int e = 0; e < 4; ++e) o_[n][e] = 0.0f;
    float l_lo = 0.0f, l_hi = 0.0f;
    const int gm_lo = mBase + 16 * w + (lane >> 2);
    const int gm_hi = gm_lo + 8;

    for (int t = 0; t < ntiles; ++t) {
        if (t + 1 < ntiles) {
            load_kv_tile(sb + ((t + 1) & 1) * FLSTG, tid, khp, vthp, (t + 1) * 64);
            CP_COMMIT();
            asm volatile("cp.async.wait_group 1;" ::: "memory");
        } else {
            asm volatile("cp.async.wait_group 0;" ::: "memory");
        }
        __syncthreads();
        const unsigned stb = sb + (t & 1) * FLSTG;

        // ---- QK^T (single term); scores in log2 domain ----
        float s_[8][4];
        #pragma unroll
        for (int j = 0; j < 8; ++j)
            #pragma unroll
            for (int e = 0; e < 4; ++e) s_[j][e] = 0.0f;

        const unsigned kB = stb + (lane & 15) * 272 + (lane >> 4) * 16;
        #pragma unroll
        for (int kt = 0; kt < 8; ++kt) {
            #pragma unroll
            for (int nt = 0; nt < 4; ++nt) {
                unsigned r0, r1, r2, r3;
                ldsm4(r0, r1, r2, r3, kB + nt * 16 * 272 + kt * 32);
                mma16816h(s_[nt * 2],     qhf[kt], r0, r2);
                mma16816h(s_[nt * 2 + 1], qhf[kt], r1, r3);
            }
        }

        // ---- mask (last two tiles only) + fixed-shift softmax ----
        const int nBase = t * 64;
        if (t >= 2 * qi) {
            #pragma unroll
            for (int j = 0; j < 8; ++j) {
                const int gn0 = nBase + 8 * j + (lane & 3) * 2;
                if (gn0 > gm_lo)     s_[j][0] = -1e30f;
                if (gn0 + 1 > gm_lo) s_[j][1] = -1e30f;
                if (gn0 > gm_hi)     s_[j][2] = -1e30f;
                if (gn0 + 1 > gm_hi) s_[j][3] = -1e30f;
            }
        }
        #pragma unroll
        for (int j = 0; j < 8; ++j) {
            float p0 = ex2(s_[j][0]);
            float p1 = ex2(s_[j][1]);
            float p2 = ex2(s_[j][2]);
            float p3 = ex2(s_[j][3]);
            s_[j][0] = p0; s_[j][1] = p1; s_[j][2] = p2; s_[j][3] = p3;
            l_lo += p0 + p1; l_hi += p2 + p3;
        }

        // ---- PV (single term, P from registers) ----
        const unsigned vB = stb + FKT + (lane & 15) * 144 + (lane >> 4) * 16;
        #pragma unroll
        for (int kt2 = 0; kt2 < 4; ++kt2) {
            const float* pa = s_[2 * kt2];
            const float* pb = s_[2 * kt2 + 1];
            unsigned ahf[4];
            ahf[0] = pack2h(pa[0], pa[1]); ahf[1] = pack2h(pa[2], pa[3]);
            ahf[2] = pack2h(pb[0], pb[1]); ahf[3] = pack2h(pb[2], pb[3]);
            #pragma unroll
            for (int vt = 0; vt < 8; ++vt) {
                unsigned r0, r1, r2, r3;
                ldsm4(r0, r1, r2, r3, vB + vt * 16 * 144 + kt2 * 32);
                mma16816h(o_[2 * vt],     ahf, r0, r2);
                mma16816h(o_[2 * vt + 1], ahf, r1, r3);
            }
        }
        __syncthreads();
    }

    // ---- epilogue: reduce l across quad, normalize, write f16 ----
    l_lo += __shfl_xor_sync(0xffffffffu, l_lo, 1);
    l_lo += __shfl_xor_sync(0xffffffffu, l_lo, 2);
    l_hi += __shfl_xor_sync(0xffffffffu, l_hi, 1);
    l_hi += __shfl_xor_sync(0xffffffffu, l_hi, 2);
    const float il = 1.0f / l_lo, ih = 1.0f / l_hi;
    __half* arl = outp + (size_t)(b * Ssz + gm_lo) * KP + h * Dh;
    __half* arh = outp + (size_t)(b * Ssz + gm_hi) * KP + h * Dh;
    #pragma unroll
    for (int n = 0; n < 16; ++n) {
        const int col = 8 * n + (lane & 3) * 2;
        *(__half2*)(arl + col) = __floats2half2_rn(o_[n][0] * il, o_[n][1] * il);
        *(__half2*)(arh + col) = __floats2half2_rn(o_[n][2] * ih, o_[n][3] * ih);
    }
}

// ---------------- host launch -------------------------------------------------
extern "C" void kernel_launch(void* const* d_in, const int* in_sizes, int n_in,
                              void* d_out, int out_size)
{
    const float* x   = (const float*)d_in[0];
    const float* Wq  = (const float*)d_in[1];
    const float* Wk  = (const float*)d_in[2];
    const float* Wv  = (const float*)d_in[3];
    const float* Wo  = (const float*)d_in[4];
    const float* qnw = (const float*)d_in[5];
    const float* knw = (const float*)d_in[6];
    const float* cs  = (const float*)d_in[7];
    const float* sn  = (const float*)d_in[8];

    __half *qkvh, *xp, *ap, *wqkvt, *wot;
    __half *qhh, *khh, *vth;
    cudaGetSymbolAddress((void**)&qkvh, g_qkvh);
    cudaGetSymbolAddress((void**)&xp, g_xp);
    cudaGetSymbolAddress((void**)&ap, g_ap);
    cudaGetSymbolAddress((void**)&wqkvt, g_wqkvt);
    cudaGetSymbolAddress((void**)&wot, g_wot);
    cudaGetSymbolAddress((void**)&qhh, g_qh);
    cudaGetSymbolAddress((void**)&khh, g_kh);
    cudaGetSymbolAddress((void**)&vth, g_vth);

    cudaFuncSetAttribute(gemm_mma, cudaFuncAttributeMaxDynamicSharedMemorySize, GEMM_SMEM);
    cudaFuncSetAttribute(flash_mma, cudaFuncAttributeMaxDynamicSharedMemorySize, FL_SMEM);

    // convert inputs + weights (QKV weights concatenated along N)
    conv_a<<<8192, 256>>>(x, xp);
    conv_w<<<dim3(64, 64), 256>>>(Wq, wqkvt, 2048);
    conv_w<<<dim3(32, 64), 256>>>(Wk, wqkvt + (size_t)2048 * KP, 1024);
    conv_w<<<dim3(32, 64), 256>>>(Wv, wqkvt + (size_t)3072 * KP, 1024);
    conv_w<<<dim3(64, 64), 256>>>(Wo, wot, 2048);

    // fused QKV projection (single-f16 HMMA), f16 output: [Q | K | V], [4096, 4096]
    gemm_mma<<<dim3(32, 32), 256, GEMM_SMEM>>>(xp, wqkvt, nullptr, qkvh, 4096);

    // fused RMSNorm + RoPE (Q pre-scaled by SCALE*log2e for exp2 softmax)
    const float qscale = (float)(0.08838834764831845 * 1.4426950408889634);
    norm_rope_split<<<8192, 256>>>(qkvh, 0, Hh, qnw, cs, sn, qhh, qscale);
    norm_rope_split<<<4096, 256>>>(qkvh, 2048, KVh, knw, cs, sn, khh, 1.0f);
    conv_vt<<<dim3(64, 4, 16), 256>>>(qkvh + 3072, vth);

    // flash attention (single-f16 QK and PV, no-running-max exp2 softmax)
    flash_mma<<<dim3(16, Hh, Bsz), 256, FL_SMEM>>>(qhh, khh, vth, ap);

    // output projection (single-f16, fp32 output)
    gemm_mma<<<dim3(16, 32), 256, GEMM_SMEM>>>(ap, wot, (float*)d_out, nullptr, 2048);
}

// round 16
// speedup vs baseline: 2.9405x; 1.0100x over previous
#include <cuda_runtime.h>
#include <cuda_bf16.h>
#include <cuda_fp16.h>
#include <math.h>

#define Bsz 2
#define Ssz 2048
#define HIDs 2048
#define Hh 16
#define KVh 8
#define Dh 128
#define KP 2048              // single-f16 GEMM: K' = K = 2048
#define NT 32                // KP / 64 k-chunks
#define STG_A (128 * 72 * 2)            // 18432 B per A tile (stride 144B)
#define STG_BYTES (2 * STG_A)           // 36864
#define GEMM_SMEM (3 * STG_BYTES)       // 3-stage = 110592

// flash smem: per stage K[64][136] f16 + V[64 n][128 d + pad] f16 (both 272B rows)
#define FKT 17408
#define FLSTG (2 * FKT)                 // 34816
#define FL_SMEM (2 * FLSTG)             // 69632

// ---------------- scratch (static device arrays: no allocs allowed) ----------
__device__ __align__(16) __half g_qkvh[(size_t)4096 * 4096];  // fused QKV f16 [M, 4096]

__device__ __align__(16) __half g_xp[(size_t)4096 * KP];
__device__ __align__(16) __half g_ap[(size_t)4096 * KP];   // att f16 (flash writes)
__device__ __align__(16) __half g_wqkvt[(size_t)4096 * KP];
__device__ __align__(16) __half g_wot[(size_t)2048 * KP];

// head-major f16 for flash Q/K
__device__ __align__(16) __half g_qh[(size_t)Bsz * Hh * Ssz * Dh];
__device__ __align__(16) __half g_kh[(size_t)Bsz * KVh * Ssz * Dh];

// ====================== PTX helpers =========================================
__device__ __forceinline__ unsigned smem_u32(const void* p) {
    unsigned a;
    asm("{ .reg .u64 t; cvta.to.shared.u64 t, %1; cvt.u32.u64 %0, t; }"
        : "=r"(a) : "l"(p));
    return a;
}
#define CP16(dst, src) \
    asm volatile("cp.async.cg.shared.global [%0], [%1], 16;" :: "r"(dst), "l"(src))
#define CP_COMMIT() asm volatile("cp.async.commit_group;")

__device__ __forceinline__ void ldsm4(unsigned& r0, unsigned& r1,
                                      unsigned& r2, unsigned& r3, unsigned a) {
    asm volatile("ldmatrix.sync.aligned.m8n8.x4.shared.b16 {%0,%1,%2,%3}, [%4];"
                 : "=r"(r0), "=r"(r1), "=r"(r2), "=r"(r3) : "r"(a));
}
__device__ __forceinline__ void ldsm4t(unsigned& r0, unsigned& r1,
                                       unsigned& r2, unsigned& r3, unsigned a) {
    asm volatile("ldmatrix.sync.aligned.m8n8.x4.trans.shared.b16 {%0,%1,%2,%3}, [%4];"
                 : "=r"(r0), "=r"(r1), "=r"(r2), "=r"(r3) : "r"(a));
}
// f16 mma
__device__ __forceinline__ void mma16816h(float* d, const unsigned* a,
                                          unsigned b0, unsigned b1) {
    asm volatile(
        "mma.sync.aligned.m16n8k16.row.col.f32.f16.f16.f32 "
        "{%0,%1,%2,%3}, {%4,%5,%6,%7}, {%8,%9}, {%0,%1,%2,%3};"
        : "+f"(d[0]), "+f"(d[1]), "+f"(d[2]), "+f"(d[3])
        : "r"(a[0]), "r"(a[1]), "r"(a[2]), "r"(a[3]), "r"(b0), "r"(b1));
}
__device__ __forceinline__ unsigned pack2h(float lo, float hi) {
    unsigned d;
    asm("cvt.rn.f16x2.f32 %0, %1, %2;" : "=r"(d) : "f"(hi), "f"(lo));
    return d;
}
__device__ __forceinline__ float ex2(float x) {
    float r;
    asm("ex2.approx.f32 %0, %1;" : "=f"(r) : "f"(x));
    return r;
}

// ====================== conversion kernels ==================================
// A' = f16 copy of src [M, 2048] fp32 row-major (single term)
__global__ __launch_bounds__(256) void conv_a(
    const float* __restrict__ src, __half* __restrict__ dst)
{
    size_t i = (size_t)blockIdx.x * 256 + threadIdx.x;   // over M*512 float4
    float4 v = ((const float4*)src)[i];
    __half2* d = (__half2*)dst + i * 2;
    d[0] = __floats2half2_rn(v.x, v.y);
    d[1] = __floats2half2_rn(v.z, v.w);
}

// B' = W^T f16 single [N, 2048].  W is [2048, N] fp32.
__global__ __launch_bounds__(256) void conv_w(
    const float* __restrict__ W, __half* __restrict__ Bt, int N)
{
    __shared__ float ts[32][33];
    int n0 = blockIdx.x * 32, k0 = blockIdx.y * 32;
    int tx = threadIdx.x & 31, ty = threadIdx.x >> 5;
    #pragma unroll
    for (int r = 0; r < 4; ++r)
        ts[ty + r * 8][tx] = W[(size_t)(k0 + ty + r * 8) * N + n0 + tx];
    __syncthreads();
    #pragma unroll
    for (int r = 0; r < 4; ++r) {
        int n = n0 + ty + r * 8, k = k0 + tx;
        Bt[(size_t)n * KP + k] = __float2half(ts[tx][ty + r * 8]);
    }
}

// fused RMSNorm + RoPE for Q AND K in one launch, reading f16 qkv buffer.
// blocks [0, 8192): Q (16 heads); blocks [8192, 12288): K (8 heads).
__global__ __launch_bounds__(256) void norm_rope_split(
    const __half* __restrict__ qkv,
    const float* __restrict__ qw, const float* __restrict__ kw,
    const float* __restrict__ cs, const float* __restrict__ sn,
    __half* __restrict__ dq, __half* __restrict__ dk, float qscale)
{
    const bool isQ = blockIdx.x < 8192;
    const int blk = isQ ? blockIdx.x : blockIdx.x - 8192;
    const int nh = isQ ? Hh : KVh;
    const int baseCol = isQ ? 0 : 2048;
    const float* w = isQ ? qw : kw;
    __half* dh = isQ ? dq : dk;
    const float scale = isQ ? qscale : 1.0f;

    const int warp = blk * 8 + (threadIdx.x >> 5);
    const int lane = threadIdx.x & 31;
    const int tok = warp / nh;          // b*S + s
    const int head = warp % nh;
    const int s = tok % Ssz;
    const int b = tok / Ssz;

    const __half* row = qkv + (size_t)tok * 4096 + baseCol + head * Dh;
    float v0 = __half2float(row[lane]);
    float v1 = __half2float(row[lane + 32]);
    float v2 = __half2float(row[lane + 64]);
    float v3 = __half2float(row[lane + 96]);

    float ss = v0 * v0 + v1 * v1 + v2 * v2 + v3 * v3;
    #pragma unroll
    for (int o = 16; o; o >>= 1) ss += __shfl_xor_sync(0xffffffffu, ss, o);
    float r = rsqrtf(ss * (1.0f / 128.0f) + 1e-6f);

    v0 = v0 * r * w[lane];
    v1 = v1 * r * w[lane + 32];
    v2 = v2 * r * w[lane + 64];
    v3 = v3 * r * w[lane + 96];

    const float* cr = cs + (size_t)s * Dh;
    const float* sr = sn + (size_t)s * Dh;
    float o0 = (v0 * cr[lane]      - v2 * sr[lane])      * scale;
    float o1 = (v1 * cr[lane + 32] - v3 * sr[lane + 32]) * scale;
    float o2 = (v2 * cr[lane + 64] + v0 * sr[lane + 64]) * scale;
    float o3 = (v3 * cr[lane + 96] + v1 * sr[lane + 96]) * scale;

    size_t o = (((size_t)b * nh + head) * Ssz + s) * 128;
    dh[o + lane]      = __float2half(o0);
    dh[o + lane + 32] = __float2half(o1);
    dh[o + lane + 64] = __float2half(o2);
    dh[o + lane + 96] = __float2half(o3);
}

// ====================== f16 GEMM (3-stage, 1 barrier/chunk) =================
// C fp32 or Ch f16 (Ch non-null selects f16 output).
__global__ __launch_bounds__(256, 2) void gemm_mma(
    const __half* __restrict__ A, const __half* __restrict__ Bm,
    float* __restrict__ C, __half* __restrict__ Ch, int N)
{
    extern __shared__ __align__(16) char smem[];
    const unsigned sb = smem_u32(smem);
    const int tid = threadIdx.x;
    const int lane = tid & 31;
    const int wid = tid >> 5;
    const int wr = wid >> 1;
    const int wc = wid & 1;
    const int bm = blockIdx.y << 7, bn = blockIdx.x << 7;

    const int lrow = tid >> 3, lcol = tid & 7;
    const __half* Ag = A + (size_t)(bm + lrow) * KP + lcol * 8;
    const __half* Bg = Bm + (size_t)(bn + lrow) * KP + lcol * 8;
    const unsigned sOff = lrow * 144 + lcol * 16;

    float acc[2][8][4];
    #pragma unroll
    for (int i = 0; i < 2; ++i)
        #pragma unroll
        for (int j = 0; j < 8; ++j)
            #pragma unroll
            for (int e = 0; e < 4; ++e) acc[i][j][e] = 0.0f;

    const unsigned aBase0 = sb + (32 * wr + (lane & 15)) * 144 + (lane >> 4) * 16;
    const unsigned bBase0 = sb + STG_A + (64 * wc + (lane & 15)) * 144 + (lane >> 4) * 16;

    #pragma unroll
    for (int c = 0; c < 2; ++c) {
        const unsigned st = c * STG_BYTES;
        const unsigned as = sb + st + sOff, bs = sb + st + STG_A + sOff;
        const __half* ag = Ag + (size_t)c * 64;
        const __half* bg = Bg + (size_t)c * 64;
        #pragma unroll
        for (int i = 0; i < 4; ++i) {
            CP16(as + i * 32 * 144, ag + (size_t)(32 * i) * KP);
            CP16(bs + i * 32 * 144, bg + (size_t)(32 * i) * KP);
        }
        CP_COMMIT();
    }

    int stage = 0, nstage = 2;
    for (int c = 0; c < NT; ++c) {
        if (c + 1 < NT) asm volatile("cp.async.wait_group 1;" ::: "memory");
        else            asm volatile("cp.async.wait_group 0;" ::: "memory");
        __syncthreads();

        if (c + 2 < NT) {
            const unsigned st = nstage * STG_BYTES;
            const unsigned as = sb + st + sOff, bs = sb + st + STG_A + sOff;
            const __half* ag = Ag + (size_t)(c + 2) * 64;
            const __half* bg = Bg + (size_t)(c + 2) * 64;
            #pragma unroll
            for (int i = 0; i < 4; ++i) {
                CP16(as + i * 32 * 144, ag + (size_t)(32 * i) * KP);
                CP16(bs + i * 32 * 144, bg + (size_t)(32 * i) * KP);
            }
            CP_COMMIT();
            nstage = (nstage == 2) ? 0 : nstage + 1;
        }

        const unsigned st = stage * STG_BYTES;
        stage = (stage == 2) ? 0 : stage + 1;
        const unsigned aB = aBase0 + st, bB = bBase0 + st;
        #pragma unroll
        for (int ks = 0; ks < 4; ++ks) {
            unsigned a[2][4];
            ldsm4(a[0][0], a[0][1], a[0][2], a[0][3], aB + ks * 32);
            ldsm4(a[1][0], a[1][1], a[1][2], a[1][3], aB + 16 * 144 + ks * 32);
            unsigned b[8][2];
            #pragma unroll
            for (int nt = 0; nt < 4; ++nt) {
                unsigned r0, r1, r2, r3;
                ldsm4(r0, r1, r2, r3, bB + nt * 16 * 144 + ks * 32);
                b[nt * 2][0] = r0; b[nt * 2][1] = r2;
                b[nt * 2 + 1][0] = r1; b[nt * 2 + 1][1] = r3;
            }
            #pragma unroll
            for (int mt = 0; mt < 2; ++mt)
                #pragma unroll
                for (int nt = 0; nt < 8; ++nt)
                    mma16816h(acc[mt][nt], a[mt], b[nt][0], b[nt][1]);
        }
    }

    if (Ch) {
        #pragma unroll
        for (int mt = 0; mt < 2; ++mt) {
            const int r0 = bm + 32 * wr + 16 * mt + (lane >> 2);
            #pragma unroll
            for (int nt = 0; nt < 8; ++nt) {
                const int col = bn + 64 * wc + 8 * nt + (lane & 3) * 2;
                *(__half2*)&Ch[(size_t)r0 * N + col] =
                    __floats2half2_rn(acc[mt][nt][0], acc[mt][nt][1]);
                *(__half2*)&Ch[(size_t)(r0 + 8) * N + col] =
                    __floats2half2_rn(acc[mt][nt][2], acc[mt][nt][3]);
            }
        }
    } else {
        #pragma unroll
        for (int mt = 0; mt < 2; ++mt) {
            const int r0 = bm + 32 * wr + 16 * mt + (lane >> 2);
            #pragma unroll
            for (int nt = 0; nt < 8; ++nt) {
                const int col = bn + 64 * wc + 8 * nt + (lane & 3) * 2;
                float2 v0 = make_float2(acc[mt][nt][0], acc[mt][nt][1]);
                float2 v1 = make_float2(acc[mt][nt][2], acc[mt][nt][3]);
                *(float2*)&C[(size_t)r0 * N + col]       = v0;
                *(float2*)&C[(size_t)(r0 + 8) * N + col] = v1;
            }
        }
    }
}

// ====================== f16 flash attention (V via ldsm.trans) ==============
// Per stage: K[64 n][128 d + pad] + V[64 n][128 d + pad], both 272B rows.
// V is read directly from the fused QKV f16 buffer (row stride 4096 halves).
__device__ __forceinline__ void load_kv_tile(
    unsigned sbase, int tid,
    const __half* khp, const __half* vhp, int nBase)
{
    const int r = tid >> 2, c0 = (tid & 3) * 4;
    // K: head-major, row stride 128 halves
    const char* gk = (const char*)(khp + (size_t)(nBase + r) * 128) + c0 * 16;
    const unsigned dk = sbase + r * 272 + c0 * 16;
    #pragma unroll
    for (int i = 0; i < 4; ++i) CP16(dk + i * 16, gk + i * 16);
    // V: fused buffer, row stride 4096 halves
    const char* gv = (const char*)(vhp + (size_t)(nBase + r) * 4096) + c0 * 16;
    const unsigned dv = sbase + FKT + r * 272 + c0 * 16;
    #pragma unroll
    for (int i = 0; i < 4; ++i) CP16(dv + i * 16, gv + i * 16);
}

__global__ __launch_bounds__(256, 1) void flash_mma(
    const __half* __restrict__ qh, const __half* __restrict__ kh,
    const __half* __restrict__ qkvh,
    __half* __restrict__ outp)           // f16 [M, 2048]
{
    extern __shared__ __align__(16) char smem[];
    const unsigned sb = smem_u32(smem);
    const int tid = threadIdx.x, lane = tid & 31, w = tid >> 5;
    const int qi = 15 - blockIdx.x;
    const int h = blockIdx.y, b = blockIdx.z;
    const int kvh = h >> 1;
    const int mBase = qi << 7;
    const int ntiles = 2 * qi + 2;

    const __half* qhp = qh + (((size_t)b * Hh + h) * Ssz + mBase) * Dh;
    const __half* khp = kh + ((size_t)b * KVh + kvh) * Ssz * Dh;
    const __half* vhp = qkvh + (size_t)b * Ssz * 4096 + 3072 + kvh * Dh;

    // prologue: stage Q at sb, extract, then KV tile0
    {
        const int r = tid >> 1, cb = (tid & 1) * 8;
        const unsigned dq = sb + r * 272 + cb * 16;
        const char* gq = (const char*)(qhp + (size_t)r * Dh) + cb * 16;
        #pragma unroll
        for (int i = 0; i < 8; ++i) CP16(dq + i * 16, gq + i * 16);
    }
    CP_COMMIT();
    asm volatile("cp.async.wait_group 0;" ::: "memory");
    __syncthreads();

    unsigned qhf[8][4];
    {
        const unsigned qB = sb + (16 * w + (lane & 15)) * 272 + (lane >> 4) * 16;
        #pragma unroll
        for (int kt = 0; kt < 8; ++kt)
            ldsm4(qhf[kt][0], qhf[kt][1], qhf[kt][2], qhf[kt][3], qB + kt * 32);
    }
    __syncthreads();        // Q fully extracted before overwriting with tile0

    load_kv_tile(sb, tid, khp, vhp, 0);
    CP_COMMIT();

    float o_[16][4];
    #pragma unroll
    for (int n = 0; n < 16; ++n)
        #pragma unroll
        for (int e = 0; e < 4; ++e) o_[n][e] = 0.0f;
    float l_lo = 0.0f, l_hi = 0.0f;
    const int gm_lo = mBase + 16 * w + (lane >> 2);
    const int gm_hi = gm_lo + 8;

    // V ldsm.trans lane base: rows n = (lane&7) + ((lane>>4)<<3), col d-chunk
    const unsigned vBt0 = ((lane & 7) + ((lane >> 4) << 3)) * 272
                        + ((lane >> 3) & 1) * 16;

    for (int t = 0; t < ntiles; ++t) {
        if (t + 1 < ntiles) {
            load_kv_tile(sb + ((t + 1) & 1) * FLSTG, tid, khp, vhp, (t + 1) * 64);
            CP_COMMIT();
            asm volatile("cp.async.wait_group 1;" ::: "memory");
        } else {
            asm volatile("cp.async.wait_group 0;" ::: "memory");
        }
        __syncthreads();
        const unsigned stb = sb + (t & 1) * FLSTG;

        // ---- QK^T (single term); scores in log2 domain ----
        float s_[8][4];
        #pragma unroll
        for (int j = 0; j < 8; ++j)
            #pragma unroll
            for (int e = 0; e < 4; ++e) s_[j][e] = 0.0f;

        const unsigned kB = stb + (lane & 15) * 272 + (lane >> 4) * 16;
        #pragma unroll
        for (int kt = 0; kt < 8; ++kt) {
            #pragma unroll
            for (int nt = 0; nt < 4; ++nt) {
                unsigned r0, r1, r2, r3;
                ldsm4(r0, r1, r2, r3, kB + nt * 16 * 272 + kt * 32);
                mma16816h(s_[nt * 2],     qhf[kt], r0, r2);
                mma16816h(s_[nt * 2 + 1], qhf[kt], r1, r3);
            }
        }

        // ---- mask (last two tiles only) + fixed-shift softmax ----
        const int nBase = t * 64;
        if (t >= 2 * qi) {
            #pragma unroll
            for (int j = 0; j < 8; ++j) {
                const int gn0 = nBase + 8 * j + (lane & 3) * 2;
                if (gn0 > gm_lo)     s_[j][0] = -1e30f;
                if (gn0 + 1 > gm_lo) s_[j][1] = -1e30f;
                if (gn0 > gm_hi)     s_[j][2] = -1e30f;
                if (gn0 + 1 > gm_hi) s_[j][3] = -1e30f;
            }
        }
        #pragma unroll
        for (int j = 0; j < 8; ++j) {
            float p0 = ex2(s_[j][0]);
            float p1 = ex2(s_[j][1]);
            float p2 = ex2(s_[j][2]);
            float p3 = ex2(s_[j][3]);
            s_[j][0] = p0; s_[j][1] = p1; s_[j][2] = p2; s_[j][3] = p3;
            l_lo += p0 + p1; l_hi += p2 + p3;
        }

        // ---- PV (single term, P from registers, V via ldsm.trans) ----
        const unsigned vB = stb + FKT + vBt0;
        #pragma unroll
        for (int kt2 = 0; kt2 < 4; ++kt2) {
            const float* pa = s_[2 * kt2];
            const float* pb = s_[2 * kt2 + 1];
            unsigned ahf[4];
            ahf[0] = pack2h(pa[0], pa[1]); ahf[1] = pack2h(pa[2], pa[3]);
            ahf[2] = pack2h(pb[0], pb[1]); ahf[3] = pack2h(pb[2], pb[3]);
            #pragma unroll
            for (int vt = 0; vt < 8; ++vt) {
                unsigned r0, r1, r2, r3;
                ldsm4t(r0, r1, r2, r3, vB + kt2 * 16 * 272 + vt * 32);
                mma16816h(o_[2 * vt],     ahf, r0, r2);
                mma16816h(o_[2 * vt + 1], ahf, r1, r3);
            }
        }
        __syncthreads();
    }

    // ---- epilogue: reduce l across quad, normalize, write f16 ----
    l_lo += __shfl_xor_sync(0xffffffffu, l_lo, 1);
    l_lo += __shfl_xor_sync(0xffffffffu, l_lo, 2);
    l_hi += __shfl_xor_sync(0xffffffffu, l_hi, 1);
    l_hi += __shfl_xor_sync(0xffffffffu, l_hi, 2);
    const float il = 1.0f / l_lo, ih = 1.0f / l_hi;
    __half* arl = outp + (size_t)(b * Ssz + gm_lo) * KP + h * Dh;
    __half* arh = outp + (size_t)(b * Ssz + gm_hi) * KP + h * Dh;
    #pragma unroll
    for (int n = 0; n < 16; ++n) {
        const int col = 8 * n + (lane & 3) * 2;
        *(__half2*)(arl + col) = __floats2half2_rn(o_[n][0] * il, o_[n][1] * il);
        *(__half2*)(arh + col) = __floats2half2_rn(o_[n][2] * ih, o_[n][3] * ih);
    }
}

// ---------------- host launch -------------------------------------------------
extern "C" void kernel_launch(void* const* d_in, const int* in_sizes, int n_in,
                              void* d_out, int out_size)
{
    const float* x   = (const float*)d_in[0];
    const float* Wq  = (const float*)d_in[1];
    const float* Wk  = (const float*)d_in[2];
    const float* Wv  = (const float*)d_in[3];
    const float* Wo  = (const float*)d_in[4];
    const float* qnw = (const float*)d_in[5];
    const float* knw = (const float*)d_in[6];
    const float* cs  = (const float*)d_in[7];
    const float* sn  = (const float*)d_in[8];

    __half *qkvh, *xp, *ap, *wqkvt, *wot;
    __half *qhh, *khh;
    cudaGetSymbolAddress((void**)&qkvh, g_qkvh);
    cudaGetSymbolAddress((void**)&xp, g_xp);
    cudaGetSymbolAddress((void**)&ap, g_ap);
    cudaGetSymbolAddress((void**)&wqkvt, g_wqkvt);
    cudaGetSymbolAddress((void**)&wot, g_wot);
    cudaGetSymbolAddress((void**)&qhh, g_qh);
    cudaGetSymbolAddress((void**)&khh, g_kh);

    cudaFuncSetAttribute(gemm_mma, cudaFuncAttributeMaxDynamicSharedMemorySize, GEMM_SMEM);
    cudaFuncSetAttribute(flash_mma, cudaFuncAttributeMaxDynamicSharedMemorySize, FL_SMEM);

    // convert inputs + weights (QKV weights concatenated along N)
    conv_a<<<8192, 256>>>(x, xp);
    conv_w<<<dim3(64, 64), 256>>>(Wq, wqkvt, 2048);
    conv_w<<<dim3(32, 64), 256>>>(Wk, wqkvt + (size_t)2048 * KP, 1024);
    conv_w<<<dim3(32, 64), 256>>>(Wv, wqkvt + (size_t)3072 * KP, 1024);
    conv_w<<<dim3(64, 64), 256>>>(Wo, wot, 2048);

    // fused QKV projection (single-f16 HMMA), f16 output: [Q | K | V], [4096, 4096]
    gemm_mma<<<dim3(32, 32), 256, GEMM_SMEM>>>(xp, wqkvt, nullptr, qkvh, 4096);

    // fused RMSNorm + RoPE for Q and K in one launch
    const float qscale = (float)(0.08838834764831845 * 1.4426950408889634);
    norm_rope_split<<<12288, 256>>>(qkvh, qnw, knw, cs, sn, qhh, khh, qscale);

    // flash attention (single-f16; V read straight from the fused buffer)
    flash_mma<<<dim3(16, Hh, Bsz), 256, FL_SMEM>>>(qhh, khh, qkvh, ap);

    // output projection (single-f16, fp32 output)
    gemm_mma<<<dim3(16, 32), 256, GEMM_SMEM>>>(ap, wot, (float*)d_out, nullptr, 2048);
}